// round 9
// baseline (speedup 1.0000x reference)
#include <cuda_runtime.h>
#include <math.h>
#include <stdint.h>

#define N_NODES 50000
#define E_MAX   1000000
#define DK 128
#define DOUT2 64
#define BN_EPS 1e-5f
#define SCAN_B 1024
#define SCAN_G ((N_NODES + SCAN_B - 1) / SCAN_B)   // 49

// ---------------- scratch ----------------
__device__ float g_agg[N_NODES * DK];   // also reused as y for layer 2
__device__ float g_h[N_NODES * DK];
__device__ float g_x1[N_NODES * DK];
__device__ float g_stats0[2 * DK];
__device__ float g_stats1[2 * DK];
__device__ int   g_is64;
__device__ int   g_deg[N_NODES];
__device__ int   g_rowptr[N_NODES + 1];
__device__ int   g_cur[N_NODES];
__device__ int   g_eidx[E_MAX];

// ---------------- helpers ----------------
__device__ __forceinline__ uint32_t f2tf(float f) {
    uint32_t r; asm("cvt.rna.tf32.f32 %0, %1;" : "=r"(r) : "f"(f)); return r;
}
__device__ __forceinline__ void mma_tf32(float* c, const uint32_t* a,
                                         uint32_t b0, uint32_t b1) {
    asm volatile(
        "mma.sync.aligned.m16n8k8.row.col.f32.tf32.tf32.f32 "
        "{%0,%1,%2,%3}, {%4,%5,%6,%7}, {%8,%9}, {%0,%1,%2,%3};"
        : "+f"(c[0]), "+f"(c[1]), "+f"(c[2]), "+f"(c[3])
        : "r"(a[0]), "r"(a[1]), "r"(a[2]), "r"(a[3]), "r"(b0), "r"(b1));
}

// ---------------- init: zero deg + zero stats + detect dtype ----------------
__global__ void init_kernel(const int* __restrict__ ei32) {
    int idx = blockIdx.x * blockDim.x + threadIdx.x;
    if (idx < N_NODES) g_deg[idx] = 0;
    if (blockIdx.x == 0) {
        g_stats0[threadIdx.x] = 0.f;
        g_stats1[threadIdx.x] = 0.f;
    }
    if (blockIdx.x == 1) {
        __shared__ int any;
        if (threadIdx.x == 0) any = 0;
        __syncthreads();
        if (threadIdx.x < 128) {
            int w = 1 + 2 * threadIdx.x;
            if (ei32[w] != 0) atomicOr(&any, 1);
        }
        __syncthreads();
        if (threadIdx.x == 0) g_is64 = (any == 0) ? 1 : 0;
    }
}

// ---------------- CSR build ----------------
__global__ void hist_kernel(const void* __restrict__ eiv, int E) {
    int i = blockIdx.x * blockDim.x + threadIdx.x;
    if (i >= E) return;
    long long d;
    if (g_is64) d = ((const long long*)eiv)[E + i];
    else        d = ((const int*)eiv)[E + i];
    if ((unsigned long long)d < N_NODES) atomicAdd(&g_deg[(int)d], 1);
}

// single-kernel scan: each block computes its own prefix from g_deg directly
__global__ void scan_kernel() {
    __shared__ int warp_sums[32];
    __shared__ int s_boff;
    int tid  = threadIdx.x;
    int lane = tid & 31, warp = tid >> 5;

    // prefix of all elements before this block
    int acc = 0;
    int lim = blockIdx.x * SCAN_B;
    for (int i = tid; i < lim; i += SCAN_B) acc += g_deg[i];
#pragma unroll
    for (int o = 16; o > 0; o >>= 1) acc += __shfl_down_sync(0xffffffffu, acc, o);
    if (lane == 0) warp_sums[warp] = acc;
    __syncthreads();
    if (tid < 32) {
        int w = warp_sums[tid];
#pragma unroll
        for (int o = 16; o > 0; o >>= 1) w += __shfl_down_sync(0xffffffffu, w, o);
        if (tid == 0) s_boff = w;
    }
    __syncthreads();

    int idx = blockIdx.x * SCAN_B + tid;
    int v = (idx < N_NODES) ? g_deg[idx] : 0;
    int s = v;
#pragma unroll
    for (int o = 1; o < 32; o <<= 1) {
        int u = __shfl_up_sync(0xffffffffu, s, o);
        if (lane >= o) s += u;
    }
    if (lane == 31) warp_sums[warp] = s;
    __syncthreads();
    if (warp == 0) {
        int w = warp_sums[lane];
        int ws = w;
#pragma unroll
        for (int o = 1; o < 32; o <<= 1) {
            int u = __shfl_up_sync(0xffffffffu, ws, o);
            if (lane >= o) ws += u;
        }
        warp_sums[lane] = ws - w;
    }
    __syncthreads();
    int excl = s - v + warp_sums[warp] + s_boff;
    if (idx < N_NODES) {
        g_rowptr[idx] = excl;
        g_cur[idx]    = excl;
        if (idx == N_NODES - 1) g_rowptr[N_NODES] = excl + v;
    }
}

__global__ void fill_kernel(const void* __restrict__ eiv, int E) {
    int i = blockIdx.x * blockDim.x + threadIdx.x;
    if (i >= E) return;
    long long s, d;
    if (g_is64) {
        s = ((const long long*)eiv)[i];
        d = ((const long long*)eiv)[E + i];
    } else {
        s = ((const int*)eiv)[i];
        d = ((const int*)eiv)[E + i];
    }
    if ((unsigned long long)s >= N_NODES || (unsigned long long)d >= N_NODES) return;
    int pos = atomicAdd(&g_cur[(int)d], 1);
    g_eidx[pos] = (int)s;
}

// ---------------- gather (128-wide): agg[n] = sum x[eidx[e]] ----------------
__global__ void __launch_bounds__(256)
gather_kernel(const float* __restrict__ x, float* __restrict__ agg) {
    int node = (blockIdx.x * blockDim.x + threadIdx.x) >> 5;
    int lane = threadIdx.x & 31;
    if (node >= N_NODES) return;
    int beg = g_rowptr[node];
    int end = g_rowptr[node + 1];

    float4 a0 = make_float4(0.f, 0.f, 0.f, 0.f);
    float4 a1 = make_float4(0.f, 0.f, 0.f, 0.f);

    for (int base = beg; base < end; base += 32) {
        int n = end - base; if (n > 32) n = 32;
        int myidx = (base + lane < end) ? g_eidx[base + lane] : 0;
        int j = 0;
        for (; j + 3 < n; j += 4) {
            int s0 = __shfl_sync(0xffffffffu, myidx, j);
            int s1 = __shfl_sync(0xffffffffu, myidx, j + 1);
            int s2 = __shfl_sync(0xffffffffu, myidx, j + 2);
            int s3 = __shfl_sync(0xffffffffu, myidx, j + 3);
            float4 v0 = *(const float4*)(x + (size_t)s0 * DK + lane * 4);
            float4 v1 = *(const float4*)(x + (size_t)s1 * DK + lane * 4);
            float4 v2 = *(const float4*)(x + (size_t)s2 * DK + lane * 4);
            float4 v3 = *(const float4*)(x + (size_t)s3 * DK + lane * 4);
            a0.x += v0.x; a0.y += v0.y; a0.z += v0.z; a0.w += v0.w;
            a1.x += v1.x; a1.y += v1.y; a1.z += v1.z; a1.w += v1.w;
            a0.x += v2.x; a0.y += v2.y; a0.z += v2.z; a0.w += v2.w;
            a1.x += v3.x; a1.y += v3.y; a1.z += v3.z; a1.w += v3.w;
        }
        for (; j < n; j++) {
            int s0 = __shfl_sync(0xffffffffu, myidx, j);
            float4 v0 = *(const float4*)(x + (size_t)s0 * DK + lane * 4);
            a0.x += v0.x; a0.y += v0.y; a0.z += v0.z; a0.w += v0.w;
        }
    }
    a0.x += a1.x; a0.y += a1.y; a0.z += a1.z; a0.w += a1.w;
    *(float4*)(agg + (size_t)node * DK + lane * 4) = a0;
}

// ---------------- gather (64-wide) + accumulate into out ----------------
__global__ void __launch_bounds__(256)
gather64_add_kernel(const float* __restrict__ y, float* __restrict__ out) {
    int node = (blockIdx.x * blockDim.x + threadIdx.x) >> 5;
    int lane = threadIdx.x & 31;
    if (node >= N_NODES) return;
    int beg = g_rowptr[node];
    int end = g_rowptr[node + 1];

    float2 a0 = make_float2(0.f, 0.f);
    float2 a1 = make_float2(0.f, 0.f);

    for (int base = beg; base < end; base += 32) {
        int n = end - base; if (n > 32) n = 32;
        int myidx = (base + lane < end) ? g_eidx[base + lane] : 0;
        int j = 0;
        for (; j + 3 < n; j += 4) {
            int s0 = __shfl_sync(0xffffffffu, myidx, j);
            int s1 = __shfl_sync(0xffffffffu, myidx, j + 1);
            int s2 = __shfl_sync(0xffffffffu, myidx, j + 2);
            int s3 = __shfl_sync(0xffffffffu, myidx, j + 3);
            float2 v0 = *(const float2*)(y + (size_t)s0 * DOUT2 + lane * 2);
            float2 v1 = *(const float2*)(y + (size_t)s1 * DOUT2 + lane * 2);
            float2 v2 = *(const float2*)(y + (size_t)s2 * DOUT2 + lane * 2);
            float2 v3 = *(const float2*)(y + (size_t)s3 * DOUT2 + lane * 2);
            a0.x += v0.x; a0.y += v0.y; a1.x += v1.x; a1.y += v1.y;
            a0.x += v2.x; a0.y += v2.y; a1.x += v3.x; a1.y += v3.y;
        }
        for (; j < n; j++) {
            int s0 = __shfl_sync(0xffffffffu, myidx, j);
            float2 v0 = *(const float2*)(y + (size_t)s0 * DOUT2 + lane * 2);
            a0.x += v0.x; a0.y += v0.y;
        }
    }
    a0.x += a1.x; a0.y += a1.y;
    float2* po = (float2*)(out + (size_t)node * DOUT2 + lane * 2);
    float2 o = *po;
    o.x += a0.x; o.y += a0.y;
    *po = o;
}

// ---------------- mma.sync tf32 GEMM ----------------
// PHASES=1, !SPLIT, !ACC : out = A@Wl + b                  (self GEMM)
// PHASES=1, !SPLIT,  ACC : out += A@Wl  (+stats on result) (agg GEMM)
// PHASES=1,  SPLIT       : cols 0-63 -> y = A@Wl; 64-127 -> out = A@Wr + b

template<int DOUT>
struct StageRegs {
    float4 rv[4];
    float4 wv[DOUT == 128 ? 4 : 2];
};

template<int DOUT, bool SPLIT>
__device__ __forceinline__ void ldg_stage(StageRegs<DOUT>& R,
                                          const float* __restrict__ rows,
                                          const float* __restrict__ Wl,
                                          const float* __restrict__ Wr,
                                          int k0, int row0, int nrows, int tid) {
#pragma unroll
    for (int j = 0; j < 4; j++) {
        int idx = tid + j * 256;
        int r = idx >> 3, c4 = idx & 7;
        float4 v = make_float4(0.f, 0.f, 0.f, 0.f);
        if (row0 + r < nrows)
            v = *(const float4*)&rows[(size_t)(row0 + r) * 128 + k0 + c4 * 4];
        R.rv[j] = v;
    }
    constexpr int WI = (DOUT == 128) ? 4 : 2;
#pragma unroll
    for (int j = 0; j < WI; j++) {
        int idx = tid + j * 256;
        int k, c4;
        if (DOUT == 128) { k = idx >> 5; c4 = idx & 31; }
        else             { k = idx >> 4; c4 = idx & 15; }
        if (SPLIT) {
            int c = c4 * 4;
            if (c < 64) R.wv[j] = *(const float4*)&Wl[(size_t)(k0 + k) * 64 + c];
            else        R.wv[j] = *(const float4*)&Wr[(size_t)(k0 + k) * 64 + (c - 64)];
        } else {
            R.wv[j] = *(const float4*)&Wl[(size_t)(k0 + k) * DOUT + c4 * 4];
        }
    }
}

template<int DOUT>
__device__ __forceinline__ void sts_stage(const StageRegs<DOUT>& R,
                                          uint32_t* sA, uint32_t* sW, int tid) {
    constexpr int WST = DOUT + 8;
#pragma unroll
    for (int j = 0; j < 4; j++) {
        int idx = tid + j * 256;
        int r = idx >> 3, c4 = idx & 7;
        float4 v = R.rv[j];
        *(uint4*)&sA[r * 36 + c4 * 4] =
            make_uint4(f2tf(v.x), f2tf(v.y), f2tf(v.z), f2tf(v.w));
    }
    constexpr int WI = (DOUT == 128) ? 4 : 2;
#pragma unroll
    for (int j = 0; j < WI; j++) {
        int idx = tid + j * 256;
        int k, c4;
        if (DOUT == 128) { k = idx >> 5; c4 = idx & 31; }
        else             { k = idx >> 4; c4 = idx & 15; }
        float4 v = R.wv[j];
        *(uint4*)&sW[k * WST + c4 * 4] =
            make_uint4(f2tf(v.x), f2tf(v.y), f2tf(v.z), f2tf(v.w));
    }
}

template<int DOUT, bool STATS, bool SPLIT, bool ACC>
__global__ void __launch_bounds__(256, 1)
gemm_mma(const float* __restrict__ A,
         const float* __restrict__ Wl, const float* __restrict__ Wr,
         const float* __restrict__ bias, float* __restrict__ out,
         float* __restrict__ y, float* __restrict__ stats, int nrows) {
    constexpr int WST = DOUT + 8;
    constexpr int NT  = DOUT / 16;
    constexpr int ASZ = 128 * 36;

    extern __shared__ uint32_t sm[];
    uint32_t* sA[2] = { sm, sm + ASZ };
    uint32_t* sW[2] = { sm + 2 * ASZ, sm + 2 * ASZ + 32 * WST };

    int tid  = threadIdx.x;
    int wid  = tid >> 5, lane = tid & 31;
    int wr   = wid & 3, wc = wid >> 2;
    int g    = lane >> 2, tg = lane & 3;
    int row0 = blockIdx.x * 128;

    float acc[2][NT][4];
#pragma unroll
    for (int rt = 0; rt < 2; rt++)
#pragma unroll
        for (int ct = 0; ct < NT; ct++)
#pragma unroll
            for (int j = 0; j < 4; j++) acc[rt][ct][j] = 0.f;

    StageRegs<DOUT> R;
    ldg_stage<DOUT, SPLIT>(R, A, Wl, Wr, 0, row0, nrows, tid);
    sts_stage<DOUT>(R, sA[0], sW[0], tid);

#pragma unroll
    for (int s = 0; s < 4; s++) {
        if (s + 1 < 4)
            ldg_stage<DOUT, SPLIT>(R, A, Wl, Wr, ((s + 1) & 3) * 32, row0, nrows, tid);
        __syncthreads();
        if (s + 1 < 4) sts_stage<DOUT>(R, sA[(s + 1) & 1], sW[(s + 1) & 1], tid);

        const uint32_t* As = sA[s & 1];
        const uint32_t* Ws = sW[s & 1];
#pragma unroll
        for (int kk = 0; kk < 32; kk += 8) {
            uint32_t a[2][4];
#pragma unroll
            for (int rt = 0; rt < 2; rt++) {
                int rb = wr * 32 + rt * 16;
                a[rt][0] = As[(rb + g) * 36 + kk + tg];
                a[rt][1] = As[(rb + g + 8) * 36 + kk + tg];
                a[rt][2] = As[(rb + g) * 36 + kk + tg + 4];
                a[rt][3] = As[(rb + g + 8) * 36 + kk + tg + 4];
            }
#pragma unroll
            for (int ct = 0; ct < NT; ct++) {
                int nb = wc * (DOUT / 2) + ct * 8 + g;
                uint32_t b0 = Ws[(kk + tg) * WST + nb];
                uint32_t b1 = Ws[(kk + tg + 4) * WST + nb];
                mma_tf32(acc[0][ct], a[0], b0, b1);
                mma_tf32(acc[1][ct], a[1], b0, b1);
            }
        }
    }

    // ---- epilogue ----
    float* sst = (float*)sm;
    if (STATS) {
        __syncthreads();
        sst[tid] = 0.f;
        __syncthreads();
    }

#pragma unroll
    for (int ct = 0; ct < NT; ct++) {
        int nb = wc * (DOUT / 2) + ct * 8 + 2 * tg;
        float b0 = 0.f, b1 = 0.f;
        if (!ACC) {
            if (SPLIT) {
                b0 = (nb >= 64) ? bias[nb - 64] : 0.f;
                b1 = (nb >= 64) ? bias[nb - 63] : 0.f;
            } else {
                b0 = bias[nb]; b1 = bias[nb + 1];
            }
        }
        float s0 = 0.f, q0 = 0.f, s1 = 0.f, q1 = 0.f;
#pragma unroll
        for (int rt = 0; rt < 2; rt++) {
            int gr = row0 + wr * 32 + rt * 16 + g;
            float v0 = acc[rt][ct][0] + b0, v1 = acc[rt][ct][1] + b1;
            float v2 = acc[rt][ct][2] + b0, v3 = acc[rt][ct][3] + b1;
            if (gr < nrows) {
                float* dst;
                if (SPLIT) dst = (nb < 64) ? (y + (size_t)gr * 64 + nb)
                                           : (out + (size_t)gr * 64 + nb - 64);
                else       dst = out + (size_t)gr * DOUT + nb;
                if (ACC) { float2 o = *(float2*)dst; v0 += o.x; v1 += o.y; }
                *(float2*)dst = make_float2(v0, v1);
                if (STATS) { s0 += v0; q0 += v0 * v0; s1 += v1; q1 += v1 * v1; }
            }
            if (gr + 8 < nrows) {
                float* dst;
                if (SPLIT) dst = (nb < 64) ? (y + (size_t)(gr + 8) * 64 + nb)
                                           : (out + (size_t)(gr + 8) * 64 + nb - 64);
                else       dst = out + (size_t)(gr + 8) * DOUT + nb;
                if (ACC) { float2 o = *(float2*)dst; v2 += o.x; v3 += o.y; }
                *(float2*)dst = make_float2(v2, v3);
                if (STATS) { s0 += v2; q0 += v2 * v2; s1 += v3; q1 += v3 * v3; }
            }
        }
        if (STATS) {
#pragma unroll
            for (int off = 4; off <= 16; off <<= 1) {
                s0 += __shfl_xor_sync(0xffffffffu, s0, off);
                q0 += __shfl_xor_sync(0xffffffffu, q0, off);
                s1 += __shfl_xor_sync(0xffffffffu, s1, off);
                q1 += __shfl_xor_sync(0xffffffffu, q1, off);
            }
            if (g == 0) {
                atomicAdd(&sst[nb],            s0);
                atomicAdd(&sst[DOUT + nb],     q0);
                atomicAdd(&sst[nb + 1],        s1);
                atomicAdd(&sst[DOUT + nb + 1], q1);
            }
        }
    }

    if (STATS) {
        __syncthreads();
        atomicAdd(&stats[tid], sst[tid]);   // tid < 256 == 2*DOUT
    }
}

// ---------------- BN (finalize fused) + exact GELU ----------------
__device__ __forceinline__ float gelu_exact(float v) {
    return 0.5f * v * (1.0f + erff(v * 0.70710678118654752f));
}

__global__ void bn_gelu_kernel(const float* __restrict__ h,
                               const float* __restrict__ stats,
                               const float* __restrict__ g,
                               const float* __restrict__ be,
                               float* __restrict__ out, int n4, float invn) {
    __shared__ float ssm[2 * DK];
    int t = threadIdx.x;
    if (t < DK) {
        float mu  = stats[t] * invn;
        float var = stats[DK + t] * invn - mu * mu;
        float rs  = rsqrtf(var + BN_EPS);
        float s   = g[t] * rs;
        ssm[t]      = s;
        ssm[DK + t] = be[t] - mu * s;
    }
    __syncthreads();
    int i = blockIdx.x * blockDim.x + t;
    if (i >= n4) return;
    int c4 = i & (DK / 4 - 1);
    float4 v  = ((const float4*)h)[i];
    float4 sc = *(float4*)&ssm[c4 * 4];
    float4 sh = *(float4*)&ssm[DK + c4 * 4];
    v.x = gelu_exact(v.x * sc.x + sh.x);
    v.y = gelu_exact(v.y * sc.y + sh.y);
    v.z = gelu_exact(v.z * sc.z + sh.z);
    v.w = gelu_exact(v.w * sc.w + sh.w);
    ((float4*)out)[i] = v;
}

// ---------------- launch ----------------
extern "C" void kernel_launch(void* const* d_in, const int* in_sizes, int n_in,
                              void* d_out, int out_size) {
    const float* x   = (const float*)d_in[0];
    const void*  ei  = d_in[1];
    const float* W0l = (const float*)d_in[2];
    const float* W0r = (const float*)d_in[3];
    const float* b0  = (const float*)d_in[4];
    const float* g0  = (const float*)d_in[5];
    const float* be0 = (const float*)d_in[6];
    const float* W1l = (const float*)d_in[7];
    const float* W1r = (const float*)d_in[8];
    const float* b1  = (const float*)d_in[9];
    const float* g1  = (const float*)d_in[10];
    const float* be1 = (const float*)d_in[11];
    const float* W2l = (const float*)d_in[12];
    const float* W2r = (const float*)d_in[13];
    const float* b2  = (const float*)d_in[14];
    float* out = (float*)d_out;

    int E = in_sizes[1] / 2;
    if (E > E_MAX) E = E_MAX;

    void* p;
    cudaGetSymbolAddress(&p, g_agg);    float* agg    = (float*)p;
    cudaGetSymbolAddress(&p, g_h);      float* h      = (float*)p;
    cudaGetSymbolAddress(&p, g_x1);     float* x1     = (float*)p;
    cudaGetSymbolAddress(&p, g_stats0); float* stats0 = (float*)p;
    cudaGetSymbolAddress(&p, g_stats1); float* stats1 = (float*)p;

    const int smemA = 2 * (128 * 36 + 32 * (128 + 8)) * 4;   // 71680
    cudaFuncSetAttribute((const void*)gemm_mma<DK, false, false, false>,
                         cudaFuncAttributeMaxDynamicSharedMemorySize, smemA);
    cudaFuncSetAttribute((const void*)gemm_mma<DK, true,  false, true>,
                         cudaFuncAttributeMaxDynamicSharedMemorySize, smemA);
    cudaFuncSetAttribute((const void*)gemm_mma<DK, false, true,  false>,
                         cudaFuncAttributeMaxDynamicSharedMemorySize, smemA);

    int eb      = (E + 255) / 256;
    int gblocks = (N_NODES + 127) / 128;
    int gab     = (N_NODES * 32 + 255) / 256;
    int n4      = N_NODES * DK / 4;
    int bgb     = (n4 + 255) / 256;
    float invn  = 1.0f / (float)N_NODES;

    // side stream + fork/join events (capture-legal fork-join pattern;
    // no device memory is allocated by stream/event creation)
    cudaStream_t s2;
    cudaStreamCreateWithFlags(&s2, cudaStreamNonBlocking);
    cudaEvent_t eF0, eJ0, eF1, eJ1;
    cudaEventCreateWithFlags(&eF0, cudaEventDisableTiming);
    cudaEventCreateWithFlags(&eJ0, cudaEventDisableTiming);
    cudaEventCreateWithFlags(&eF1, cudaEventDisableTiming);
    cudaEventCreateWithFlags(&eJ1, cudaEventDisableTiming);

    // ---- fork: self-GEMM0 (h = x@W0r + b0) runs concurrent with CSR build --
    cudaEventRecord(eF0, 0);
    cudaStreamWaitEvent(s2, eF0, 0);
    gemm_mma<DK, false, false, false><<<gblocks, 256, smemA, s2>>>(
        x, W0r, W0r, b0, h, nullptr, nullptr, N_NODES);

    // main stream: CSR build + gather0
    init_kernel<<<(N_NODES + 255) / 256, 256>>>((const int*)ei);
    hist_kernel<<<eb, 256>>>(ei, E);
    scan_kernel<<<SCAN_G, SCAN_B>>>();
    fill_kernel<<<eb, 256>>>(ei, E);
    gather_kernel<<<gab, 256>>>(x, agg);

    // join, then agg-GEMM0 (h += agg@W0l, stats) + bn_gelu
    cudaEventRecord(eJ0, s2);
    cudaStreamWaitEvent(0, eJ0, 0);
    gemm_mma<DK, true, false, true><<<gblocks, 256, smemA>>>(
        agg, W0l, W0l, b0, h, nullptr, stats0, N_NODES);
    bn_gelu_kernel<<<bgb, 256>>>(h, stats0, g0, be0, x1, n4, invn);

    // ---- layer 1: fork self-GEMM1 concurrent with gather1 ----
    cudaEventRecord(eF1, 0);
    cudaStreamWaitEvent(s2, eF1, 0);
    gemm_mma<DK, false, false, false><<<gblocks, 256, smemA, s2>>>(
        x1, W1r, W1r, b1, h, nullptr, nullptr, N_NODES);

    gather_kernel<<<gab, 256>>>(x1, agg);

    cudaEventRecord(eJ1, s2);
    cudaStreamWaitEvent(0, eJ1, 0);
    gemm_mma<DK, true, false, true><<<gblocks, 256, smemA>>>(
        agg, W1l, W1l, b1, h, nullptr, stats1, N_NODES);
    bn_gelu_kernel<<<bgb, 256>>>(h, stats1, g1, be1, x1, n4, invn);

    // ---- layer 2: split gemm ([y | self+bias]) then 64-wide gather-add ----
    gemm_mma<DK, false, true, false><<<gblocks, 256, smemA>>>(
        x1, W2l, W2r, b2, out, agg, nullptr, N_NODES);
    gather64_add_kernel<<<gab, 256>>>(agg, out);
}

// round 10
// speedup vs baseline: 1.1835x; 1.1835x over previous
#include <cuda_runtime.h>
#include <math.h>
#include <stdint.h>

#define N_NODES 50000
#define E_MAX   1000000
#define DK 128
#define DOUT2 64
#define BN_EPS 1e-5f
#define SCAN_B 1024
#define SCAN_G ((N_NODES + SCAN_B - 1) / SCAN_B)   // 49

// ---------------- scratch ----------------
__device__ float g_agg[N_NODES * DK];   // also reused as y for layer 2
__device__ float g_h[N_NODES * DK];
__device__ float g_x1[N_NODES * DK];
__device__ float g_stats0[2 * DK];
__device__ float g_stats1[2 * DK];
__device__ int   g_is64;
__device__ int   g_deg[N_NODES];
__device__ int   g_rowptr[N_NODES + 1];
__device__ int   g_cur[N_NODES];
__device__ int   g_eidx[E_MAX];

// ---------------- helpers ----------------
__device__ __forceinline__ uint32_t f2tf(float f) {
    uint32_t r; asm("cvt.rna.tf32.f32 %0, %1;" : "=r"(r) : "f"(f)); return r;
}
__device__ __forceinline__ void mma_tf32(float* c, const uint32_t* a,
                                         uint32_t b0, uint32_t b1) {
    asm volatile(
        "mma.sync.aligned.m16n8k8.row.col.f32.tf32.tf32.f32 "
        "{%0,%1,%2,%3}, {%4,%5,%6,%7}, {%8,%9}, {%0,%1,%2,%3};"
        : "+f"(c[0]), "+f"(c[1]), "+f"(c[2]), "+f"(c[3])
        : "r"(a[0]), "r"(a[1]), "r"(a[2]), "r"(a[3]), "r"(b0), "r"(b1));
}

// ---------------- init: zero deg + zero stats + detect dtype ----------------
__global__ void init_kernel(const int* __restrict__ ei32) {
    int idx = blockIdx.x * blockDim.x + threadIdx.x;
    if (idx < N_NODES) g_deg[idx] = 0;
    if (blockIdx.x == 0) {
        g_stats0[threadIdx.x] = 0.f;
        g_stats1[threadIdx.x] = 0.f;
    }
    if (blockIdx.x == 1) {
        __shared__ int any;
        if (threadIdx.x == 0) any = 0;
        __syncthreads();
        if (threadIdx.x < 128) {
            int w = 1 + 2 * threadIdx.x;
            if (ei32[w] != 0) atomicOr(&any, 1);
        }
        __syncthreads();
        if (threadIdx.x == 0) g_is64 = (any == 0) ? 1 : 0;
    }
}

// ---------------- CSR build ----------------
__global__ void hist_kernel(const void* __restrict__ eiv, int E) {
    int i = blockIdx.x * blockDim.x + threadIdx.x;
    if (i >= E) return;
    long long d;
    if (g_is64) d = ((const long long*)eiv)[E + i];
    else        d = ((const int*)eiv)[E + i];
    if ((unsigned long long)d < N_NODES) atomicAdd(&g_deg[(int)d], 1);
}

// single-kernel scan: each block computes its own prefix from g_deg directly
__global__ void scan_kernel() {
    __shared__ int warp_sums[32];
    __shared__ int s_boff;
    int tid  = threadIdx.x;
    int lane = tid & 31, warp = tid >> 5;

    // prefix of all elements before this block
    int acc = 0;
    int lim = blockIdx.x * SCAN_B;
    for (int i = tid; i < lim; i += SCAN_B) acc += g_deg[i];
#pragma unroll
    for (int o = 16; o > 0; o >>= 1) acc += __shfl_down_sync(0xffffffffu, acc, o);
    if (lane == 0) warp_sums[warp] = acc;
    __syncthreads();
    if (tid < 32) {
        int w = warp_sums[tid];
#pragma unroll
        for (int o = 16; o > 0; o >>= 1) w += __shfl_down_sync(0xffffffffu, w, o);
        if (tid == 0) s_boff = w;
    }
    __syncthreads();

    int idx = blockIdx.x * SCAN_B + tid;
    int v = (idx < N_NODES) ? g_deg[idx] : 0;
    int s = v;
#pragma unroll
    for (int o = 1; o < 32; o <<= 1) {
        int u = __shfl_up_sync(0xffffffffu, s, o);
        if (lane >= o) s += u;
    }
    if (lane == 31) warp_sums[warp] = s;
    __syncthreads();
    if (warp == 0) {
        int w = warp_sums[lane];
        int ws = w;
#pragma unroll
        for (int o = 1; o < 32; o <<= 1) {
            int u = __shfl_up_sync(0xffffffffu, ws, o);
            if (lane >= o) ws += u;
        }
        warp_sums[lane] = ws - w;
    }
    __syncthreads();
    int excl = s - v + warp_sums[warp] + s_boff;
    if (idx < N_NODES) {
        g_rowptr[idx] = excl;
        g_cur[idx]    = excl;
        if (idx == N_NODES - 1) g_rowptr[N_NODES] = excl + v;
    }
}

__global__ void fill_kernel(const void* __restrict__ eiv, int E) {
    int i = blockIdx.x * blockDim.x + threadIdx.x;
    if (i >= E) return;
    long long s, d;
    if (g_is64) {
        s = ((const long long*)eiv)[i];
        d = ((const long long*)eiv)[E + i];
    } else {
        s = ((const int*)eiv)[i];
        d = ((const int*)eiv)[E + i];
    }
    if ((unsigned long long)s >= N_NODES || (unsigned long long)d >= N_NODES) return;
    int pos = atomicAdd(&g_cur[(int)d], 1);
    g_eidx[pos] = (int)s;
}

// ---------------- gather (128-wide): agg[n] = sum x[eidx[e]] ----------------
__global__ void __launch_bounds__(256)
gather_kernel(const float* __restrict__ x, float* __restrict__ agg) {
    int node = (blockIdx.x * blockDim.x + threadIdx.x) >> 5;
    int lane = threadIdx.x & 31;
    if (node >= N_NODES) return;
    int beg = g_rowptr[node];
    int end = g_rowptr[node + 1];

    float4 a0 = make_float4(0.f, 0.f, 0.f, 0.f);
    float4 a1 = make_float4(0.f, 0.f, 0.f, 0.f);

    for (int base = beg; base < end; base += 32) {
        int n = end - base; if (n > 32) n = 32;
        int myidx = (base + lane < end) ? g_eidx[base + lane] : 0;
        int j = 0;
        for (; j + 3 < n; j += 4) {
            int s0 = __shfl_sync(0xffffffffu, myidx, j);
            int s1 = __shfl_sync(0xffffffffu, myidx, j + 1);
            int s2 = __shfl_sync(0xffffffffu, myidx, j + 2);
            int s3 = __shfl_sync(0xffffffffu, myidx, j + 3);
            float4 v0 = *(const float4*)(x + (size_t)s0 * DK + lane * 4);
            float4 v1 = *(const float4*)(x + (size_t)s1 * DK + lane * 4);
            float4 v2 = *(const float4*)(x + (size_t)s2 * DK + lane * 4);
            float4 v3 = *(const float4*)(x + (size_t)s3 * DK + lane * 4);
            a0.x += v0.x; a0.y += v0.y; a0.z += v0.z; a0.w += v0.w;
            a1.x += v1.x; a1.y += v1.y; a1.z += v1.z; a1.w += v1.w;
            a0.x += v2.x; a0.y += v2.y; a0.z += v2.z; a0.w += v2.w;
            a1.x += v3.x; a1.y += v3.y; a1.z += v3.z; a1.w += v3.w;
        }
        for (; j < n; j++) {
            int s0 = __shfl_sync(0xffffffffu, myidx, j);
            float4 v0 = *(const float4*)(x + (size_t)s0 * DK + lane * 4);
            a0.x += v0.x; a0.y += v0.y; a0.z += v0.z; a0.w += v0.w;
        }
    }
    a0.x += a1.x; a0.y += a1.y; a0.z += a1.z; a0.w += a1.w;
    *(float4*)(agg + (size_t)node * DK + lane * 4) = a0;
}

// ---------------- gather (64-wide) + accumulate into out ----------------
__global__ void __launch_bounds__(256)
gather64_add_kernel(const float* __restrict__ y, float* __restrict__ out) {
    int node = (blockIdx.x * blockDim.x + threadIdx.x) >> 5;
    int lane = threadIdx.x & 31;
    if (node >= N_NODES) return;
    int beg = g_rowptr[node];
    int end = g_rowptr[node + 1];

    float2 a0 = make_float2(0.f, 0.f);
    float2 a1 = make_float2(0.f, 0.f);

    for (int base = beg; base < end; base += 32) {
        int n = end - base; if (n > 32) n = 32;
        int myidx = (base + lane < end) ? g_eidx[base + lane] : 0;
        int j = 0;
        for (; j + 3 < n; j += 4) {
            int s0 = __shfl_sync(0xffffffffu, myidx, j);
            int s1 = __shfl_sync(0xffffffffu, myidx, j + 1);
            int s2 = __shfl_sync(0xffffffffu, myidx, j + 2);
            int s3 = __shfl_sync(0xffffffffu, myidx, j + 3);
            float2 v0 = *(const float2*)(y + (size_t)s0 * DOUT2 + lane * 2);
            float2 v1 = *(const float2*)(y + (size_t)s1 * DOUT2 + lane * 2);
            float2 v2 = *(const float2*)(y + (size_t)s2 * DOUT2 + lane * 2);
            float2 v3 = *(const float2*)(y + (size_t)s3 * DOUT2 + lane * 2);
            a0.x += v0.x; a0.y += v0.y; a1.x += v1.x; a1.y += v1.y;
            a0.x += v2.x; a0.y += v2.y; a1.x += v3.x; a1.y += v3.y;
        }
        for (; j < n; j++) {
            int s0 = __shfl_sync(0xffffffffu, myidx, j);
            float2 v0 = *(const float2*)(y + (size_t)s0 * DOUT2 + lane * 2);
            a0.x += v0.x; a0.y += v0.y;
        }
    }
    a0.x += a1.x; a0.y += a1.y;
    float2* po = (float2*)(out + (size_t)node * DOUT2 + lane * 2);
    float2 o = *po;
    o.x += a0.x; o.y += a0.y;
    *po = o;
}

// ---------------- mma.sync tf32 GEMM ----------------
// PHASES=2: out = A@Wl + X@Wr + b  (dual K-phase)
// PHASES=1 + SPLIT: cols 0-63 -> y = A@Wl (no bias); cols 64-127 -> out = A@Wr + b
// STATS: column sum/sumsq of the (bias-added) result accumulated into stats.

template<int DOUT>
struct StageRegs {
    float4 rv[4];
    float4 wv[DOUT == 128 ? 4 : 2];
};

template<int DOUT, bool SPLIT>
__device__ __forceinline__ void ldg_stage(StageRegs<DOUT>& R,
                                          const float* __restrict__ rows,
                                          const float* __restrict__ Wl,
                                          const float* __restrict__ Wr,
                                          int k0, int row0, int nrows, int tid) {
#pragma unroll
    for (int j = 0; j < 4; j++) {
        int idx = tid + j * 256;
        int r = idx >> 3, c4 = idx & 7;
        float4 v = make_float4(0.f, 0.f, 0.f, 0.f);
        if (row0 + r < nrows)
            v = *(const float4*)&rows[(size_t)(row0 + r) * 128 + k0 + c4 * 4];
        R.rv[j] = v;
    }
    constexpr int WI = (DOUT == 128) ? 4 : 2;
#pragma unroll
    for (int j = 0; j < WI; j++) {
        int idx = tid + j * 256;
        int k, c4;
        if (DOUT == 128) { k = idx >> 5; c4 = idx & 31; }
        else             { k = idx >> 4; c4 = idx & 15; }
        if (SPLIT) {
            int c = c4 * 4;
            if (c < 64) R.wv[j] = *(const float4*)&Wl[(size_t)(k0 + k) * 64 + c];
            else        R.wv[j] = *(const float4*)&Wr[(size_t)(k0 + k) * 64 + (c - 64)];
        } else {
            R.wv[j] = *(const float4*)&Wl[(size_t)(k0 + k) * DOUT + c4 * 4];
        }
    }
}

template<int DOUT>
__device__ __forceinline__ void sts_stage(const StageRegs<DOUT>& R,
                                          uint32_t* sA, uint32_t* sW, int tid) {
    constexpr int WST = DOUT + 8;
#pragma unroll
    for (int j = 0; j < 4; j++) {
        int idx = tid + j * 256;
        int r = idx >> 3, c4 = idx & 7;
        float4 v = R.rv[j];
        *(uint4*)&sA[r * 36 + c4 * 4] =
            make_uint4(f2tf(v.x), f2tf(v.y), f2tf(v.z), f2tf(v.w));
    }
    constexpr int WI = (DOUT == 128) ? 4 : 2;
#pragma unroll
    for (int j = 0; j < WI; j++) {
        int idx = tid + j * 256;
        int k, c4;
        if (DOUT == 128) { k = idx >> 5; c4 = idx & 31; }
        else             { k = idx >> 4; c4 = idx & 15; }
        float4 v = R.wv[j];
        *(uint4*)&sW[k * WST + c4 * 4] =
            make_uint4(f2tf(v.x), f2tf(v.y), f2tf(v.z), f2tf(v.w));
    }
}

template<int DOUT, int PHASES, bool STATS, bool SPLIT>
__global__ void __launch_bounds__(256, 1)
gemm_mma(const float* __restrict__ A, const float* __restrict__ X,
         const float* __restrict__ Wl, const float* __restrict__ Wr,
         const float* __restrict__ bias, float* __restrict__ out,
         float* __restrict__ y, float* __restrict__ stats, int nrows) {
    constexpr int WST    = DOUT + 8;
    constexpr int NT     = DOUT / 16;
    constexpr int ASZ    = 128 * 36;
    constexpr int NSTAGE = PHASES * 4;

    extern __shared__ uint32_t sm[];
    uint32_t* sA[2] = { sm, sm + ASZ };
    uint32_t* sW[2] = { sm + 2 * ASZ, sm + 2 * ASZ + 32 * WST };

    int tid  = threadIdx.x;
    int wid  = tid >> 5, lane = tid & 31;
    int wr   = wid & 3, wc = wid >> 2;
    int g    = lane >> 2, tg = lane & 3;
    int row0 = blockIdx.x * 128;

    float acc[2][NT][4];
#pragma unroll
    for (int rt = 0; rt < 2; rt++)
#pragma unroll
        for (int ct = 0; ct < NT; ct++)
#pragma unroll
            for (int j = 0; j < 4; j++) acc[rt][ct][j] = 0.f;

    StageRegs<DOUT> R;
    ldg_stage<DOUT, SPLIT>(R, A, Wl, Wr, 0, row0, nrows, tid);
    sts_stage<DOUT>(R, sA[0], sW[0], tid);

#pragma unroll
    for (int s = 0; s < NSTAGE; s++) {
        if (s + 1 < NSTAGE) {
            const float* rows = (PHASES == 2 && s + 1 >= 4) ? X : A;
            const float* W1   = (PHASES == 2 && s + 1 >= 4) ? Wr : Wl;
            ldg_stage<DOUT, SPLIT>(R, rows, W1, Wr, ((s + 1) & 3) * 32, row0, nrows, tid);
        }
        __syncthreads();
        if (s + 1 < NSTAGE) sts_stage<DOUT>(R, sA[(s + 1) & 1], sW[(s + 1) & 1], tid);

        const uint32_t* As = sA[s & 1];
        const uint32_t* Ws = sW[s & 1];
#pragma unroll
        for (int kk = 0; kk < 32; kk += 8) {
            uint32_t a[2][4];
#pragma unroll
            for (int rt = 0; rt < 2; rt++) {
                int rb = wr * 32 + rt * 16;
                a[rt][0] = As[(rb + g) * 36 + kk + tg];
                a[rt][1] = As[(rb + g + 8) * 36 + kk + tg];
                a[rt][2] = As[(rb + g) * 36 + kk + tg + 4];
                a[rt][3] = As[(rb + g + 8) * 36 + kk + tg + 4];
            }
#pragma unroll
            for (int ct = 0; ct < NT; ct++) {
                int nb = wc * (DOUT / 2) + ct * 8 + g;
                uint32_t b0 = Ws[(kk + tg) * WST + nb];
                uint32_t b1 = Ws[(kk + tg + 4) * WST + nb];
                mma_tf32(acc[0][ct], a[0], b0, b1);
                mma_tf32(acc[1][ct], a[1], b0, b1);
            }
        }
    }

    // ---- epilogue ----
    float* sst = (float*)sm;
    if (STATS) {
        __syncthreads();
        sst[tid] = 0.f;
        __syncthreads();
    }

#pragma unroll
    for (int ct = 0; ct < NT; ct++) {
        int nb = wc * (DOUT / 2) + ct * 8 + 2 * tg;
        float b0, b1;
        if (SPLIT) {
            b0 = (nb >= 64) ? bias[nb - 64] : 0.f;
            b1 = (nb >= 64) ? bias[nb - 63] : 0.f;
        } else {
            b0 = bias[nb]; b1 = bias[nb + 1];
        }
        float s0 = 0.f, q0 = 0.f, s1 = 0.f, q1 = 0.f;
#pragma unroll
        for (int rt = 0; rt < 2; rt++) {
            int gr = row0 + wr * 32 + rt * 16 + g;
            float v0 = acc[rt][ct][0] + b0, v1 = acc[rt][ct][1] + b1;
            float v2 = acc[rt][ct][2] + b0, v3 = acc[rt][ct][3] + b1;
            if (gr < nrows) {
                float* dst;
                if (SPLIT) dst = (nb < 64) ? (y + (size_t)gr * 64 + nb)
                                           : (out + (size_t)gr * 64 + nb - 64);
                else       dst = out + (size_t)gr * DOUT + nb;
                *(float2*)dst = make_float2(v0, v1);
                if (STATS) { s0 += v0; q0 += v0 * v0; s1 += v1; q1 += v1 * v1; }
            }
            if (gr + 8 < nrows) {
                float* dst;
                if (SPLIT) dst = (nb < 64) ? (y + (size_t)(gr + 8) * 64 + nb)
                                           : (out + (size_t)(gr + 8) * 64 + nb - 64);
                else       dst = out + (size_t)(gr + 8) * DOUT + nb;
                *(float2*)dst = make_float2(v2, v3);
                if (STATS) { s0 += v2; q0 += v2 * v2; s1 += v3; q1 += v3 * v3; }
            }
        }
        if (STATS) {
#pragma unroll
            for (int off = 4; off <= 16; off <<= 1) {
                s0 += __shfl_xor_sync(0xffffffffu, s0, off);
                q0 += __shfl_xor_sync(0xffffffffu, q0, off);
                s1 += __shfl_xor_sync(0xffffffffu, s1, off);
                q1 += __shfl_xor_sync(0xffffffffu, q1, off);
            }
            if (g == 0) {
                atomicAdd(&sst[nb],            s0);
                atomicAdd(&sst[DOUT + nb],     q0);
                atomicAdd(&sst[nb + 1],        s1);
                atomicAdd(&sst[DOUT + nb + 1], q1);
            }
        }
    }

    if (STATS) {
        __syncthreads();
        atomicAdd(&stats[tid], sst[tid]);   // tid < 256 == 2*DOUT
    }
}

// ---------------- BN (finalize fused) + exact GELU ----------------
__device__ __forceinline__ float gelu_exact(float v) {
    return 0.5f * v * (1.0f + erff(v * 0.70710678118654752f));
}

__global__ void bn_gelu_kernel(const float* __restrict__ h,
                               const float* __restrict__ stats,
                               const float* __restrict__ g,
                               const float* __restrict__ be,
                               float* __restrict__ out, int n4, float invn) {
    __shared__ float ssm[2 * DK];
    int t = threadIdx.x;
    if (t < DK) {
        float mu  = stats[t] * invn;
        float var = stats[DK + t] * invn - mu * mu;
        float rs  = rsqrtf(var + BN_EPS);
        float s   = g[t] * rs;
        ssm[t]      = s;
        ssm[DK + t] = be[t] - mu * s;
    }
    __syncthreads();
    int i = blockIdx.x * blockDim.x + t;
    if (i >= n4) return;
    int c4 = i & (DK / 4 - 1);
    float4 v  = ((const float4*)h)[i];
    float4 sc = *(float4*)&ssm[c4 * 4];
    float4 sh = *(float4*)&ssm[DK + c4 * 4];
    v.x = gelu_exact(v.x * sc.x + sh.x);
    v.y = gelu_exact(v.y * sc.y + sh.y);
    v.z = gelu_exact(v.z * sc.z + sh.z);
    v.w = gelu_exact(v.w * sc.w + sh.w);
    ((float4*)out)[i] = v;
}

// ---------------- launch ----------------
extern "C" void kernel_launch(void* const* d_in, const int* in_sizes, int n_in,
                              void* d_out, int out_size) {
    const float* x   = (const float*)d_in[0];
    const void*  ei  = d_in[1];
    const float* W0l = (const float*)d_in[2];
    const float* W0r = (const float*)d_in[3];
    const float* b0  = (const float*)d_in[4];
    const float* g0  = (const float*)d_in[5];
    const float* be0 = (const float*)d_in[6];
    const float* W1l = (const float*)d_in[7];
    const float* W1r = (const float*)d_in[8];
    const float* b1  = (const float*)d_in[9];
    const float* g1  = (const float*)d_in[10];
    const float* be1 = (const float*)d_in[11];
    const float* W2l = (const float*)d_in[12];
    const float* W2r = (const float*)d_in[13];
    const float* b2  = (const float*)d_in[14];
    float* out = (float*)d_out;

    int E = in_sizes[1] / 2;
    if (E > E_MAX) E = E_MAX;

    void* p;
    cudaGetSymbolAddress(&p, g_agg);    float* agg    = (float*)p;
    cudaGetSymbolAddress(&p, g_h);      float* h      = (float*)p;
    cudaGetSymbolAddress(&p, g_x1);     float* x1     = (float*)p;
    cudaGetSymbolAddress(&p, g_stats0); float* stats0 = (float*)p;
    cudaGetSymbolAddress(&p, g_stats1); float* stats1 = (float*)p;

    const int smemA = 2 * (128 * 36 + 32 * (128 + 8)) * 4;   // 71680
    cudaFuncSetAttribute((const void*)gemm_mma<DK, 2, true,  false>,
                         cudaFuncAttributeMaxDynamicSharedMemorySize, smemA);
    cudaFuncSetAttribute((const void*)gemm_mma<DK, 1, false, true>,
                         cudaFuncAttributeMaxDynamicSharedMemorySize, smemA);

    int eb      = (E + 255) / 256;
    int gblocks = (N_NODES + 127) / 128;
    int gab     = (N_NODES * 32 + 255) / 256;
    int n4      = N_NODES * DK / 4;
    int bgb     = (n4 + 255) / 256;
    float invn  = 1.0f / (float)N_NODES;

    // ---- CSR build (once) ----
    init_kernel<<<(N_NODES + 255) / 256, 256>>>((const int*)ei);
    hist_kernel<<<eb, 256>>>(ei, E);
    scan_kernel<<<SCAN_G, SCAN_B>>>();
    fill_kernel<<<eb, 256>>>(ei, E);

    // ---- layer 0 ----
    gather_kernel<<<gab, 256>>>(x, agg);
    gemm_mma<DK, 2, true, false><<<gblocks, 256, smemA>>>(
        agg, x, W0l, W0r, b0, h, nullptr, stats0, N_NODES);
    bn_gelu_kernel<<<bgb, 256>>>(h, stats0, g0, be0, x1, n4, invn);

    // ---- layer 1 ----
    gather_kernel<<<gab, 256>>>(x1, agg);
    gemm_mma<DK, 2, true, false><<<gblocks, 256, smemA>>>(
        agg, x1, W1l, W1r, b1, h, nullptr, stats1, N_NODES);
    bn_gelu_kernel<<<bgb, 256>>>(h, stats1, g1, be1, x1, n4, invn);

    // ---- layer 2: gemm first ([y | self+bias]), then 64-wide gather-add ----
    gemm_mma<DK, 1, false, true><<<gblocks, 256, smemA>>>(
        x1, x1, W2l, W2r, b2, out, agg, nullptr, N_NODES);
    gather64_add_kernel<<<gab, 256>>>(agg, out);
}

// round 11
// speedup vs baseline: 1.2286x; 1.0381x over previous
#include <cuda_runtime.h>
#include <cuda_fp16.h>
#include <math.h>
#include <stdint.h>

#define N_NODES 50000
#define E_MAX   1000000
#define DK 128
#define DOUT2 64
#define BN_EPS 1e-5f
#define SCAN_B 1024
#define SCAN_G ((N_NODES + SCAN_B - 1) / SCAN_B)   // 49

// ---------------- scratch ----------------
__device__ float  g_agg[N_NODES * DK];
__device__ float  g_h[N_NODES * DK];
__device__ float  g_x1[N_NODES * DK];
__device__ __half g_xh[N_NODES * DK];    // fp16 gather payload (x or x1)
__device__ __half g_yh[N_NODES * DOUT2]; // fp16 layer-2 neighbor-path
__device__ float  g_stats0[2 * DK];
__device__ float  g_stats1[2 * DK];
__device__ int    g_is64;
__device__ int    g_deg[N_NODES];
__device__ int    g_rowptr[N_NODES + 1];
__device__ int    g_cur[N_NODES];
__device__ int    g_eidx[E_MAX];

// ---------------- helpers ----------------
__device__ __forceinline__ uint32_t f2tf(float f) {
    uint32_t r; asm("cvt.rna.tf32.f32 %0, %1;" : "=r"(r) : "f"(f)); return r;
}
__device__ __forceinline__ void mma_tf32(float* c, const uint32_t* a,
                                         uint32_t b0, uint32_t b1) {
    asm volatile(
        "mma.sync.aligned.m16n8k8.row.col.f32.tf32.tf32.f32 "
        "{%0,%1,%2,%3}, {%4,%5,%6,%7}, {%8,%9}, {%0,%1,%2,%3};"
        : "+f"(c[0]), "+f"(c[1]), "+f"(c[2]), "+f"(c[3])
        : "r"(a[0]), "r"(a[1]), "r"(a[2]), "r"(a[3]), "r"(b0), "r"(b1));
}

// ---------------- init: zero deg + zero stats + detect dtype ----------------
__global__ void init_kernel(const int* __restrict__ ei32) {
    int idx = blockIdx.x * blockDim.x + threadIdx.x;
    if (idx < N_NODES) g_deg[idx] = 0;
    if (blockIdx.x == 0) {
        g_stats0[threadIdx.x] = 0.f;
        g_stats1[threadIdx.x] = 0.f;
    }
    if (blockIdx.x == 1) {
        __shared__ int any;
        if (threadIdx.x == 0) any = 0;
        __syncthreads();
        if (threadIdx.x < 128) {
            int w = 1 + 2 * threadIdx.x;
            if (ei32[w] != 0) atomicOr(&any, 1);
        }
        __syncthreads();
        if (threadIdx.x == 0) g_is64 = (any == 0) ? 1 : 0;
    }
}

// ---------------- fp32 -> fp16 conversion (gather payload) ----------------
__global__ void f2h_kernel(const float* __restrict__ in, __half* __restrict__ out, int n4) {
    int i = blockIdx.x * blockDim.x + threadIdx.x;
    if (i >= n4) return;
    float4 v = ((const float4*)in)[i];
    __half2 h0 = __floats2half2_rn(v.x, v.y);
    __half2 h1 = __floats2half2_rn(v.z, v.w);
    ((uint2*)out)[i] = make_uint2(*(uint32_t*)&h0, *(uint32_t*)&h1);
}

// ---------------- CSR build ----------------
__global__ void hist_kernel(const void* __restrict__ eiv, int E) {
    int i = blockIdx.x * blockDim.x + threadIdx.x;
    if (i >= E) return;
    long long d;
    if (g_is64) d = ((const long long*)eiv)[E + i];
    else        d = ((const int*)eiv)[E + i];
    if ((unsigned long long)d < N_NODES) atomicAdd(&g_deg[(int)d], 1);
}

// single-kernel scan: each block computes its own prefix from g_deg directly
__global__ void scan_kernel() {
    __shared__ int warp_sums[32];
    __shared__ int s_boff;
    int tid  = threadIdx.x;
    int lane = tid & 31, warp = tid >> 5;

    int acc = 0;
    int lim = blockIdx.x * SCAN_B;
    for (int i = tid; i < lim; i += SCAN_B) acc += g_deg[i];
#pragma unroll
    for (int o = 16; o > 0; o >>= 1) acc += __shfl_down_sync(0xffffffffu, acc, o);
    if (lane == 0) warp_sums[warp] = acc;
    __syncthreads();
    if (tid < 32) {
        int w = warp_sums[tid];
#pragma unroll
        for (int o = 16; o > 0; o >>= 1) w += __shfl_down_sync(0xffffffffu, w, o);
        if (tid == 0) s_boff = w;
    }
    __syncthreads();

    int idx = blockIdx.x * SCAN_B + tid;
    int v = (idx < N_NODES) ? g_deg[idx] : 0;
    int s = v;
#pragma unroll
    for (int o = 1; o < 32; o <<= 1) {
        int u = __shfl_up_sync(0xffffffffu, s, o);
        if (lane >= o) s += u;
    }
    if (lane == 31) warp_sums[warp] = s;
    __syncthreads();
    if (warp == 0) {
        int w = warp_sums[lane];
        int ws = w;
#pragma unroll
        for (int o = 1; o < 32; o <<= 1) {
            int u = __shfl_up_sync(0xffffffffu, ws, o);
            if (lane >= o) ws += u;
        }
        warp_sums[lane] = ws - w;
    }
    __syncthreads();
    int excl = s - v + warp_sums[warp] + s_boff;
    if (idx < N_NODES) {
        g_rowptr[idx] = excl;
        g_cur[idx]    = excl;
        if (idx == N_NODES - 1) g_rowptr[N_NODES] = excl + v;
    }
}

__global__ void fill_kernel(const void* __restrict__ eiv, int E) {
    int i = blockIdx.x * blockDim.x + threadIdx.x;
    if (i >= E) return;
    long long s, d;
    if (g_is64) {
        s = ((const long long*)eiv)[i];
        d = ((const long long*)eiv)[E + i];
    } else {
        s = ((const int*)eiv)[i];
        d = ((const int*)eiv)[E + i];
    }
    if ((unsigned long long)s >= N_NODES || (unsigned long long)d >= N_NODES) return;
    int pos = atomicAdd(&g_cur[(int)d], 1);
    g_eidx[pos] = (int)s;
}

// ---------------- gather (128-wide, fp16 in / fp32 out) ----------------
__global__ void __launch_bounds__(256)
gather_kernel(const __half* __restrict__ xh, float* __restrict__ agg) {
    int node = (blockIdx.x * blockDim.x + threadIdx.x) >> 5;
    int lane = threadIdx.x & 31;
    if (node >= N_NODES) return;
    int beg = g_rowptr[node];
    int end = g_rowptr[node + 1];

    float4 a0 = make_float4(0.f, 0.f, 0.f, 0.f);
    float4 a1 = make_float4(0.f, 0.f, 0.f, 0.f);

    for (int base = beg; base < end; base += 32) {
        int n = end - base; if (n > 32) n = 32;
        int myidx = (base + lane < end) ? g_eidx[base + lane] : 0;
        int j = 0;
        for (; j + 3 < n; j += 4) {
            int s0 = __shfl_sync(0xffffffffu, myidx, j);
            int s1 = __shfl_sync(0xffffffffu, myidx, j + 1);
            int s2 = __shfl_sync(0xffffffffu, myidx, j + 2);
            int s3 = __shfl_sync(0xffffffffu, myidx, j + 3);
            uint2 u0 = *(const uint2*)(xh + (size_t)s0 * DK + lane * 4);
            uint2 u1 = *(const uint2*)(xh + (size_t)s1 * DK + lane * 4);
            uint2 u2 = *(const uint2*)(xh + (size_t)s2 * DK + lane * 4);
            uint2 u3 = *(const uint2*)(xh + (size_t)s3 * DK + lane * 4);
            float2 f;
            f = __half22float2(*(__half2*)&u0.x); a0.x += f.x; a0.y += f.y;
            f = __half22float2(*(__half2*)&u0.y); a0.z += f.x; a0.w += f.y;
            f = __half22float2(*(__half2*)&u1.x); a1.x += f.x; a1.y += f.y;
            f = __half22float2(*(__half2*)&u1.y); a1.z += f.x; a1.w += f.y;
            f = __half22float2(*(__half2*)&u2.x); a0.x += f.x; a0.y += f.y;
            f = __half22float2(*(__half2*)&u2.y); a0.z += f.x; a0.w += f.y;
            f = __half22float2(*(__half2*)&u3.x); a1.x += f.x; a1.y += f.y;
            f = __half22float2(*(__half2*)&u3.y); a1.z += f.x; a1.w += f.y;
        }
        for (; j < n; j++) {
            int s0 = __shfl_sync(0xffffffffu, myidx, j);
            uint2 u0 = *(const uint2*)(xh + (size_t)s0 * DK + lane * 4);
            float2 f;
            f = __half22float2(*(__half2*)&u0.x); a0.x += f.x; a0.y += f.y;
            f = __half22float2(*(__half2*)&u0.y); a0.z += f.x; a0.w += f.y;
        }
    }
    a0.x += a1.x; a0.y += a1.y; a0.z += a1.z; a0.w += a1.w;
    *(float4*)(agg + (size_t)node * DK + lane * 4) = a0;
}

// ---------------- gather (64-wide, fp16 in) + accumulate into out ----------
__global__ void __launch_bounds__(256)
gather64_add_kernel(const __half* __restrict__ yh, float* __restrict__ out) {
    int node = (blockIdx.x * blockDim.x + threadIdx.x) >> 5;
    int lane = threadIdx.x & 31;
    if (node >= N_NODES) return;
    int beg = g_rowptr[node];
    int end = g_rowptr[node + 1];

    float2 a0 = make_float2(0.f, 0.f);
    float2 a1 = make_float2(0.f, 0.f);

    for (int base = beg; base < end; base += 32) {
        int n = end - base; if (n > 32) n = 32;
        int myidx = (base + lane < end) ? g_eidx[base + lane] : 0;
        int j = 0;
        for (; j + 3 < n; j += 4) {
            int s0 = __shfl_sync(0xffffffffu, myidx, j);
            int s1 = __shfl_sync(0xffffffffu, myidx, j + 1);
            int s2 = __shfl_sync(0xffffffffu, myidx, j + 2);
            int s3 = __shfl_sync(0xffffffffu, myidx, j + 3);
            uint32_t u0 = *(const uint32_t*)(yh + (size_t)s0 * DOUT2 + lane * 2);
            uint32_t u1 = *(const uint32_t*)(yh + (size_t)s1 * DOUT2 + lane * 2);
            uint32_t u2 = *(const uint32_t*)(yh + (size_t)s2 * DOUT2 + lane * 2);
            uint32_t u3 = *(const uint32_t*)(yh + (size_t)s3 * DOUT2 + lane * 2);
            float2 f;
            f = __half22float2(*(__half2*)&u0); a0.x += f.x; a0.y += f.y;
            f = __half22float2(*(__half2*)&u1); a1.x += f.x; a1.y += f.y;
            f = __half22float2(*(__half2*)&u2); a0.x += f.x; a0.y += f.y;
            f = __half22float2(*(__half2*)&u3); a1.x += f.x; a1.y += f.y;
        }
        for (; j < n; j++) {
            int s0 = __shfl_sync(0xffffffffu, myidx, j);
            uint32_t u0 = *(const uint32_t*)(yh + (size_t)s0 * DOUT2 + lane * 2);
            float2 f = __half22float2(*(__half2*)&u0);
            a0.x += f.x; a0.y += f.y;
        }
    }
    a0.x += a1.x; a0.y += a1.y;
    float2* po = (float2*)(out + (size_t)node * DOUT2 + lane * 2);
    float2 o = *po;
    o.x += a0.x; o.y += a0.y;
    *po = o;
}

// ---------------- mma.sync tf32 GEMM ----------------
// PHASES=2: out = A@Wl + X@Wr + b  (dual K-phase)
// PHASES=1 + SPLIT: cols 0-63 -> yh = fp16(A@Wl); cols 64-127 -> out = A@Wr + b
// STATS: column sum/sumsq of the (bias-added) result accumulated into stats.

template<int DOUT>
struct StageRegs {
    float4 rv[4];
    float4 wv[DOUT == 128 ? 4 : 2];
};

template<int DOUT, bool SPLIT>
__device__ __forceinline__ void ldg_stage(StageRegs<DOUT>& R,
                                          const float* __restrict__ rows,
                                          const float* __restrict__ Wl,
                                          const float* __restrict__ Wr,
                                          int k0, int row0, int nrows, int tid) {
#pragma unroll
    for (int j = 0; j < 4; j++) {
        int idx = tid + j * 256;
        int r = idx >> 3, c4 = idx & 7;
        float4 v = make_float4(0.f, 0.f, 0.f, 0.f);
        if (row0 + r < nrows)
            v = *(const float4*)&rows[(size_t)(row0 + r) * 128 + k0 + c4 * 4];
        R.rv[j] = v;
    }
    constexpr int WI = (DOUT == 128) ? 4 : 2;
#pragma unroll
    for (int j = 0; j < WI; j++) {
        int idx = tid + j * 256;
        int k, c4;
        if (DOUT == 128) { k = idx >> 5; c4 = idx & 31; }
        else             { k = idx >> 4; c4 = idx & 15; }
        if (SPLIT) {
            int c = c4 * 4;
            if (c < 64) R.wv[j] = *(const float4*)&Wl[(size_t)(k0 + k) * 64 + c];
            else        R.wv[j] = *(const float4*)&Wr[(size_t)(k0 + k) * 64 + (c - 64)];
        } else {
            R.wv[j] = *(const float4*)&Wl[(size_t)(k0 + k) * DOUT + c4 * 4];
        }
    }
}

template<int DOUT>
__device__ __forceinline__ void sts_stage(const StageRegs<DOUT>& R,
                                          uint32_t* sA, uint32_t* sW, int tid) {
    constexpr int WST = DOUT + 8;
#pragma unroll
    for (int j = 0; j < 4; j++) {
        int idx = tid + j * 256;
        int r = idx >> 3, c4 = idx & 7;
        float4 v = R.rv[j];
        *(uint4*)&sA[r * 36 + c4 * 4] =
            make_uint4(f2tf(v.x), f2tf(v.y), f2tf(v.z), f2tf(v.w));
    }
    constexpr int WI = (DOUT == 128) ? 4 : 2;
#pragma unroll
    for (int j = 0; j < WI; j++) {
        int idx = tid + j * 256;
        int k, c4;
        if (DOUT == 128) { k = idx >> 5; c4 = idx & 31; }
        else             { k = idx >> 4; c4 = idx & 15; }
        float4 v = R.wv[j];
        *(uint4*)&sW[k * WST + c4 * 4] =
            make_uint4(f2tf(v.x), f2tf(v.y), f2tf(v.z), f2tf(v.w));
    }
}

template<int DOUT, int PHASES, bool STATS, bool SPLIT>
__global__ void __launch_bounds__(256, 1)
gemm_mma(const float* __restrict__ A, const float* __restrict__ X,
         const float* __restrict__ Wl, const float* __restrict__ Wr,
         const float* __restrict__ bias, float* __restrict__ out,
         __half* __restrict__ yh, float* __restrict__ stats, int nrows) {
    constexpr int WST    = DOUT + 8;
    constexpr int NT     = DOUT / 16;
    constexpr int ASZ    = 128 * 36;
    constexpr int NSTAGE = PHASES * 4;

    extern __shared__ uint32_t sm[];
    uint32_t* sA[2] = { sm, sm + ASZ };
    uint32_t* sW[2] = { sm + 2 * ASZ, sm + 2 * ASZ + 32 * WST };

    int tid  = threadIdx.x;
    int wid  = tid >> 5, lane = tid & 31;
    int wr   = wid & 3, wc = wid >> 2;
    int g    = lane >> 2, tg = lane & 3;
    int row0 = blockIdx.x * 128;

    float acc[2][NT][4];
#pragma unroll
    for (int rt = 0; rt < 2; rt++)
#pragma unroll
        for (int ct = 0; ct < NT; ct++)
#pragma unroll
            for (int j = 0; j < 4; j++) acc[rt][ct][j] = 0.f;

    StageRegs<DOUT> R;
    ldg_stage<DOUT, SPLIT>(R, A, Wl, Wr, 0, row0, nrows, tid);
    sts_stage<DOUT>(R, sA[0], sW[0], tid);

#pragma unroll
    for (int s = 0; s < NSTAGE; s++) {
        if (s + 1 < NSTAGE) {
            const float* rows = (PHASES == 2 && s + 1 >= 4) ? X : A;
            const float* W1   = (PHASES == 2 && s + 1 >= 4) ? Wr : Wl;
            ldg_stage<DOUT, SPLIT>(R, rows, W1, Wr, ((s + 1) & 3) * 32, row0, nrows, tid);
        }
        __syncthreads();
        if (s + 1 < NSTAGE) sts_stage<DOUT>(R, sA[(s + 1) & 1], sW[(s + 1) & 1], tid);

        const uint32_t* As = sA[s & 1];
        const uint32_t* Ws = sW[s & 1];
#pragma unroll
        for (int kk = 0; kk < 32; kk += 8) {
            uint32_t a[2][4];
#pragma unroll
            for (int rt = 0; rt < 2; rt++) {
                int rb = wr * 32 + rt * 16;
                a[rt][0] = As[(rb + g) * 36 + kk + tg];
                a[rt][1] = As[(rb + g + 8) * 36 + kk + tg];
                a[rt][2] = As[(rb + g) * 36 + kk + tg + 4];
                a[rt][3] = As[(rb + g + 8) * 36 + kk + tg + 4];
            }
#pragma unroll
            for (int ct = 0; ct < NT; ct++) {
                int nb = wc * (DOUT / 2) + ct * 8 + g;
                uint32_t b0 = Ws[(kk + tg) * WST + nb];
                uint32_t b1 = Ws[(kk + tg + 4) * WST + nb];
                mma_tf32(acc[0][ct], a[0], b0, b1);
                mma_tf32(acc[1][ct], a[1], b0, b1);
            }
        }
    }

    // ---- epilogue ----
    float* sst = (float*)sm;
    if (STATS) {
        __syncthreads();
        sst[tid] = 0.f;
        __syncthreads();
    }

#pragma unroll
    for (int ct = 0; ct < NT; ct++) {
        int nb = wc * (DOUT / 2) + ct * 8 + 2 * tg;
        float b0, b1;
        if (SPLIT) {
            b0 = (nb >= 64) ? bias[nb - 64] : 0.f;
            b1 = (nb >= 64) ? bias[nb - 63] : 0.f;
        } else {
            b0 = bias[nb]; b1 = bias[nb + 1];
        }
        float s0 = 0.f, q0 = 0.f, s1 = 0.f, q1 = 0.f;
#pragma unroll
        for (int rt = 0; rt < 2; rt++) {
            int gr = row0 + wr * 32 + rt * 16 + g;
            float v0 = acc[rt][ct][0] + b0, v1 = acc[rt][ct][1] + b1;
            float v2 = acc[rt][ct][2] + b0, v3 = acc[rt][ct][3] + b1;
            if (gr < nrows) {
                if (SPLIT && nb < 64) {
                    __half2 hv = __floats2half2_rn(v0, v1);
                    *(__half2*)(yh + (size_t)gr * 64 + nb) = hv;
                } else {
                    float* dst = SPLIT ? (out + (size_t)gr * 64 + nb - 64)
                                       : (out + (size_t)gr * DOUT + nb);
                    *(float2*)dst = make_float2(v0, v1);
                }
                if (STATS) { s0 += v0; q0 += v0 * v0; s1 += v1; q1 += v1 * v1; }
            }
            if (gr + 8 < nrows) {
                if (SPLIT && nb < 64) {
                    __half2 hv = __floats2half2_rn(v2, v3);
                    *(__half2*)(yh + (size_t)(gr + 8) * 64 + nb) = hv;
                } else {
                    float* dst = SPLIT ? (out + (size_t)(gr + 8) * 64 + nb - 64)
                                       : (out + (size_t)(gr + 8) * DOUT + nb);
                    *(float2*)dst = make_float2(v2, v3);
                }
                if (STATS) { s0 += v2; q0 += v2 * v2; s1 += v3; q1 += v3 * v3; }
            }
        }
        if (STATS) {
#pragma unroll
            for (int off = 4; off <= 16; off <<= 1) {
                s0 += __shfl_xor_sync(0xffffffffu, s0, off);
                q0 += __shfl_xor_sync(0xffffffffu, q0, off);
                s1 += __shfl_xor_sync(0xffffffffu, s1, off);
                q1 += __shfl_xor_sync(0xffffffffu, q1, off);
            }
            if (g == 0) {
                atomicAdd(&sst[nb],            s0);
                atomicAdd(&sst[DOUT + nb],     q0);
                atomicAdd(&sst[nb + 1],        s1);
                atomicAdd(&sst[DOUT + nb + 1], q1);
            }
        }
    }

    if (STATS) {
        __syncthreads();
        atomicAdd(&stats[tid], sst[tid]);   // tid < 256 == 2*DOUT
    }
}

// ---------------- BN (finalize fused) + exact GELU; dual fp32/fp16 output ----
__device__ __forceinline__ float gelu_exact(float v) {
    return 0.5f * v * (1.0f + erff(v * 0.70710678118654752f));
}

__global__ void bn_gelu_kernel(const float* __restrict__ h,
                               const float* __restrict__ stats,
                               const float* __restrict__ g,
                               const float* __restrict__ be,
                               float* __restrict__ out,
                               __half* __restrict__ outh,
                               int n4, float invn) {
    __shared__ float ssm[2 * DK];
    int t = threadIdx.x;
    if (t < DK) {
        float mu  = stats[t] * invn;
        float var = stats[DK + t] * invn - mu * mu;
        float rs  = rsqrtf(var + BN_EPS);
        float s   = g[t] * rs;
        ssm[t]      = s;
        ssm[DK + t] = be[t] - mu * s;
    }
    __syncthreads();
    int i = blockIdx.x * blockDim.x + t;
    if (i >= n4) return;
    int c4 = i & (DK / 4 - 1);
    float4 v  = ((const float4*)h)[i];
    float4 sc = *(float4*)&ssm[c4 * 4];
    float4 sh = *(float4*)&ssm[DK + c4 * 4];
    v.x = gelu_exact(v.x * sc.x + sh.x);
    v.y = gelu_exact(v.y * sc.y + sh.y);
    v.z = gelu_exact(v.z * sc.z + sh.z);
    v.w = gelu_exact(v.w * sc.w + sh.w);
    ((float4*)out)[i] = v;
    __half2 h0 = __floats2half2_rn(v.x, v.y);
    __half2 h1 = __floats2half2_rn(v.z, v.w);
    ((uint2*)outh)[i] = make_uint2(*(uint32_t*)&h0, *(uint32_t*)&h1);
}

// ---------------- launch ----------------
extern "C" void kernel_launch(void* const* d_in, const int* in_sizes, int n_in,
                              void* d_out, int out_size) {
    const float* x   = (const float*)d_in[0];
    const void*  ei  = d_in[1];
    const float* W0l = (const float*)d_in[2];
    const float* W0r = (const float*)d_in[3];
    const float* b0  = (const float*)d_in[4];
    const float* g0  = (const float*)d_in[5];
    const float* be0 = (const float*)d_in[6];
    const float* W1l = (const float*)d_in[7];
    const float* W1r = (const float*)d_in[8];
    const float* b1  = (const float*)d_in[9];
    const float* g1  = (const float*)d_in[10];
    const float* be1 = (const float*)d_in[11];
    const float* W2l = (const float*)d_in[12];
    const float* W2r = (const float*)d_in[13];
    const float* b2  = (const float*)d_in[14];
    float* out = (float*)d_out;

    int E = in_sizes[1] / 2;
    if (E > E_MAX) E = E_MAX;

    void* p;
    cudaGetSymbolAddress(&p, g_agg);    float*  agg    = (float*)p;
    cudaGetSymbolAddress(&p, g_h);      float*  h      = (float*)p;
    cudaGetSymbolAddress(&p, g_x1);     float*  x1     = (float*)p;
    cudaGetSymbolAddress(&p, g_xh);     __half* xh     = (__half*)p;
    cudaGetSymbolAddress(&p, g_yh);     __half* yh     = (__half*)p;
    cudaGetSymbolAddress(&p, g_stats0); float*  stats0 = (float*)p;
    cudaGetSymbolAddress(&p, g_stats1); float*  stats1 = (float*)p;

    const int smemA = 2 * (128 * 36 + 32 * (128 + 8)) * 4;   // 71680
    cudaFuncSetAttribute((const void*)gemm_mma<DK, 2, true,  false>,
                         cudaFuncAttributeMaxDynamicSharedMemorySize, smemA);
    cudaFuncSetAttribute((const void*)gemm_mma<DK, 1, false, true>,
                         cudaFuncAttributeMaxDynamicSharedMemorySize, smemA);

    int eb      = (E + 255) / 256;
    int gblocks = (N_NODES + 127) / 128;
    int gab     = (N_NODES * 32 + 255) / 256;
    int n4      = N_NODES * DK / 4;
    int bgb     = (n4 + 255) / 256;
    float invn  = 1.0f / (float)N_NODES;

    // ---- CSR build + fp16 copy of x ----
    init_kernel<<<(N_NODES + 255) / 256, 256>>>((const int*)ei);
    f2h_kernel<<<bgb, 256>>>(x, xh, n4);
    hist_kernel<<<eb, 256>>>(ei, E);
    scan_kernel<<<SCAN_G, SCAN_B>>>();
    fill_kernel<<<eb, 256>>>(ei, E);

    // ---- layer 0 ----
    gather_kernel<<<gab, 256>>>(xh, agg);
    gemm_mma<DK, 2, true, false><<<gblocks, 256, smemA>>>(
        agg, x, W0l, W0r, b0, h, nullptr, stats0, N_NODES);
    bn_gelu_kernel<<<bgb, 256>>>(h, stats0, g0, be0, x1, xh, n4, invn);

    // ---- layer 1 ----
    gather_kernel<<<gab, 256>>>(xh, agg);
    gemm_mma<DK, 2, true, false><<<gblocks, 256, smemA>>>(
        agg, x1, W1l, W1r, b1, h, nullptr, stats1, N_NODES);
    bn_gelu_kernel<<<bgb, 256>>>(h, stats1, g1, be1, x1, xh, n4, invn);

    // ---- layer 2: split gemm ([yh fp16 | self+bias fp32]) then gather-add ----
    gemm_mma<DK, 1, false, true><<<gblocks, 256, smemA>>>(
        x1, x1, W2l, W2r, b2, out, yh, nullptr, N_NODES);
    gather64_add_kernel<<<gab, 256>>>(yh, out);
}

// round 12
// speedup vs baseline: 1.2306x; 1.0016x over previous
#include <cuda_runtime.h>
#include <cuda_fp16.h>
#include <math.h>
#include <stdint.h>

#define N_NODES 50000
#define E_MAX   1000000
#define DK 128
#define DOUT2 64
#define BN_EPS 1e-5f
#define SCAN_B 1024
#define SCAN_G ((N_NODES + SCAN_B - 1) / SCAN_B)   // 49
#define EPT 4   // edges per thread in hist/fill

// ---------------- scratch ----------------
__device__ float  g_agg[N_NODES * DK];
__device__ float  g_h[N_NODES * DK];
__device__ float  g_x1[N_NODES * DK];
__device__ __half g_xh[N_NODES * DK];    // fp16 gather payload (x or x1)
__device__ __half g_yh[N_NODES * DOUT2]; // fp16 layer-2 neighbor-path
__device__ float  g_stats0[2 * DK];
__device__ float  g_stats1[2 * DK];
__device__ int    g_is64;
__device__ int    g_deg[N_NODES];
__device__ int    g_rowptr[N_NODES + 1];
__device__ int    g_cur[N_NODES];
__device__ int    g_eidx[E_MAX];

// ---------------- helpers ----------------
__device__ __forceinline__ uint32_t f2tf(float f) {
    uint32_t r; asm("cvt.rna.tf32.f32 %0, %1;" : "=r"(r) : "f"(f)); return r;
}
__device__ __forceinline__ void mma_tf32(float* c, const uint32_t* a,
                                         uint32_t b0, uint32_t b1) {
    asm volatile(
        "mma.sync.aligned.m16n8k8.row.col.f32.tf32.tf32.f32 "
        "{%0,%1,%2,%3}, {%4,%5,%6,%7}, {%8,%9}, {%0,%1,%2,%3};"
        : "+f"(c[0]), "+f"(c[1]), "+f"(c[2]), "+f"(c[3])
        : "r"(a[0]), "r"(a[1]), "r"(a[2]), "r"(a[3]), "r"(b0), "r"(b1));
}

// ---------------- init: zero deg + zero stats + detect dtype + x->fp16 ------
__global__ void init_kernel(const int* __restrict__ ei32,
                            const float* __restrict__ x,
                            __half* __restrict__ xh, int n4) {
    int idx = blockIdx.x * blockDim.x + threadIdx.x;
    if (idx < N_NODES) g_deg[idx] = 0;
    if (idx < n4) {
        float4 v = ((const float4*)x)[idx];
        __half2 h0 = __floats2half2_rn(v.x, v.y);
        __half2 h1 = __floats2half2_rn(v.z, v.w);
        ((uint2*)xh)[idx] = make_uint2(*(uint32_t*)&h0, *(uint32_t*)&h1);
    }
    if (blockIdx.x == 0) {
        g_stats0[threadIdx.x] = 0.f;
        g_stats1[threadIdx.x] = 0.f;
    }
    if (blockIdx.x == 1) {
        __shared__ int any;
        if (threadIdx.x == 0) any = 0;
        __syncthreads();
        if (threadIdx.x < 128) {
            int w = 1 + 2 * threadIdx.x;
            if (ei32[w] != 0) atomicOr(&any, 1);
        }
        __syncthreads();
        if (threadIdx.x == 0) g_is64 = (any == 0) ? 1 : 0;
    }
}

// ---------------- CSR build (batched for atomic MLP) ----------------
__global__ void hist_kernel(const void* __restrict__ eiv, int E) {
    int base = (blockIdx.x * blockDim.x + threadIdx.x) * EPT;
    int is64 = g_is64;
#pragma unroll
    for (int j = 0; j < EPT; j++) {
        int i = base + j;
        if (i >= E) break;
        long long d;
        if (is64) d = ((const long long*)eiv)[E + i];
        else      d = ((const int*)eiv)[E + i];
        if ((unsigned long long)d < N_NODES) atomicAdd(&g_deg[(int)d], 1);
    }
}

// single-kernel scan: each block computes its own prefix from g_deg directly
__global__ void scan_kernel() {
    __shared__ int warp_sums[32];
    __shared__ int s_boff;
    int tid  = threadIdx.x;
    int lane = tid & 31, warp = tid >> 5;

    int acc = 0;
    int lim = blockIdx.x * SCAN_B;
    for (int i = tid; i < lim; i += SCAN_B) acc += g_deg[i];
#pragma unroll
    for (int o = 16; o > 0; o >>= 1) acc += __shfl_down_sync(0xffffffffu, acc, o);
    if (lane == 0) warp_sums[warp] = acc;
    __syncthreads();
    if (tid < 32) {
        int w = warp_sums[tid];
#pragma unroll
        for (int o = 16; o > 0; o >>= 1) w += __shfl_down_sync(0xffffffffu, w, o);
        if (tid == 0) s_boff = w;
    }
    __syncthreads();

    int idx = blockIdx.x * SCAN_B + tid;
    int v = (idx < N_NODES) ? g_deg[idx] : 0;
    int s = v;
#pragma unroll
    for (int o = 1; o < 32; o <<= 1) {
        int u = __shfl_up_sync(0xffffffffu, s, o);
        if (lane >= o) s += u;
    }
    if (lane == 31) warp_sums[warp] = s;
    __syncthreads();
    if (warp == 0) {
        int w = warp_sums[lane];
        int ws = w;
#pragma unroll
        for (int o = 1; o < 32; o <<= 1) {
            int u = __shfl_up_sync(0xffffffffu, ws, o);
            if (lane >= o) ws += u;
        }
        warp_sums[lane] = ws - w;
    }
    __syncthreads();
    int excl = s - v + warp_sums[warp] + s_boff;
    if (idx < N_NODES) {
        g_rowptr[idx] = excl;
        g_cur[idx]    = excl;
        if (idx == N_NODES - 1) g_rowptr[N_NODES] = excl + v;
    }
}

__global__ void fill_kernel(const void* __restrict__ eiv, int E) {
    int base = (blockIdx.x * blockDim.x + threadIdx.x) * EPT;
    int is64 = g_is64;
    int ss[EPT], dd[EPT];
    int cnt = 0;
#pragma unroll
    for (int j = 0; j < EPT; j++) {
        int i = base + j;
        if (i >= E) break;
        long long s, d;
        if (is64) {
            s = ((const long long*)eiv)[i];
            d = ((const long long*)eiv)[E + i];
        } else {
            s = ((const int*)eiv)[i];
            d = ((const int*)eiv)[E + i];
        }
        if ((unsigned long long)s >= N_NODES || (unsigned long long)d >= N_NODES) continue;
        ss[cnt] = (int)s; dd[cnt] = (int)d; cnt++;
    }
    int pos[EPT];
#pragma unroll
    for (int j = 0; j < EPT; j++)
        if (j < cnt) pos[j] = atomicAdd(&g_cur[dd[j]], 1);
#pragma unroll
    for (int j = 0; j < EPT; j++)
        if (j < cnt) g_eidx[pos[j]] = ss[j];
}

// ---------------- gather (128-wide, fp16 in / fp32 out) ----------------
__global__ void __launch_bounds__(256)
gather_kernel(const __half* __restrict__ xh, float* __restrict__ agg) {
    int node = (blockIdx.x * blockDim.x + threadIdx.x) >> 5;
    int lane = threadIdx.x & 31;
    if (node >= N_NODES) return;
    int beg = g_rowptr[node];
    int end = g_rowptr[node + 1];

    float4 a0 = make_float4(0.f, 0.f, 0.f, 0.f);
    float4 a1 = make_float4(0.f, 0.f, 0.f, 0.f);

    for (int base = beg; base < end; base += 32) {
        int n = end - base; if (n > 32) n = 32;
        int myidx = (base + lane < end) ? g_eidx[base + lane] : 0;
        int j = 0;
        for (; j + 3 < n; j += 4) {
            int s0 = __shfl_sync(0xffffffffu, myidx, j);
            int s1 = __shfl_sync(0xffffffffu, myidx, j + 1);
            int s2 = __shfl_sync(0xffffffffu, myidx, j + 2);
            int s3 = __shfl_sync(0xffffffffu, myidx, j + 3);
            uint2 u0 = *(const uint2*)(xh + (size_t)s0 * DK + lane * 4);
            uint2 u1 = *(const uint2*)(xh + (size_t)s1 * DK + lane * 4);
            uint2 u2 = *(const uint2*)(xh + (size_t)s2 * DK + lane * 4);
            uint2 u3 = *(const uint2*)(xh + (size_t)s3 * DK + lane * 4);
            float2 f;
            f = __half22float2(*(__half2*)&u0.x); a0.x += f.x; a0.y += f.y;
            f = __half22float2(*(__half2*)&u0.y); a0.z += f.x; a0.w += f.y;
            f = __half22float2(*(__half2*)&u1.x); a1.x += f.x; a1.y += f.y;
            f = __half22float2(*(__half2*)&u1.y); a1.z += f.x; a1.w += f.y;
            f = __half22float2(*(__half2*)&u2.x); a0.x += f.x; a0.y += f.y;
            f = __half22float2(*(__half2*)&u2.y); a0.z += f.x; a0.w += f.y;
            f = __half22float2(*(__half2*)&u3.x); a1.x += f.x; a1.y += f.y;
            f = __half22float2(*(__half2*)&u3.y); a1.z += f.x; a1.w += f.y;
        }
        for (; j < n; j++) {
            int s0 = __shfl_sync(0xffffffffu, myidx, j);
            uint2 u0 = *(const uint2*)(xh + (size_t)s0 * DK + lane * 4);
            float2 f;
            f = __half22float2(*(__half2*)&u0.x); a0.x += f.x; a0.y += f.y;
            f = __half22float2(*(__half2*)&u0.y); a0.z += f.x; a0.w += f.y;
        }
    }
    a0.x += a1.x; a0.y += a1.y; a0.z += a1.z; a0.w += a1.w;
    *(float4*)(agg + (size_t)node * DK + lane * 4) = a0;
}

// ---------------- gather (64-wide, fp16 in) + accumulate into out ----------
__global__ void __launch_bounds__(256)
gather64_add_kernel(const __half* __restrict__ yh, float* __restrict__ out) {
    int node = (blockIdx.x * blockDim.x + threadIdx.x) >> 5;
    int lane = threadIdx.x & 31;
    if (node >= N_NODES) return;
    int beg = g_rowptr[node];
    int end = g_rowptr[node + 1];

    float2 a0 = make_float2(0.f, 0.f);
    float2 a1 = make_float2(0.f, 0.f);

    for (int base = beg; base < end; base += 32) {
        int n = end - base; if (n > 32) n = 32;
        int myidx = (base + lane < end) ? g_eidx[base + lane] : 0;
        int j = 0;
        for (; j + 3 < n; j += 4) {
            int s0 = __shfl_sync(0xffffffffu, myidx, j);
            int s1 = __shfl_sync(0xffffffffu, myidx, j + 1);
            int s2 = __shfl_sync(0xffffffffu, myidx, j + 2);
            int s3 = __shfl_sync(0xffffffffu, myidx, j + 3);
            uint32_t u0 = *(const uint32_t*)(yh + (size_t)s0 * DOUT2 + lane * 2);
            uint32_t u1 = *(const uint32_t*)(yh + (size_t)s1 * DOUT2 + lane * 2);
            uint32_t u2 = *(const uint32_t*)(yh + (size_t)s2 * DOUT2 + lane * 2);
            uint32_t u3 = *(const uint32_t*)(yh + (size_t)s3 * DOUT2 + lane * 2);
            float2 f;
            f = __half22float2(*(__half2*)&u0); a0.x += f.x; a0.y += f.y;
            f = __half22float2(*(__half2*)&u1); a1.x += f.x; a1.y += f.y;
            f = __half22float2(*(__half2*)&u2); a0.x += f.x; a0.y += f.y;
            f = __half22float2(*(__half2*)&u3); a1.x += f.x; a1.y += f.y;
        }
        for (; j < n; j++) {
            int s0 = __shfl_sync(0xffffffffu, myidx, j);
            uint32_t u0 = *(const uint32_t*)(yh + (size_t)s0 * DOUT2 + lane * 2);
            float2 f = __half22float2(*(__half2*)&u0);
            a0.x += f.x; a0.y += f.y;
        }
    }
    a0.x += a1.x; a0.y += a1.y;
    float2* po = (float2*)(out + (size_t)node * DOUT2 + lane * 2);
    float2 o = *po;
    o.x += a0.x; o.y += a0.y;
    *po = o;
}

// ---------------- mma.sync tf32 GEMM ----------------
// PHASES=2: out = A@Wl + X@Wr + b  (dual K-phase)
// PHASES=1 + SPLIT: cols 0-63 -> yh = fp16(A@Wl); cols 64-127 -> out = A@Wr + b
// STATS: column sum/sumsq of the (bias-added) result accumulated into stats.

template<int DOUT>
struct StageRegs {
    float4 rv[4];
    float4 wv[DOUT == 128 ? 4 : 2];
};

template<int DOUT, bool SPLIT>
__device__ __forceinline__ void ldg_stage(StageRegs<DOUT>& R,
                                          const float* __restrict__ rows,
                                          const float* __restrict__ Wl,
                                          const float* __restrict__ Wr,
                                          int k0, int row0, int nrows, int tid) {
#pragma unroll
    for (int j = 0; j < 4; j++) {
        int idx = tid + j * 256;
        int r = idx >> 3, c4 = idx & 7;
        float4 v = make_float4(0.f, 0.f, 0.f, 0.f);
        if (row0 + r < nrows)
            v = *(const float4*)&rows[(size_t)(row0 + r) * 128 + k0 + c4 * 4];
        R.rv[j] = v;
    }
    constexpr int WI = (DOUT == 128) ? 4 : 2;
#pragma unroll
    for (int j = 0; j < WI; j++) {
        int idx = tid + j * 256;
        int k, c4;
        if (DOUT == 128) { k = idx >> 5; c4 = idx & 31; }
        else             { k = idx >> 4; c4 = idx & 15; }
        if (SPLIT) {
            int c = c4 * 4;
            if (c < 64) R.wv[j] = *(const float4*)&Wl[(size_t)(k0 + k) * 64 + c];
            else        R.wv[j] = *(const float4*)&Wr[(size_t)(k0 + k) * 64 + (c - 64)];
        } else {
            R.wv[j] = *(const float4*)&Wl[(size_t)(k0 + k) * DOUT + c4 * 4];
        }
    }
}

template<int DOUT>
__device__ __forceinline__ void sts_stage(const StageRegs<DOUT>& R,
                                          uint32_t* sA, uint32_t* sW, int tid) {
    constexpr int WST = DOUT + 8;
#pragma unroll
    for (int j = 0; j < 4; j++) {
        int idx = tid + j * 256;
        int r = idx >> 3, c4 = idx & 7;
        float4 v = R.rv[j];
        *(uint4*)&sA[r * 36 + c4 * 4] =
            make_uint4(f2tf(v.x), f2tf(v.y), f2tf(v.z), f2tf(v.w));
    }
    constexpr int WI = (DOUT == 128) ? 4 : 2;
#pragma unroll
    for (int j = 0; j < WI; j++) {
        int idx = tid + j * 256;
        int k, c4;
        if (DOUT == 128) { k = idx >> 5; c4 = idx & 31; }
        else             { k = idx >> 4; c4 = idx & 15; }
        float4 v = R.wv[j];
        *(uint4*)&sW[k * WST + c4 * 4] =
            make_uint4(f2tf(v.x), f2tf(v.y), f2tf(v.z), f2tf(v.w));
    }
}

template<int DOUT, int PHASES, bool STATS, bool SPLIT>
__global__ void __launch_bounds__(256, 1)
gemm_mma(const float* __restrict__ A, const float* __restrict__ X,
         const float* __restrict__ Wl, const float* __restrict__ Wr,
         const float* __restrict__ bias, float* __restrict__ out,
         __half* __restrict__ yh, float* __restrict__ stats, int nrows) {
    constexpr int WST    = DOUT + 8;
    constexpr int NT     = DOUT / 16;
    constexpr int ASZ    = 128 * 36;
    constexpr int NSTAGE = PHASES * 4;

    extern __shared__ uint32_t sm[];
    uint32_t* sA[2] = { sm, sm + ASZ };
    uint32_t* sW[2] = { sm + 2 * ASZ, sm + 2 * ASZ + 32 * WST };

    int tid  = threadIdx.x;
    int wid  = tid >> 5, lane = tid & 31;
    int wr   = wid & 3, wc = wid >> 2;
    int g    = lane >> 2, tg = lane & 3;
    int row0 = blockIdx.x * 128;

    float acc[2][NT][4];
#pragma unroll
    for (int rt = 0; rt < 2; rt++)
#pragma unroll
        for (int ct = 0; ct < NT; ct++)
#pragma unroll
            for (int j = 0; j < 4; j++) acc[rt][ct][j] = 0.f;

    StageRegs<DOUT> R;
    ldg_stage<DOUT, SPLIT>(R, A, Wl, Wr, 0, row0, nrows, tid);
    sts_stage<DOUT>(R, sA[0], sW[0], tid);

#pragma unroll
    for (int s = 0; s < NSTAGE; s++) {
        if (s + 1 < NSTAGE) {
            const float* rows = (PHASES == 2 && s + 1 >= 4) ? X : A;
            const float* W1   = (PHASES == 2 && s + 1 >= 4) ? Wr : Wl;
            ldg_stage<DOUT, SPLIT>(R, rows, W1, Wr, ((s + 1) & 3) * 32, row0, nrows, tid);
        }
        __syncthreads();
        if (s + 1 < NSTAGE) sts_stage<DOUT>(R, sA[(s + 1) & 1], sW[(s + 1) & 1], tid);

        const uint32_t* As = sA[s & 1];
        const uint32_t* Ws = sW[s & 1];
#pragma unroll
        for (int kk = 0; kk < 32; kk += 8) {
            uint32_t a[2][4];
#pragma unroll
            for (int rt = 0; rt < 2; rt++) {
                int rb = wr * 32 + rt * 16;
                a[rt][0] = As[(rb + g) * 36 + kk + tg];
                a[rt][1] = As[(rb + g + 8) * 36 + kk + tg];
                a[rt][2] = As[(rb + g) * 36 + kk + tg + 4];
                a[rt][3] = As[(rb + g + 8) * 36 + kk + tg + 4];
            }
#pragma unroll
            for (int ct = 0; ct < NT; ct++) {
                int nb = wc * (DOUT / 2) + ct * 8 + g;
                uint32_t b0 = Ws[(kk + tg) * WST + nb];
                uint32_t b1 = Ws[(kk + tg + 4) * WST + nb];
                mma_tf32(acc[0][ct], a[0], b0, b1);
                mma_tf32(acc[1][ct], a[1], b0, b1);
            }
        }
    }

    // ---- epilogue ----
    float* sst = (float*)sm;
    if (STATS) {
        __syncthreads();
        sst[tid] = 0.f;
        __syncthreads();
    }

#pragma unroll
    for (int ct = 0; ct < NT; ct++) {
        int nb = wc * (DOUT / 2) + ct * 8 + 2 * tg;
        float b0, b1;
        if (SPLIT) {
            b0 = (nb >= 64) ? bias[nb - 64] : 0.f;
            b1 = (nb >= 64) ? bias[nb - 63] : 0.f;
        } else {
            b0 = bias[nb]; b1 = bias[nb + 1];
        }
        float s0 = 0.f, q0 = 0.f, s1 = 0.f, q1 = 0.f;
#pragma unroll
        for (int rt = 0; rt < 2; rt++) {
            int gr = row0 + wr * 32 + rt * 16 + g;
            float v0 = acc[rt][ct][0] + b0, v1 = acc[rt][ct][1] + b1;
            float v2 = acc[rt][ct][2] + b0, v3 = acc[rt][ct][3] + b1;
            if (gr < nrows) {
                if (SPLIT && nb < 64) {
                    __half2 hv = __floats2half2_rn(v0, v1);
                    *(__half2*)(yh + (size_t)gr * 64 + nb) = hv;
                } else {
                    float* dst = SPLIT ? (out + (size_t)gr * 64 + nb - 64)
                                       : (out + (size_t)gr * DOUT + nb);
                    *(float2*)dst = make_float2(v0, v1);
                }
                if (STATS) { s0 += v0; q0 += v0 * v0; s1 += v1; q1 += v1 * v1; }
            }
            if (gr + 8 < nrows) {
                if (SPLIT && nb < 64) {
                    __half2 hv = __floats2half2_rn(v2, v3);
                    *(__half2*)(yh + (size_t)(gr + 8) * 64 + nb) = hv;
                } else {
                    float* dst = SPLIT ? (out + (size_t)(gr + 8) * 64 + nb - 64)
                                       : (out + (size_t)(gr + 8) * DOUT + nb);
                    *(float2*)dst = make_float2(v2, v3);
                }
                if (STATS) { s0 += v2; q0 += v2 * v2; s1 += v3; q1 += v3 * v3; }
            }
        }
        if (STATS) {
#pragma unroll
            for (int off = 4; off <= 16; off <<= 1) {
                s0 += __shfl_xor_sync(0xffffffffu, s0, off);
                q0 += __shfl_xor_sync(0xffffffffu, q0, off);
                s1 += __shfl_xor_sync(0xffffffffu, s1, off);
                q1 += __shfl_xor_sync(0xffffffffu, q1, off);
            }
            if (g == 0) {
                atomicAdd(&sst[nb],            s0);
                atomicAdd(&sst[DOUT + nb],     q0);
                atomicAdd(&sst[nb + 1],        s1);
                atomicAdd(&sst[DOUT + nb + 1], q1);
            }
        }
    }

    if (STATS) {
        __syncthreads();
        atomicAdd(&stats[tid], sst[tid]);   // tid < 256 == 2*DOUT
    }
}

// ---------------- BN (finalize fused) + exact GELU; dual fp32/fp16 output ----
__device__ __forceinline__ float gelu_exact(float v) {
    return 0.5f * v * (1.0f + erff(v * 0.70710678118654752f));
}

__global__ void bn_gelu_kernel(const float* __restrict__ h,
                               const float* __restrict__ stats,
                               const float* __restrict__ g,
                               const float* __restrict__ be,
                               float* __restrict__ out,
                               __half* __restrict__ outh,
                               int n4, float invn) {
    __shared__ float ssm[2 * DK];
    int t = threadIdx.x;
    if (t < DK) {
        float mu  = stats[t] * invn;
        float var = stats[DK + t] * invn - mu * mu;
        float rs  = rsqrtf(var + BN_EPS);
        float s   = g[t] * rs;
        ssm[t]      = s;
        ssm[DK + t] = be[t] - mu * s;
    }
    __syncthreads();
    int i = blockIdx.x * blockDim.x + t;
    if (i >= n4) return;
    int c4 = i & (DK / 4 - 1);
    float4 v  = ((const float4*)h)[i];
    float4 sc = *(float4*)&ssm[c4 * 4];
    float4 sh = *(float4*)&ssm[DK + c4 * 4];
    v.x = gelu_exact(v.x * sc.x + sh.x);
    v.y = gelu_exact(v.y * sc.y + sh.y);
    v.z = gelu_exact(v.z * sc.z + sh.z);
    v.w = gelu_exact(v.w * sc.w + sh.w);
    ((float4*)out)[i] = v;
    __half2 h0 = __floats2half2_rn(v.x, v.y);
    __half2 h1 = __floats2half2_rn(v.z, v.w);
    ((uint2*)outh)[i] = make_uint2(*(uint32_t*)&h0, *(uint32_t*)&h1);
}

// ---------------- launch ----------------
extern "C" void kernel_launch(void* const* d_in, const int* in_sizes, int n_in,
                              void* d_out, int out_size) {
    const float* x   = (const float*)d_in[0];
    const void*  ei  = d_in[1];
    const float* W0l = (const float*)d_in[2];
    const float* W0r = (const float*)d_in[3];
    const float* b0  = (const float*)d_in[4];
    const float* g0  = (const float*)d_in[5];
    const float* be0 = (const float*)d_in[6];
    const float* W1l = (const float*)d_in[7];
    const float* W1r = (const float*)d_in[8];
    const float* b1  = (const float*)d_in[9];
    const float* g1  = (const float*)d_in[10];
    const float* be1 = (const float*)d_in[11];
    const float* W2l = (const float*)d_in[12];
    const float* W2r = (const float*)d_in[13];
    const float* b2  = (const float*)d_in[14];
    float* out = (float*)d_out;

    int E = in_sizes[1] / 2;
    if (E > E_MAX) E = E_MAX;

    void* p;
    cudaGetSymbolAddress(&p, g_agg);    float*  agg    = (float*)p;
    cudaGetSymbolAddress(&p, g_h);      float*  h      = (float*)p;
    cudaGetSymbolAddress(&p, g_x1);     float*  x1     = (float*)p;
    cudaGetSymbolAddress(&p, g_xh);     __half* xh     = (__half*)p;
    cudaGetSymbolAddress(&p, g_yh);     __half* yh     = (__half*)p;
    cudaGetSymbolAddress(&p, g_stats0); float*  stats0 = (float*)p;
    cudaGetSymbolAddress(&p, g_stats1); float*  stats1 = (float*)p;

    const int smemA = 2 * (128 * 36 + 32 * (128 + 8)) * 4;   // 71680
    cudaFuncSetAttribute((const void*)gemm_mma<DK, 2, true,  false>,
                         cudaFuncAttributeMaxDynamicSharedMemorySize, smemA);
    cudaFuncSetAttribute((const void*)gemm_mma<DK, 1, false, true>,
                         cudaFuncAttributeMaxDynamicSharedMemorySize, smemA);

    int ebb     = (E + 256 * EPT - 1) / (256 * EPT);
    int gblocks = (N_NODES + 127) / 128;
    int gab     = (N_NODES * 32 + 255) / 256;
    int n4      = N_NODES * DK / 4;
    int bgb     = (n4 + 255) / 256;
    float invn  = 1.0f / (float)N_NODES;

    // ---- CSR build (fused init: deg-zero + stats-zero + detect + x->fp16) ----
    init_kernel<<<(n4 + 255) / 256, 256>>>((const int*)ei, x, xh, n4);
    hist_kernel<<<ebb, 256>>>(ei, E);
    scan_kernel<<<SCAN_G, SCAN_B>>>();
    fill_kernel<<<ebb, 256>>>(ei, E);

    // ---- layer 0 ----
    gather_kernel<<<gab, 256>>>(xh, agg);
    gemm_mma<DK, 2, true, false><<<gblocks, 256, smemA>>>(
        agg, x, W0l, W0r, b0, h, nullptr, stats0, N_NODES);
    bn_gelu_kernel<<<bgb, 256>>>(h, stats0, g0, be0, x1, xh, n4, invn);

    // ---- layer 1 ----
    gather_kernel<<<gab, 256>>>(xh, agg);
    gemm_mma<DK, 2, true, false><<<gblocks, 256, smemA>>>(
        agg, x1, W1l, W1r, b1, h, nullptr, stats1, N_NODES);
    bn_gelu_kernel<<<bgb, 256>>>(h, stats1, g1, be1, x1, xh, n4, invn);

    // ---- layer 2: split gemm ([yh fp16 | self+bias fp32]) then gather-add ----
    gemm_mma<DK, 1, false, true><<<gblocks, 256, smemA>>>(
        x1, x1, W2l, W2r, b2, out, yh, nullptr, N_NODES);
    gather64_add_kernel<<<gab, 256>>>(yh, out);
}

// round 13
// speedup vs baseline: 1.2612x; 1.0249x over previous
#include <cuda_runtime.h>
#include <cuda_fp16.h>
#include <math.h>
#include <stdint.h>

#define N_NODES 50000
#define E_MAX   1000000
#define DK 128
#define DOUT2 64
#define BN_EPS 1e-5f
#define SCAN_B 1024
#define SCAN_G ((N_NODES + SCAN_B - 1) / SCAN_B)   // 49

// ---------------- scratch ----------------
__device__ float  g_agg[N_NODES * DK];
__device__ float  g_h[N_NODES * DK];
__device__ __half g_xh[N_NODES * DK];    // fp16 activations (x or gelu output)
__device__ __half g_yh[N_NODES * DOUT2]; // fp16 layer-2 neighbor-path
__device__ float  g_stats0[2 * DK];
__device__ float  g_stats1[2 * DK];
__device__ int    g_is64;
__device__ int    g_deg[N_NODES];
__device__ int    g_rowptr[N_NODES + 1];
__device__ int    g_cur[N_NODES];
__device__ int    g_eidx[E_MAX];

// ---------------- helpers ----------------
__device__ __forceinline__ uint32_t f2tf(float f) {
    uint32_t r; asm("cvt.rna.tf32.f32 %0, %1;" : "=r"(r) : "f"(f)); return r;
}
__device__ __forceinline__ void mma_tf32(float* c, const uint32_t* a,
                                         uint32_t b0, uint32_t b1) {
    asm volatile(
        "mma.sync.aligned.m16n8k8.row.col.f32.tf32.tf32.f32 "
        "{%0,%1,%2,%3}, {%4,%5,%6,%7}, {%8,%9}, {%0,%1,%2,%3};"
        : "+f"(c[0]), "+f"(c[1]), "+f"(c[2]), "+f"(c[3])
        : "r"(a[0]), "r"(a[1]), "r"(a[2]), "r"(a[3]), "r"(b0), "r"(b1));
}

// ---------------- init: zero deg + zero stats + detect dtype + x->fp16 ------
__global__ void init_kernel(const int* __restrict__ ei32,
                            const float* __restrict__ x,
                            __half* __restrict__ xh, int n4) {
    int idx = blockIdx.x * blockDim.x + threadIdx.x;
    if (idx < N_NODES) g_deg[idx] = 0;
    if (idx < n4) {
        float4 v = ((const float4*)x)[idx];
        __half2 h0 = __floats2half2_rn(v.x, v.y);
        __half2 h1 = __floats2half2_rn(v.z, v.w);
        ((uint2*)xh)[idx] = make_uint2(*(uint32_t*)&h0, *(uint32_t*)&h1);
    }
    if (blockIdx.x == 0) {
        g_stats0[threadIdx.x] = 0.f;
        g_stats1[threadIdx.x] = 0.f;
    }
    if (blockIdx.x == 1) {
        __shared__ int any;
        if (threadIdx.x == 0) any = 0;
        __syncthreads();
        if (threadIdx.x < 128) {
            int w = 1 + 2 * threadIdx.x;
            if (ei32[w] != 0) atomicOr(&any, 1);
        }
        __syncthreads();
        if (threadIdx.x == 0) g_is64 = (any == 0) ? 1 : 0;
    }
}

// ---------------- CSR build ----------------
__global__ void hist_kernel(const void* __restrict__ eiv, int E) {
    int i = blockIdx.x * blockDim.x + threadIdx.x;
    if (i >= E) return;
    long long d;
    if (g_is64) d = ((const long long*)eiv)[E + i];
    else        d = ((const int*)eiv)[E + i];
    if ((unsigned long long)d < N_NODES) atomicAdd(&g_deg[(int)d], 1);
}

__global__ void scan_kernel() {
    __shared__ int warp_sums[32];
    __shared__ int s_boff;
    int tid  = threadIdx.x;
    int lane = tid & 31, warp = tid >> 5;

    int acc = 0;
    int lim = blockIdx.x * SCAN_B;
    for (int i = tid; i < lim; i += SCAN_B) acc += g_deg[i];
#pragma unroll
    for (int o = 16; o > 0; o >>= 1) acc += __shfl_down_sync(0xffffffffu, acc, o);
    if (lane == 0) warp_sums[warp] = acc;
    __syncthreads();
    if (tid < 32) {
        int w = warp_sums[tid];
#pragma unroll
        for (int o = 16; o > 0; o >>= 1) w += __shfl_down_sync(0xffffffffu, w, o);
        if (tid == 0) s_boff = w;
    }
    __syncthreads();

    int idx = blockIdx.x * SCAN_B + tid;
    int v = (idx < N_NODES) ? g_deg[idx] : 0;
    int s = v;
#pragma unroll
    for (int o = 1; o < 32; o <<= 1) {
        int u = __shfl_up_sync(0xffffffffu, s, o);
        if (lane >= o) s += u;
    }
    if (lane == 31) warp_sums[warp] = s;
    __syncthreads();
    if (warp == 0) {
        int w = warp_sums[lane];
        int ws = w;
#pragma unroll
        for (int o = 1; o < 32; o <<= 1) {
            int u = __shfl_up_sync(0xffffffffu, ws, o);
            if (lane >= o) ws += u;
        }
        warp_sums[lane] = ws - w;
    }
    __syncthreads();
    int excl = s - v + warp_sums[warp] + s_boff;
    if (idx < N_NODES) {
        g_rowptr[idx] = excl;
        g_cur[idx]    = excl;
        if (idx == N_NODES - 1) g_rowptr[N_NODES] = excl + v;
    }
}

__global__ void fill_kernel(const void* __restrict__ eiv, int E) {
    int i = blockIdx.x * blockDim.x + threadIdx.x;
    if (i >= E) return;
    long long s, d;
    if (g_is64) {
        s = ((const long long*)eiv)[i];
        d = ((const long long*)eiv)[E + i];
    } else {
        s = ((const int*)eiv)[i];
        d = ((const int*)eiv)[E + i];
    }
    if ((unsigned long long)s >= N_NODES || (unsigned long long)d >= N_NODES) return;
    int pos = atomicAdd(&g_cur[(int)d], 1);
    g_eidx[pos] = (int)s;
}

// ---------------- gather (128-wide, fp16 in / fp32 out) ----------------
__global__ void __launch_bounds__(256)
gather_kernel(const __half* __restrict__ xh, float* __restrict__ agg) {
    int node = (blockIdx.x * blockDim.x + threadIdx.x) >> 5;
    int lane = threadIdx.x & 31;
    if (node >= N_NODES) return;
    int beg = g_rowptr[node];
    int end = g_rowptr[node + 1];

    float4 a0 = make_float4(0.f, 0.f, 0.f, 0.f);
    float4 a1 = make_float4(0.f, 0.f, 0.f, 0.f);

    for (int base = beg; base < end; base += 32) {
        int n = end - base; if (n > 32) n = 32;
        int myidx = (base + lane < end) ? g_eidx[base + lane] : 0;
        int j = 0;
        for (; j + 3 < n; j += 4) {
            int s0 = __shfl_sync(0xffffffffu, myidx, j);
            int s1 = __shfl_sync(0xffffffffu, myidx, j + 1);
            int s2 = __shfl_sync(0xffffffffu, myidx, j + 2);
            int s3 = __shfl_sync(0xffffffffu, myidx, j + 3);
            uint2 u0 = *(const uint2*)(xh + (size_t)s0 * DK + lane * 4);
            uint2 u1 = *(const uint2*)(xh + (size_t)s1 * DK + lane * 4);
            uint2 u2 = *(const uint2*)(xh + (size_t)s2 * DK + lane * 4);
            uint2 u3 = *(const uint2*)(xh + (size_t)s3 * DK + lane * 4);
            float2 f;
            f = __half22float2(*(__half2*)&u0.x); a0.x += f.x; a0.y += f.y;
            f = __half22float2(*(__half2*)&u0.y); a0.z += f.x; a0.w += f.y;
            f = __half22float2(*(__half2*)&u1.x); a1.x += f.x; a1.y += f.y;
            f = __half22float2(*(__half2*)&u1.y); a1.z += f.x; a1.w += f.y;
            f = __half22float2(*(__half2*)&u2.x); a0.x += f.x; a0.y += f.y;
            f = __half22float2(*(__half2*)&u2.y); a0.z += f.x; a0.w += f.y;
            f = __half22float2(*(__half2*)&u3.x); a1.x += f.x; a1.y += f.y;
            f = __half22float2(*(__half2*)&u3.y); a1.z += f.x; a1.w += f.y;
        }
        for (; j < n; j++) {
            int s0 = __shfl_sync(0xffffffffu, myidx, j);
            uint2 u0 = *(const uint2*)(xh + (size_t)s0 * DK + lane * 4);
            float2 f;
            f = __half22float2(*(__half2*)&u0.x); a0.x += f.x; a0.y += f.y;
            f = __half22float2(*(__half2*)&u0.y); a0.z += f.x; a0.w += f.y;
        }
    }
    a0.x += a1.x; a0.y += a1.y; a0.z += a1.z; a0.w += a1.w;
    *(float4*)(agg + (size_t)node * DK + lane * 4) = a0;
}

// ---------------- gather (64-wide, fp16 in) + accumulate into out ----------
__global__ void __launch_bounds__(256)
gather64_add_kernel(const __half* __restrict__ yh, float* __restrict__ out) {
    int node = (blockIdx.x * blockDim.x + threadIdx.x) >> 5;
    int lane = threadIdx.x & 31;
    if (node >= N_NODES) return;
    int beg = g_rowptr[node];
    int end = g_rowptr[node + 1];

    float2 a0 = make_float2(0.f, 0.f);
    float2 a1 = make_float2(0.f, 0.f);

    for (int base = beg; base < end; base += 32) {
        int n = end - base; if (n > 32) n = 32;
        int myidx = (base + lane < end) ? g_eidx[base + lane] : 0;
        int j = 0;
        for (; j + 3 < n; j += 4) {
            int s0 = __shfl_sync(0xffffffffu, myidx, j);
            int s1 = __shfl_sync(0xffffffffu, myidx, j + 1);
            int s2 = __shfl_sync(0xffffffffu, myidx, j + 2);
            int s3 = __shfl_sync(0xffffffffu, myidx, j + 3);
            uint32_t u0 = *(const uint32_t*)(yh + (size_t)s0 * DOUT2 + lane * 2);
            uint32_t u1 = *(const uint32_t*)(yh + (size_t)s1 * DOUT2 + lane * 2);
            uint32_t u2 = *(const uint32_t*)(yh + (size_t)s2 * DOUT2 + lane * 2);
            uint32_t u3 = *(const uint32_t*)(yh + (size_t)s3 * DOUT2 + lane * 2);
            float2 f;
            f = __half22float2(*(__half2*)&u0); a0.x += f.x; a0.y += f.y;
            f = __half22float2(*(__half2*)&u1); a1.x += f.x; a1.y += f.y;
            f = __half22float2(*(__half2*)&u2); a0.x += f.x; a0.y += f.y;
            f = __half22float2(*(__half2*)&u3); a1.x += f.x; a1.y += f.y;
        }
        for (; j < n; j++) {
            int s0 = __shfl_sync(0xffffffffu, myidx, j);
            uint32_t u0 = *(const uint32_t*)(yh + (size_t)s0 * DOUT2 + lane * 2);
            float2 f = __half22float2(*(__half2*)&u0);
            a0.x += f.x; a0.y += f.y;
        }
    }
    a0.x += a1.x; a0.y += a1.y;
    float2* po = (float2*)(out + (size_t)node * DOUT2 + lane * 2);
    float2 o = *po;
    o.x += a0.x; o.y += a0.y;
    *po = o;
}

// ---------------- mma.sync tf32 GEMM (fp32 agg phase, fp16 row phase) -------
// PHASES=2: out = A(fp32)@Wl + Xh(fp16)@Wr + b
// PHASES=1 + SPLIT: rows = Xh fp16; cols 0-63 -> yh = fp16(Xh@Wl); 64-127 -> out = Xh@Wr + b
// STATS: column sum/sumsq of the (bias-added) result accumulated into stats.

template<int DOUT>
struct StageRegs {
    float4 rv[4];                       // fp32 row regs
    uint2  hv[4];                       // fp16 row regs (4 halfs each)
    float4 wv[DOUT == 128 ? 4 : 2];
};

template<int DOUT, bool SPLIT>
__device__ __forceinline__ void ldg_stage(StageRegs<DOUT>& R, bool useHalf,
                                          const float* __restrict__ rowsF,
                                          const __half* __restrict__ rowsH,
                                          const float* __restrict__ Wl,
                                          const float* __restrict__ Wr,
                                          int k0, int row0, int nrows, int tid) {
#pragma unroll
    for (int j = 0; j < 4; j++) {
        int idx = tid + j * 256;
        int r = idx >> 3, c4 = idx & 7;
        if (useHalf) {
            uint2 u = make_uint2(0u, 0u);
            if (row0 + r < nrows)
                u = *(const uint2*)&rowsH[(size_t)(row0 + r) * 128 + k0 + c4 * 4];
            R.hv[j] = u;
        } else {
            float4 v = make_float4(0.f, 0.f, 0.f, 0.f);
            if (row0 + r < nrows)
                v = *(const float4*)&rowsF[(size_t)(row0 + r) * 128 + k0 + c4 * 4];
            R.rv[j] = v;
        }
    }
    constexpr int WI = (DOUT == 128) ? 4 : 2;
#pragma unroll
    for (int j = 0; j < WI; j++) {
        int idx = tid + j * 256;
        int k, c4;
        if (DOUT == 128) { k = idx >> 5; c4 = idx & 31; }
        else             { k = idx >> 4; c4 = idx & 15; }
        if (SPLIT) {
            int c = c4 * 4;
            if (c < 64) R.wv[j] = *(const float4*)&Wl[(size_t)(k0 + k) * 64 + c];
            else        R.wv[j] = *(const float4*)&Wr[(size_t)(k0 + k) * 64 + (c - 64)];
        } else {
            R.wv[j] = *(const float4*)&Wl[(size_t)(k0 + k) * DOUT + c4 * 4];
        }
    }
}

template<int DOUT>
__device__ __forceinline__ void sts_stage(const StageRegs<DOUT>& R, bool useHalf,
                                          uint32_t* sA, uint32_t* sW, int tid) {
    constexpr int WST = DOUT + 8;
#pragma unroll
    for (int j = 0; j < 4; j++) {
        int idx = tid + j * 256;
        int r = idx >> 3, c4 = idx & 7;
        uint4 o;
        if (useHalf) {
            uint2 u = R.hv[j];
            float2 f01 = __half22float2(*(__half2*)&u.x);
            float2 f23 = __half22float2(*(__half2*)&u.y);
            o = make_uint4(f2tf(f01.x), f2tf(f01.y), f2tf(f23.x), f2tf(f23.y));
        } else {
            float4 v = R.rv[j];
            o = make_uint4(f2tf(v.x), f2tf(v.y), f2tf(v.z), f2tf(v.w));
        }
        *(uint4*)&sA[r * 36 + c4 * 4] = o;
    }
    constexpr int WI = (DOUT == 128) ? 4 : 2;
#pragma unroll
    for (int j = 0; j < WI; j++) {
        int idx = tid + j * 256;
        int k, c4;
        if (DOUT == 128) { k = idx >> 5; c4 = idx & 31; }
        else             { k = idx >> 4; c4 = idx & 15; }
        float4 v = R.wv[j];
        *(uint4*)&sW[k * WST + c4 * 4] =
            make_uint4(f2tf(v.x), f2tf(v.y), f2tf(v.z), f2tf(v.w));
    }
}

template<int DOUT, int PHASES, bool STATS, bool SPLIT>
__global__ void __launch_bounds__(256, 1)
gemm_mma(const float* __restrict__ A, const __half* __restrict__ Xh,
         const float* __restrict__ Wl, const float* __restrict__ Wr,
         const float* __restrict__ bias, float* __restrict__ out,
         __half* __restrict__ yh, float* __restrict__ stats, int nrows) {
    constexpr int WST    = DOUT + 8;
    constexpr int NT     = DOUT / 16;
    constexpr int ASZ    = 128 * 36;
    constexpr int NSTAGE = PHASES * 4;

    extern __shared__ uint32_t sm[];
    uint32_t* sA[2] = { sm, sm + ASZ };
    uint32_t* sW[2] = { sm + 2 * ASZ, sm + 2 * ASZ + 32 * WST };

    int tid  = threadIdx.x;
    int wid  = tid >> 5, lane = tid & 31;
    int wr   = wid & 3, wc = wid >> 2;
    int g    = lane >> 2, tg = lane & 3;
    int row0 = blockIdx.x * 128;

    float acc[2][NT][4];
#pragma unroll
    for (int rt = 0; rt < 2; rt++)
#pragma unroll
        for (int ct = 0; ct < NT; ct++)
#pragma unroll
            for (int j = 0; j < 4; j++) acc[rt][ct][j] = 0.f;

    StageRegs<DOUT> R;
    const bool half0 = SPLIT;   // stage 0: SPLIT reads fp16 rows, dual reads fp32 agg
    ldg_stage<DOUT, SPLIT>(R, half0, A, Xh, Wl, Wr, 0, row0, nrows, tid);
    sts_stage<DOUT>(R, half0, sA[0], sW[0], tid);

#pragma unroll
    for (int s = 0; s < NSTAGE; s++) {
        bool hn = false;
        if (s + 1 < NSTAGE) {
            hn = SPLIT || (PHASES == 2 && s + 1 >= 4);
            const float* W1 = (PHASES == 2 && s + 1 >= 4) ? Wr : Wl;
            ldg_stage<DOUT, SPLIT>(R, hn, A, Xh, W1, Wr, ((s + 1) & 3) * 32,
                                   row0, nrows, tid);
        }
        __syncthreads();
        if (s + 1 < NSTAGE) sts_stage<DOUT>(R, hn, sA[(s + 1) & 1], sW[(s + 1) & 1], tid);

        const uint32_t* As = sA[s & 1];
        const uint32_t* Ws = sW[s & 1];
#pragma unroll
        for (int kk = 0; kk < 32; kk += 8) {
            uint32_t a[2][4];
#pragma unroll
            for (int rt = 0; rt < 2; rt++) {
                int rb = wr * 32 + rt * 16;
                a[rt][0] = As[(rb + g) * 36 + kk + tg];
                a[rt][1] = As[(rb + g + 8) * 36 + kk + tg];
                a[rt][2] = As[(rb + g) * 36 + kk + tg + 4];
                a[rt][3] = As[(rb + g + 8) * 36 + kk + tg + 4];
            }
#pragma unroll
            for (int ct = 0; ct < NT; ct++) {
                int nb = wc * (DOUT / 2) + ct * 8 + g;
                uint32_t b0 = Ws[(kk + tg) * WST + nb];
                uint32_t b1 = Ws[(kk + tg + 4) * WST + nb];
                mma_tf32(acc[0][ct], a[0], b0, b1);
                mma_tf32(acc[1][ct], a[1], b0, b1);
            }
        }
    }

    // ---- epilogue ----
    float* sst = (float*)sm;
    if (STATS) {
        __syncthreads();
        sst[tid] = 0.f;
        __syncthreads();
    }

#pragma unroll
    for (int ct = 0; ct < NT; ct++) {
        int nb = wc * (DOUT / 2) + ct * 8 + 2 * tg;
        float b0, b1;
        if (SPLIT) {
            b0 = (nb >= 64) ? bias[nb - 64] : 0.f;
            b1 = (nb >= 64) ? bias[nb - 63] : 0.f;
        } else {
            b0 = bias[nb]; b1 = bias[nb + 1];
        }
        float s0 = 0.f, q0 = 0.f, s1 = 0.f, q1 = 0.f;
#pragma unroll
        for (int rt = 0; rt < 2; rt++) {
            int gr = row0 + wr * 32 + rt * 16 + g;
            float v0 = acc[rt][ct][0] + b0, v1 = acc[rt][ct][1] + b1;
            float v2 = acc[rt][ct][2] + b0, v3 = acc[rt][ct][3] + b1;
            if (gr < nrows) {
                if (SPLIT && nb < 64) {
                    __half2 hv = __floats2half2_rn(v0, v1);
                    *(__half2*)(yh + (size_t)gr * 64 + nb) = hv;
                } else {
                    float* dst = SPLIT ? (out + (size_t)gr * 64 + nb - 64)
                                       : (out + (size_t)gr * DOUT + nb);
                    *(float2*)dst = make_float2(v0, v1);
                }
                if (STATS) { s0 += v0; q0 += v0 * v0; s1 += v1; q1 += v1 * v1; }
            }
            if (gr + 8 < nrows) {
                if (SPLIT && nb < 64) {
                    __half2 hv = __floats2half2_rn(v2, v3);
                    *(__half2*)(yh + (size_t)(gr + 8) * 64 + nb) = hv;
                } else {
                    float* dst = SPLIT ? (out + (size_t)(gr + 8) * 64 + nb - 64)
                                       : (out + (size_t)(gr + 8) * DOUT + nb);
                    *(float2*)dst = make_float2(v2, v3);
                }
                if (STATS) { s0 += v2; q0 += v2 * v2; s1 += v3; q1 += v3 * v3; }
            }
        }
        if (STATS) {
#pragma unroll
            for (int off = 4; off <= 16; off <<= 1) {
                s0 += __shfl_xor_sync(0xffffffffu, s0, off);
                q0 += __shfl_xor_sync(0xffffffffu, q0, off);
                s1 += __shfl_xor_sync(0xffffffffu, s1, off);
                q1 += __shfl_xor_sync(0xffffffffu, q1, off);
            }
            if (g == 0) {
                atomicAdd(&sst[nb],            s0);
                atomicAdd(&sst[DOUT + nb],     q0);
                atomicAdd(&sst[nb + 1],        s1);
                atomicAdd(&sst[DOUT + nb + 1], q1);
            }
        }
    }

    if (STATS) {
        __syncthreads();
        atomicAdd(&stats[tid], sst[tid]);   // tid < 256 == 2*DOUT
    }
}

// ---------------- BN (finalize fused) + exact GELU; fp16 output only ----
__device__ __forceinline__ float gelu_exact(float v) {
    return 0.5f * v * (1.0f + erff(v * 0.70710678118654752f));
}

__global__ void bn_gelu_kernel(const float* __restrict__ h,
                               const float* __restrict__ stats,
                               const float* __restrict__ g,
                               const float* __restrict__ be,
                               __half* __restrict__ outh,
                               int n4, float invn) {
    __shared__ float ssm[2 * DK];
    int t = threadIdx.x;
    if (t < DK) {
        float mu  = stats[t] * invn;
        float var = stats[DK + t] * invn - mu * mu;
        float rs  = rsqrtf(var + BN_EPS);
        float s   = g[t] * rs;
        ssm[t]      = s;
        ssm[DK + t] = be[t] - mu * s;
    }
    __syncthreads();
    int i = blockIdx.x * blockDim.x + t;
    if (i >= n4) return;
    int c4 = i & (DK / 4 - 1);
    float4 v  = ((const float4*)h)[i];
    float4 sc = *(float4*)&ssm[c4 * 4];
    float4 sh = *(float4*)&ssm[DK + c4 * 4];
    v.x = gelu_exact(v.x * sc.x + sh.x);
    v.y = gelu_exact(v.y * sc.y + sh.y);
    v.z = gelu_exact(v.z * sc.z + sh.z);
    v.w = gelu_exact(v.w * sc.w + sh.w);
    __half2 h0 = __floats2half2_rn(v.x, v.y);
    __half2 h1 = __floats2half2_rn(v.z, v.w);
    ((uint2*)outh)[i] = make_uint2(*(uint32_t*)&h0, *(uint32_t*)&h1);
}

// ---------------- launch ----------------
extern "C" void kernel_launch(void* const* d_in, const int* in_sizes, int n_in,
                              void* d_out, int out_size) {
    const float* x   = (const float*)d_in[0];
    const void*  ei  = d_in[1];
    const float* W0l = (const float*)d_in[2];
    const float* W0r = (const float*)d_in[3];
    const float* b0  = (const float*)d_in[4];
    const float* g0  = (const float*)d_in[5];
    const float* be0 = (const float*)d_in[6];
    const float* W1l = (const float*)d_in[7];
    const float* W1r = (const float*)d_in[8];
    const float* b1  = (const float*)d_in[9];
    const float* g1  = (const float*)d_in[10];
    const float* be1 = (const float*)d_in[11];
    const float* W2l = (const float*)d_in[12];
    const float* W2r = (const float*)d_in[13];
    const float* b2  = (const float*)d_in[14];
    float* out = (float*)d_out;

    int E = in_sizes[1] / 2;
    if (E > E_MAX) E = E_MAX;

    void* p;
    cudaGetSymbolAddress(&p, g_agg);    float*  agg    = (float*)p;
    cudaGetSymbolAddress(&p, g_h);      float*  h      = (float*)p;
    cudaGetSymbolAddress(&p, g_xh);     __half* xh     = (__half*)p;
    cudaGetSymbolAddress(&p, g_yh);     __half* yh     = (__half*)p;
    cudaGetSymbolAddress(&p, g_stats0); float*  stats0 = (float*)p;
    cudaGetSymbolAddress(&p, g_stats1); float*  stats1 = (float*)p;

    const int smemA = 2 * (128 * 36 + 32 * (128 + 8)) * 4;   // 71680
    cudaFuncSetAttribute((const void*)gemm_mma<DK, 2, true,  false>,
                         cudaFuncAttributeMaxDynamicSharedMemorySize, smemA);
    cudaFuncSetAttribute((const void*)gemm_mma<DK, 1, false, true>,
                         cudaFuncAttributeMaxDynamicSharedMemorySize, smemA);

    int eb      = (E + 255) / 256;
    int gblocks = (N_NODES + 127) / 128;
    int gab     = (N_NODES * 32 + 255) / 256;
    int n4      = N_NODES * DK / 4;
    int bgb     = (n4 + 255) / 256;
    float invn  = 1.0f / (float)N_NODES;

    // ---- CSR build (fused init: deg-zero + stats-zero + detect + x->fp16) ----
    init_kernel<<<(n4 + 255) / 256, 256>>>((const int*)ei, x, xh, n4);
    hist_kernel<<<eb, 256>>>(ei, E);
    scan_kernel<<<SCAN_G, SCAN_B>>>();
    fill_kernel<<<eb, 256>>>(ei, E);

    // ---- layer 0 ----
    gather_kernel<<<gab, 256>>>(xh, agg);
    gemm_mma<DK, 2, true, false><<<gblocks, 256, smemA>>>(
        agg, xh, W0l, W0r, b0, h, nullptr, stats0, N_NODES);
    bn_gelu_kernel<<<bgb, 256>>>(h, stats0, g0, be0, xh, n4, invn);

    // ---- layer 1 ----
    gather_kernel<<<gab, 256>>>(xh, agg);
    gemm_mma<DK, 2, true, false><<<gblocks, 256, smemA>>>(
        agg, xh, W1l, W1r, b1, h, nullptr, stats1, N_NODES);
    bn_gelu_kernel<<<bgb, 256>>>(h, stats1, g1, be1, xh, n4, invn);

    // ---- layer 2: split gemm ([yh fp16 | self+bias fp32]) then gather-add ----
    gemm_mma<DK, 1, false, true><<<gblocks, 256, smemA>>>(
        agg, xh, W2l, W2r, b2, out, yh, nullptr, N_NODES);
    gather64_add_kernel<<<gab, 256>>>(yh, out);
}

// round 15
// speedup vs baseline: 1.2761x; 1.0118x over previous
#include <cuda_runtime.h>
#include <cuda_fp16.h>
#include <math.h>
#include <stdint.h>

#define N_NODES 50000
#define E_MAX   1000000
#define DK 128
#define DOUT2 64
#define BN_EPS 1e-5f
#define SCAN_B 1024
#define SCAN_G ((N_NODES + SCAN_B - 1) / SCAN_B)   // 49

// ---------------- scratch ----------------
__device__ float  g_agg[N_NODES * DK];
__device__ __half g_hh[N_NODES * DK];    // fp16 pre-BN hidden
__device__ __half g_xh[N_NODES * DK];    // fp16 activations (x or gelu output)
__device__ __half g_yh[N_NODES * DOUT2]; // fp16 layer-2 neighbor-path
__device__ float  g_stats0[2 * DK];
__device__ float  g_stats1[2 * DK];
__device__ int    g_is64;
__device__ int    g_deg[N_NODES];
__device__ int    g_rowptr[N_NODES + 1];
__device__ int    g_cur[N_NODES];
__device__ int    g_eidx[E_MAX];

// ---------------- helpers ----------------
__device__ __forceinline__ uint32_t f2tf(float f) {
    uint32_t r; asm("cvt.rna.tf32.f32 %0, %1;" : "=r"(r) : "f"(f)); return r;
}
__device__ __forceinline__ void mma_tf32(float* c, const uint32_t* a,
                                         uint32_t b0, uint32_t b1) {
    asm volatile(
        "mma.sync.aligned.m16n8k8.row.col.f32.tf32.tf32.f32 "
        "{%0,%1,%2,%3}, {%4,%5,%6,%7}, {%8,%9}, {%0,%1,%2,%3};"
        : "+f"(c[0]), "+f"(c[1]), "+f"(c[2]), "+f"(c[3])
        : "r"(a[0]), "r"(a[1]), "r"(a[2]), "r"(a[3]), "r"(b0), "r"(b1));
}

// ---------------- init: zero deg + zero stats + detect dtype + x->fp16 ------
__global__ void init_kernel(const int* __restrict__ ei32,
                            const float* __restrict__ x,
                            __half* __restrict__ xh, int n4) {
    int idx = blockIdx.x * blockDim.x + threadIdx.x;
    if (idx < N_NODES) g_deg[idx] = 0;
    if (idx < n4) {
        float4 v = ((const float4*)x)[idx];
        __half2 h0 = __floats2half2_rn(v.x, v.y);
        __half2 h1 = __floats2half2_rn(v.z, v.w);
        ((uint2*)xh)[idx] = make_uint2(*(uint32_t*)&h0, *(uint32_t*)&h1);
    }
    if (blockIdx.x == 0) {
        g_stats0[threadIdx.x] = 0.f;
        g_stats1[threadIdx.x] = 0.f;
    }
    if (blockIdx.x == 1) {
        __shared__ int any;
        if (threadIdx.x == 0) any = 0;
        __syncthreads();
        if (threadIdx.x < 128) {
            int w = 1 + 2 * threadIdx.x;
            if (ei32[w] != 0) atomicOr(&any, 1);
        }
        __syncthreads();
        if (threadIdx.x == 0) g_is64 = (any == 0) ? 1 : 0;
    }
}

// ---------------- CSR build ----------------
__global__ void hist_kernel(const void* __restrict__ eiv, int E) {
    int i = blockIdx.x * blockDim.x + threadIdx.x;
    if (i >= E) return;
    long long d;
    if (g_is64) d = ((const long long*)eiv)[E + i];
    else        d = ((const int*)eiv)[E + i];
    if ((unsigned long long)d < N_NODES) atomicAdd(&g_deg[(int)d], 1);
}

__global__ void scan_kernel() {
    __shared__ int warp_sums[32];
    __shared__ int s_boff;
    int tid  = threadIdx.x;
    int lane = tid & 31, warp = tid >> 5;

    int acc = 0;
    int lim = blockIdx.x * SCAN_B;
    for (int i = tid; i < lim; i += SCAN_B) acc += g_deg[i];
#pragma unroll
    for (int o = 16; o > 0; o >>= 1) acc += __shfl_down_sync(0xffffffffu, acc, o);
    if (lane == 0) warp_sums[warp] = acc;
    __syncthreads();
    if (tid < 32) {
        int w = warp_sums[tid];
#pragma unroll
        for (int o = 16; o > 0; o >>= 1) w += __shfl_down_sync(0xffffffffu, w, o);
        if (tid == 0) s_boff = w;
    }
    __syncthreads();

    int idx = blockIdx.x * SCAN_B + tid;
    int v = (idx < N_NODES) ? g_deg[idx] : 0;
    int s = v;
#pragma unroll
    for (int o = 1; o < 32; o <<= 1) {
        int u = __shfl_up_sync(0xffffffffu, s, o);
        if (lane >= o) s += u;
    }
    if (lane == 31) warp_sums[warp] = s;
    __syncthreads();
    if (warp == 0) {
        int w = warp_sums[lane];
        int ws = w;
#pragma unroll
        for (int o = 1; o < 32; o <<= 1) {
            int u = __shfl_up_sync(0xffffffffu, ws, o);
            if (lane >= o) ws += u;
        }
        warp_sums[lane] = ws - w;
    }
    __syncthreads();
    int excl = s - v + warp_sums[warp] + s_boff;
    if (idx < N_NODES) {
        g_rowptr[idx] = excl;
        g_cur[idx]    = excl;
        if (idx == N_NODES - 1) g_rowptr[N_NODES] = excl + v;
    }
}

__global__ void fill_kernel(const void* __restrict__ eiv, int E) {
    int i = blockIdx.x * blockDim.x + threadIdx.x;
    if (i >= E) return;
    long long s, d;
    if (g_is64) {
        s = ((const long long*)eiv)[i];
        d = ((const long long*)eiv)[E + i];
    } else {
        s = ((const int*)eiv)[i];
        d = ((const int*)eiv)[E + i];
    }
    if ((unsigned long long)s >= N_NODES || (unsigned long long)d >= N_NODES) return;
    int pos = atomicAdd(&g_cur[(int)d], 1);
    g_eidx[pos] = (int)s;
}

// ---------------- gather (128-wide, fp16 in / fp32 out) ----------------
__global__ void __launch_bounds__(256)
gather_kernel(const __half* __restrict__ xh, float* __restrict__ agg) {
    int node = (blockIdx.x * blockDim.x + threadIdx.x) >> 5;
    int lane = threadIdx.x & 31;
    if (node >= N_NODES) return;
    int beg = g_rowptr[node];
    int end = g_rowptr[node + 1];

    float4 a0 = make_float4(0.f, 0.f, 0.f, 0.f);
    float4 a1 = make_float4(0.f, 0.f, 0.f, 0.f);

    for (int base = beg; base < end; base += 32) {
        int n = end - base; if (n > 32) n = 32;
        int myidx = (base + lane < end) ? g_eidx[base + lane] : 0;
        int j = 0;
        for (; j + 3 < n; j += 4) {
            int s0 = __shfl_sync(0xffffffffu, myidx, j);
            int s1 = __shfl_sync(0xffffffffu, myidx, j + 1);
            int s2 = __shfl_sync(0xffffffffu, myidx, j + 2);
            int s3 = __shfl_sync(0xffffffffu, myidx, j + 3);
            uint2 u0 = *(const uint2*)(xh + (size_t)s0 * DK + lane * 4);
            uint2 u1 = *(const uint2*)(xh + (size_t)s1 * DK + lane * 4);
            uint2 u2 = *(const uint2*)(xh + (size_t)s2 * DK + lane * 4);
            uint2 u3 = *(const uint2*)(xh + (size_t)s3 * DK + lane * 4);
            float2 f;
            f = __half22float2(*(__half2*)&u0.x); a0.x += f.x; a0.y += f.y;
            f = __half22float2(*(__half2*)&u0.y); a0.z += f.x; a0.w += f.y;
            f = __half22float2(*(__half2*)&u1.x); a1.x += f.x; a1.y += f.y;
            f = __half22float2(*(__half2*)&u1.y); a1.z += f.x; a1.w += f.y;
            f = __half22float2(*(__half2*)&u2.x); a0.x += f.x; a0.y += f.y;
            f = __half22float2(*(__half2*)&u2.y); a0.z += f.x; a0.w += f.y;
            f = __half22float2(*(__half2*)&u3.x); a1.x += f.x; a1.y += f.y;
            f = __half22float2(*(__half2*)&u3.y); a1.z += f.x; a1.w += f.y;
        }
        for (; j < n; j++) {
            int s0 = __shfl_sync(0xffffffffu, myidx, j);
            uint2 u0 = *(const uint2*)(xh + (size_t)s0 * DK + lane * 4);
            float2 f;
            f = __half22float2(*(__half2*)&u0.x); a0.x += f.x; a0.y += f.y;
            f = __half22float2(*(__half2*)&u0.y); a0.z += f.x; a0.w += f.y;
        }
    }
    a0.x += a1.x; a0.y += a1.y; a0.z += a1.z; a0.w += a1.w;
    *(float4*)(agg + (size_t)node * DK + lane * 4) = a0;
}

// ---------------- gather (64-wide, fp16 in) + accumulate into out ----------
__global__ void __launch_bounds__(256)
gather64_add_kernel(const __half* __restrict__ yh, float* __restrict__ out) {
    int node = (blockIdx.x * blockDim.x + threadIdx.x) >> 5;
    int lane = threadIdx.x & 31;
    if (node >= N_NODES) return;
    int beg = g_rowptr[node];
    int end = g_rowptr[node + 1];

    float2 a0 = make_float2(0.f, 0.f);
    float2 a1 = make_float2(0.f, 0.f);

    for (int base = beg; base < end; base += 32) {
        int n = end - base; if (n > 32) n = 32;
        int myidx = (base + lane < end) ? g_eidx[base + lane] : 0;
        int j = 0;
        for (; j + 3 < n; j += 4) {
            int s0 = __shfl_sync(0xffffffffu, myidx, j);
            int s1 = __shfl_sync(0xffffffffu, myidx, j + 1);
            int s2 = __shfl_sync(0xffffffffu, myidx, j + 2);
            int s3 = __shfl_sync(0xffffffffu, myidx, j + 3);
            uint32_t u0 = *(const uint32_t*)(yh + (size_t)s0 * DOUT2 + lane * 2);
            uint32_t u1 = *(const uint32_t*)(yh + (size_t)s1 * DOUT2 + lane * 2);
            uint32_t u2 = *(const uint32_t*)(yh + (size_t)s2 * DOUT2 + lane * 2);
            uint32_t u3 = *(const uint32_t*)(yh + (size_t)s3 * DOUT2 + lane * 2);
            float2 f;
            f = __half22float2(*(__half2*)&u0); a0.x += f.x; a0.y += f.y;
            f = __half22float2(*(__half2*)&u1); a1.x += f.x; a1.y += f.y;
            f = __half22float2(*(__half2*)&u2); a0.x += f.x; a0.y += f.y;
            f = __half22float2(*(__half2*)&u3); a1.x += f.x; a1.y += f.y;
        }
        for (; j < n; j++) {
            int s0 = __shfl_sync(0xffffffffu, myidx, j);
            uint32_t u0 = *(const uint32_t*)(yh + (size_t)s0 * DOUT2 + lane * 2);
            float2 f = __half22float2(*(__half2*)&u0);
            a0.x += f.x; a0.y += f.y;
        }
    }
    a0.x += a1.x; a0.y += a1.y;
    float2* po = (float2*)(out + (size_t)node * DOUT2 + lane * 2);
    float2 o = *po;
    o.x += a0.x; o.y += a0.y;
    *po = o;
}

// ---------------- mma.sync tf32 GEMM (fp32 agg phase, fp16 row phase) -------
// PHASES=2: hh(fp16, [N,128]) = A(fp32)@Wl + Xh(fp16)@Wr + b  (+ fp32 stats)
// PHASES=1 + SPLIT: rows = Xh fp16; cols 0-63 -> yh(fp16, [N,64]) = Xh@Wl;
//                   cols 64-127 -> out(fp32, [N,64]) = Xh@Wr + b

template<int DOUT>
struct StageRegs {
    float4 rv[4];                       // fp32 row regs
    uint2  hv[4];                       // fp16 row regs (4 halfs each)
    float4 wv[DOUT == 128 ? 4 : 2];
};

template<int DOUT, bool SPLIT>
__device__ __forceinline__ void ldg_stage(StageRegs<DOUT>& R, bool useHalf,
                                          const float* __restrict__ rowsF,
                                          const __half* __restrict__ rowsH,
                                          const float* __restrict__ Wl,
                                          const float* __restrict__ Wr,
                                          int k0, int row0, int nrows, int tid) {
#pragma unroll
    for (int j = 0; j < 4; j++) {
        int idx = tid + j * 256;
        int r = idx >> 3, c4 = idx & 7;
        if (useHalf) {
            uint2 u = make_uint2(0u, 0u);
            if (row0 + r < nrows)
                u = *(const uint2*)&rowsH[(size_t)(row0 + r) * 128 + k0 + c4 * 4];
            R.hv[j] = u;
        } else {
            float4 v = make_float4(0.f, 0.f, 0.f, 0.f);
            if (row0 + r < nrows)
                v = *(const float4*)&rowsF[(size_t)(row0 + r) * 128 + k0 + c4 * 4];
            R.rv[j] = v;
        }
    }
    constexpr int WI = (DOUT == 128) ? 4 : 2;
#pragma unroll
    for (int j = 0; j < WI; j++) {
        int idx = tid + j * 256;
        int k, c4;
        if (DOUT == 128) { k = idx >> 5; c4 = idx & 31; }
        else             { k = idx >> 4; c4 = idx & 15; }
        if (SPLIT) {
            int c = c4 * 4;
            if (c < 64) R.wv[j] = *(const float4*)&Wl[(size_t)(k0 + k) * 64 + c];
            else        R.wv[j] = *(const float4*)&Wr[(size_t)(k0 + k) * 64 + (c - 64)];
        } else {
            R.wv[j] = *(const float4*)&Wl[(size_t)(k0 + k) * DOUT + c4 * 4];
        }
    }
}

template<int DOUT>
__device__ __forceinline__ void sts_stage(const StageRegs<DOUT>& R, bool useHalf,
                                          uint32_t* sA, uint32_t* sW, int tid) {
    constexpr int WST = DOUT + 8;
#pragma unroll
    for (int j = 0; j < 4; j++) {
        int idx = tid + j * 256;
        int r = idx >> 3, c4 = idx & 7;
        uint4 o;
        if (useHalf) {
            uint2 u = R.hv[j];
            float2 f01 = __half22float2(*(__half2*)&u.x);
            float2 f23 = __half22float2(*(__half2*)&u.y);
            o = make_uint4(f2tf(f01.x), f2tf(f01.y), f2tf(f23.x), f2tf(f23.y));
        } else {
            float4 v = R.rv[j];
            o = make_uint4(f2tf(v.x), f2tf(v.y), f2tf(v.z), f2tf(v.w));
        }
        *(uint4*)&sA[r * 36 + c4 * 4] = o;
    }
    constexpr int WI = (DOUT == 128) ? 4 : 2;
#pragma unroll
    for (int j = 0; j < WI; j++) {
        int idx = tid + j * 256;
        int k, c4;
        if (DOUT == 128) { k = idx >> 5; c4 = idx & 31; }
        else             { k = idx >> 4; c4 = idx & 15; }
        float4 v = R.wv[j];
        *(uint4*)&sW[k * WST + c4 * 4] =
            make_uint4(f2tf(v.x), f2tf(v.y), f2tf(v.z), f2tf(v.w));
    }
}

template<int DOUT, int PHASES, bool STATS, bool SPLIT>
__global__ void __launch_bounds__(256, 1)
gemm_mma(const float* __restrict__ A, const __half* __restrict__ Xh,
         const float* __restrict__ Wl, const float* __restrict__ Wr,
         const float* __restrict__ bias, float* __restrict__ out,
         __half* __restrict__ ho, float* __restrict__ stats, int nrows) {
    constexpr int WST    = DOUT + 8;
    constexpr int NT     = DOUT / 16;
    constexpr int ASZ    = 128 * 36;
    constexpr int NSTAGE = PHASES * 4;
    constexpr int HOST   = SPLIT ? 64 : DOUT;   // ho row stride (halfs)

    extern __shared__ uint32_t sm[];
    uint32_t* sA[2] = { sm, sm + ASZ };
    uint32_t* sW[2] = { sm + 2 * ASZ, sm + 2 * ASZ + 32 * WST };

    int tid  = threadIdx.x;
    int wid  = tid >> 5, lane = tid & 31;
    int wr   = wid & 3, wc = wid >> 2;
    int g    = lane >> 2, tg = lane & 3;
    int row0 = blockIdx.x * 128;

    float acc[2][NT][4];
#pragma unroll
    for (int rt = 0; rt < 2; rt++)
#pragma unroll
        for (int ct = 0; ct < NT; ct++)
#pragma unroll
            for (int j = 0; j < 4; j++) acc[rt][ct][j] = 0.f;

    StageRegs<DOUT> R;
    const bool half0 = SPLIT;   // stage 0: SPLIT reads fp16 rows, dual reads fp32 agg
    ldg_stage<DOUT, SPLIT>(R, half0, A, Xh, Wl, Wr, 0, row0, nrows, tid);
    sts_stage<DOUT>(R, half0, sA[0], sW[0], tid);

#pragma unroll
    for (int s = 0; s < NSTAGE; s++) {
        bool hn = false;
        if (s + 1 < NSTAGE) {
            hn = SPLIT || (PHASES == 2 && s + 1 >= 4);
            const float* W1 = (PHASES == 2 && s + 1 >= 4) ? Wr : Wl;
            ldg_stage<DOUT, SPLIT>(R, hn, A, Xh, W1, Wr, ((s + 1) & 3) * 32,
                                   row0, nrows, tid);
        }
        __syncthreads();
        if (s + 1 < NSTAGE) sts_stage<DOUT>(R, hn, sA[(s + 1) & 1], sW[(s + 1) & 1], tid);

        const uint32_t* As = sA[s & 1];
        const uint32_t* Ws = sW[s & 1];
#pragma unroll
        for (int kk = 0; kk < 32; kk += 8) {
            uint32_t a[2][4];
#pragma unroll
            for (int rt = 0; rt < 2; rt++) {
                int rb = wr * 32 + rt * 16;
                a[rt][0] = As[(rb + g) * 36 + kk + tg];
                a[rt][1] = As[(rb + g + 8) * 36 + kk + tg];
                a[rt][2] = As[(rb + g) * 36 + kk + tg + 4];
                a[rt][3] = As[(rb + g + 8) * 36 + kk + tg + 4];
            }
#pragma unroll
            for (int ct = 0; ct < NT; ct++) {
                int nb = wc * (DOUT / 2) + ct * 8 + g;
                uint32_t b0 = Ws[(kk + tg) * WST + nb];
                uint32_t b1 = Ws[(kk + tg + 4) * WST + nb];
                mma_tf32(acc[0][ct], a[0], b0, b1);
                mma_tf32(acc[1][ct], a[1], b0, b1);
            }
        }
    }

    // ---- epilogue ----
    float* sst = (float*)sm;
    if (STATS) {
        __syncthreads();
        sst[tid] = 0.f;
        __syncthreads();
    }

#pragma unroll
    for (int ct = 0; ct < NT; ct++) {
        int nb = wc * (DOUT / 2) + ct * 8 + 2 * tg;
        float b0, b1;
        if (SPLIT) {
            b0 = (nb >= 64) ? bias[nb - 64] : 0.f;
            b1 = (nb >= 64) ? bias[nb - 63] : 0.f;
        } else {
            b0 = bias[nb]; b1 = bias[nb + 1];
        }
        float s0 = 0.f, q0 = 0.f, s1 = 0.f, q1 = 0.f;
#pragma unroll
        for (int rt = 0; rt < 2; rt++) {
            int gr = row0 + wr * 32 + rt * 16 + g;
            float v0 = acc[rt][ct][0] + b0, v1 = acc[rt][ct][1] + b1;
            float v2 = acc[rt][ct][2] + b0, v3 = acc[rt][ct][3] + b1;
            if (gr < nrows) {
                if (!SPLIT || nb < 64) {
                    __half2 hv = __floats2half2_rn(v0, v1);
                    *(__half2*)(ho + (size_t)gr * HOST + nb) = hv;
                } else {
                    *(float2*)(out + (size_t)gr * 64 + nb - 64) = make_float2(v0, v1);
                }
                if (STATS) { s0 += v0; q0 += v0 * v0; s1 += v1; q1 += v1 * v1; }
            }
            if (gr + 8 < nrows) {
                if (!SPLIT || nb < 64) {
                    __half2 hv = __floats2half2_rn(v2, v3);
                    *(__half2*)(ho + (size_t)(gr + 8) * HOST + nb) = hv;
                } else {
                    *(float2*)(out + (size_t)(gr + 8) * 64 + nb - 64) = make_float2(v2, v3);
                }
                if (STATS) { s0 += v2; q0 += v2 * v2; s1 += v3; q1 += v3 * v3; }
            }
        }
        if (STATS) {
#pragma unroll
            for (int off = 4; off <= 16; off <<= 1) {
                s0 += __shfl_xor_sync(0xffffffffu, s0, off);
                q0 += __shfl_xor_sync(0xffffffffu, q0, off);
                s1 += __shfl_xor_sync(0xffffffffu, s1, off);
                q1 += __shfl_xor_sync(0xffffffffu, q1, off);
            }
            if (g == 0) {
                atomicAdd(&sst[nb],            s0);
                atomicAdd(&sst[DOUT + nb],     q0);
                atomicAdd(&sst[nb + 1],        s1);
                atomicAdd(&sst[DOUT + nb + 1], q1);
            }
        }
    }

    if (STATS) {
        __syncthreads();
        atomicAdd(&stats[tid], sst[tid]);   // tid < 256 == 2*DOUT
    }
}

// ---------------- BN (finalize fused) + exact GELU; fp16 in, fp16 out ----
__device__ __forceinline__ float gelu_exact(float v) {
    return 0.5f * v * (1.0f + erff(v * 0.70710678118654752f));
}

__global__ void bn_gelu_kernel(const __half* __restrict__ hh,
                               const float* __restrict__ stats,
                               const float* __restrict__ g,
                               const float* __restrict__ be,
                               __half* __restrict__ outh,
                               int n4, float invn) {
    __shared__ float ssm[2 * DK];
    int t = threadIdx.x;
    if (t < DK) {
        float mu  = stats[t] * invn;
        float var = stats[DK + t] * invn - mu * mu;
        float rs  = rsqrtf(var + BN_EPS);
        float s   = g[t] * rs;
        ssm[t]      = s;
        ssm[DK + t] = be[t] - mu * s;
    }
    __syncthreads();
    int i = blockIdx.x * blockDim.x + t;
    if (i >= n4) return;
    int c4 = i & (DK / 4 - 1);
    uint2 u = ((const uint2*)hh)[i];
    float2 f01 = __half22float2(*(__half2*)&u.x);
    float2 f23 = __half22float2(*(__half2*)&u.y);
    float4 sc = *(float4*)&ssm[c4 * 4];
    float4 sh = *(float4*)&ssm[DK + c4 * 4];
    float4 v;
    v.x = gelu_exact(f01.x * sc.x + sh.x);
    v.y = gelu_exact(f01.y * sc.y + sh.y);
    v.z = gelu_exact(f23.x * sc.z + sh.z);
    v.w = gelu_exact(f23.y * sc.w + sh.w);
    __half2 h0 = __floats2half2_rn(v.x, v.y);
    __half2 h1 = __floats2half2_rn(v.z, v.w);
    ((uint2*)outh)[i] = make_uint2(*(uint32_t*)&h0, *(uint32_t*)&h1);
}

// ---------------- launch ----------------
extern "C" void kernel_launch(void* const* d_in, const int* in_sizes, int n_in,
                              void* d_out, int out_size) {
    const float* x   = (const float*)d_in[0];
    const void*  ei  = d_in[1];
    const float* W0l = (const float*)d_in[2];
    const float* W0r = (const float*)d_in[3];
    const float* b0  = (const float*)d_in[4];
    const float* g0  = (const float*)d_in[5];
    const float* be0 = (const float*)d_in[6];
    const float* W1l = (const float*)d_in[7];
    const float* W1r = (const float*)d_in[8];
    const float* b1  = (const float*)d_in[9];
    const float* g1  = (const float*)d_in[10];
    const float* be1 = (const float*)d_in[11];
    const float* W2l = (const float*)d_in[12];
    const float* W2r = (const float*)d_in[13];
    const float* b2  = (const float*)d_in[14];
    float* out = (float*)d_out;

    int E = in_sizes[1] / 2;
    if (E > E_MAX) E = E_MAX;

    void* p;
    cudaGetSymbolAddress(&p, g_agg);    float*  agg    = (float*)p;
    cudaGetSymbolAddress(&p, g_hh);     __half* hh     = (__half*)p;
    cudaGetSymbolAddress(&p, g_xh);     __half* xh     = (__half*)p;
    cudaGetSymbolAddress(&p, g_yh);     __half* yh     = (__half*)p;
    cudaGetSymbolAddress(&p, g_stats0); float*  stats0 = (float*)p;
    cudaGetSymbolAddress(&p, g_stats1); float*  stats1 = (float*)p;

    const int smemA = 2 * (128 * 36 + 32 * (128 + 8)) * 4;   // 71680
    cudaFuncSetAttribute((const void*)gemm_mma<DK, 2, true,  false>,
                         cudaFuncAttributeMaxDynamicSharedMemorySize, smemA);
    cudaFuncSetAttribute((const void*)gemm_mma<DK, 1, false, true>,
                         cudaFuncAttributeMaxDynamicSharedMemorySize, smemA);

    int eb      = (E + 255) / 256;
    int gblocks = (N_NODES + 127) / 128;
    int gab     = (N_NODES * 32 + 255) / 256;
    int n4      = N_NODES * DK / 4;
    int bgb     = (n4 + 255) / 256;
    float invn  = 1.0f / (float)N_NODES;

    // ---- CSR build (fused init: deg-zero + stats-zero + detect + x->fp16) ----
    init_kernel<<<(n4 + 255) / 256, 256>>>((const int*)ei, x, xh, n4);
    hist_kernel<<<eb, 256>>>(ei, E);
    scan_kernel<<<SCAN_G, SCAN_B>>>();
    fill_kernel<<<eb, 256>>>(ei, E);

    // ---- layer 0 ----
    gather_kernel<<<gab, 256>>>(xh, agg);
    gemm_mma<DK, 2, true, false><<<gblocks, 256, smemA>>>(
        agg, xh, W0l, W0r, b0, nullptr, hh, stats0, N_NODES);
    bn_gelu_kernel<<<bgb, 256>>>(hh, stats0, g0, be0, xh, n4, invn);

    // ---- layer 1 ----
    gather_kernel<<<gab, 256>>>(xh, agg);
    gemm_mma<DK, 2, true, false><<<gblocks, 256, smemA>>>(
        agg, xh, W1l, W1r, b1, nullptr, hh, stats1, N_NODES);
    bn_gelu_kernel<<<bgb, 256>>>(hh, stats1, g1, be1, xh, n4, invn);

    // ---- layer 2: split gemm ([yh fp16 | self+bias fp32]) then gather-add ----
    gemm_mma<DK, 1, false, true><<<gblocks, 256, smemA>>>(
        agg, xh, W2l, W2r, b2, out, yh, nullptr, N_NODES);
    gather64_add_kernel<<<gab, 256>>>(yh, out);
}

// round 16
// speedup vs baseline: 1.2869x; 1.0085x over previous
#include <cuda_runtime.h>
#include <cuda_fp16.h>
#include <math.h>
#include <stdint.h>

#define N_NODES 50000
#define E_MAX   1000000
#define DK 128
#define DOUT2 64
#define BN_EPS 1e-5f
#define SCAN_B 1024
#define SCAN_G ((N_NODES + SCAN_B - 1) / SCAN_B)   // 49

// ---------------- scratch ----------------
__device__ float  g_agg[N_NODES * DK];
__device__ __half g_hh[N_NODES * DK];    // fp16 pre-BN hidden
__device__ __half g_xh[N_NODES * DK];    // fp16 activations (x or gelu output)
__device__ __half g_yh[N_NODES * DOUT2]; // fp16 layer-2 neighbor-path
__device__ float  g_stats0[2 * DK];
__device__ float  g_stats1[2 * DK];
__device__ int    g_is64;
__device__ int    g_deg[N_NODES];
__device__ int    g_rowptr[N_NODES + 1];
__device__ int    g_rank[E_MAX];         // per-edge rank within destination
__device__ int    g_eidx[E_MAX];

// ---------------- helpers ----------------
__device__ __forceinline__ uint32_t f2tf(float f) {
    uint32_t r; asm("cvt.rna.tf32.f32 %0, %1;" : "=r"(r) : "f"(f)); return r;
}
__device__ __forceinline__ void mma_tf32(float* c, const uint32_t* a,
                                         uint32_t b0, uint32_t b1) {
    asm volatile(
        "mma.sync.aligned.m16n8k8.row.col.f32.tf32.tf32.f32 "
        "{%0,%1,%2,%3}, {%4,%5,%6,%7}, {%8,%9}, {%0,%1,%2,%3};"
        : "+f"(c[0]), "+f"(c[1]), "+f"(c[2]), "+f"(c[3])
        : "r"(a[0]), "r"(a[1]), "r"(a[2]), "r"(a[3]), "r"(b0), "r"(b1));
}

// ---------------- init: zero deg + zero stats + detect dtype + x->fp16 ------
__global__ void init_kernel(const int* __restrict__ ei32,
                            const float* __restrict__ x,
                            __half* __restrict__ xh, int n4) {
    int idx = blockIdx.x * blockDim.x + threadIdx.x;
    if (idx < N_NODES) g_deg[idx] = 0;
    if (idx < n4) {
        float4 v = ((const float4*)x)[idx];
        __half2 h0 = __floats2half2_rn(v.x, v.y);
        __half2 h1 = __floats2half2_rn(v.z, v.w);
        ((uint2*)xh)[idx] = make_uint2(*(uint32_t*)&h0, *(uint32_t*)&h1);
    }
    if (blockIdx.x == 0) {
        g_stats0[threadIdx.x] = 0.f;
        g_stats1[threadIdx.x] = 0.f;
    }
    if (blockIdx.x == 1) {
        __shared__ int any;
        if (threadIdx.x == 0) any = 0;
        __syncthreads();
        if (threadIdx.x < 128) {
            int w = 1 + 2 * threadIdx.x;
            if (ei32[w] != 0) atomicOr(&any, 1);
        }
        __syncthreads();
        if (threadIdx.x == 0) g_is64 = (any == 0) ? 1 : 0;
    }
}

// ---------------- CSR build ----------------
// hist: histogram destination degrees AND record each edge's rank (the
// returned pre-increment count) so fill needs no atomics.
__global__ void hist_kernel(const void* __restrict__ eiv, int E) {
    int i = blockIdx.x * blockDim.x + threadIdx.x;
    if (i >= E) return;
    long long d;
    if (g_is64) d = ((const long long*)eiv)[E + i];
    else        d = ((const int*)eiv)[E + i];
    if ((unsigned long long)d < N_NODES)
        g_rank[i] = atomicAdd(&g_deg[(int)d], 1);
}

__global__ void scan_kernel() {
    __shared__ int warp_sums[32];
    __shared__ int s_boff;
    int tid  = threadIdx.x;
    int lane = tid & 31, warp = tid >> 5;

    int acc = 0;
    int lim = blockIdx.x * SCAN_B;
    for (int i = tid; i < lim; i += SCAN_B) acc += g_deg[i];
#pragma unroll
    for (int o = 16; o > 0; o >>= 1) acc += __shfl_down_sync(0xffffffffu, acc, o);
    if (lane == 0) warp_sums[warp] = acc;
    __syncthreads();
    if (tid < 32) {
        int w = warp_sums[tid];
#pragma unroll
        for (int o = 16; o > 0; o >>= 1) w += __shfl_down_sync(0xffffffffu, w, o);
        if (tid == 0) s_boff = w;
    }
    __syncthreads();

    int idx = blockIdx.x * SCAN_B + tid;
    int v = (idx < N_NODES) ? g_deg[idx] : 0;
    int s = v;
#pragma unroll
    for (int o = 1; o < 32; o <<= 1) {
        int u = __shfl_up_sync(0xffffffffu, s, o);
        if (lane >= o) s += u;
    }
    if (lane == 31) warp_sums[warp] = s;
    __syncthreads();
    if (warp == 0) {
        int w = warp_sums[lane];
        int ws = w;
#pragma unroll
        for (int o = 1; o < 32; o <<= 1) {
            int u = __shfl_up_sync(0xffffffffu, ws, o);
            if (lane >= o) ws += u;
        }
        warp_sums[lane] = ws - w;
    }
    __syncthreads();
    int excl = s - v + warp_sums[warp] + s_boff;
    if (idx < N_NODES) {
        g_rowptr[idx] = excl;
        if (idx == N_NODES - 1) g_rowptr[N_NODES] = excl + v;
    }
}

// fill: atomic-free scatter using precomputed ranks
__global__ void fill_kernel(const void* __restrict__ eiv, int E) {
    int i = blockIdx.x * blockDim.x + threadIdx.x;
    if (i >= E) return;
    long long s, d;
    if (g_is64) {
        s = ((const long long*)eiv)[i];
        d = ((const long long*)eiv)[E + i];
    } else {
        s = ((const int*)eiv)[i];
        d = ((const int*)eiv)[E + i];
    }
    if ((unsigned long long)s >= N_NODES || (unsigned long long)d >= N_NODES) return;
    g_eidx[g_rowptr[(int)d] + g_rank[i]] = (int)s;
}

// ---------------- gather (128-wide, fp16 in / fp32 out) ----------------
__global__ void __launch_bounds__(256)
gather_kernel(const __half* __restrict__ xh, float* __restrict__ agg) {
    int node = (blockIdx.x * blockDim.x + threadIdx.x) >> 5;
    int lane = threadIdx.x & 31;
    if (node >= N_NODES) return;
    int beg = g_rowptr[node];
    int end = g_rowptr[node + 1];

    float4 a0 = make_float4(0.f, 0.f, 0.f, 0.f);
    float4 a1 = make_float4(0.f, 0.f, 0.f, 0.f);

    for (int base = beg; base < end; base += 32) {
        int n = end - base; if (n > 32) n = 32;
        int myidx = (base + lane < end) ? g_eidx[base + lane] : 0;
        int j = 0;
        for (; j + 3 < n; j += 4) {
            int s0 = __shfl_sync(0xffffffffu, myidx, j);
            int s1 = __shfl_sync(0xffffffffu, myidx, j + 1);
            int s2 = __shfl_sync(0xffffffffu, myidx, j + 2);
            int s3 = __shfl_sync(0xffffffffu, myidx, j + 3);
            uint2 u0 = *(const uint2*)(xh + (size_t)s0 * DK + lane * 4);
            uint2 u1 = *(const uint2*)(xh + (size_t)s1 * DK + lane * 4);
            uint2 u2 = *(const uint2*)(xh + (size_t)s2 * DK + lane * 4);
            uint2 u3 = *(const uint2*)(xh + (size_t)s3 * DK + lane * 4);
            float2 f;
            f = __half22float2(*(__half2*)&u0.x); a0.x += f.x; a0.y += f.y;
            f = __half22float2(*(__half2*)&u0.y); a0.z += f.x; a0.w += f.y;
            f = __half22float2(*(__half2*)&u1.x); a1.x += f.x; a1.y += f.y;
            f = __half22float2(*(__half2*)&u1.y); a1.z += f.x; a1.w += f.y;
            f = __half22float2(*(__half2*)&u2.x); a0.x += f.x; a0.y += f.y;
            f = __half22float2(*(__half2*)&u2.y); a0.z += f.x; a0.w += f.y;
            f = __half22float2(*(__half2*)&u3.x); a1.x += f.x; a1.y += f.y;
            f = __half22float2(*(__half2*)&u3.y); a1.z += f.x; a1.w += f.y;
        }
        for (; j < n; j++) {
            int s0 = __shfl_sync(0xffffffffu, myidx, j);
            uint2 u0 = *(const uint2*)(xh + (size_t)s0 * DK + lane * 4);
            float2 f;
            f = __half22float2(*(__half2*)&u0.x); a0.x += f.x; a0.y += f.y;
            f = __half22float2(*(__half2*)&u0.y); a0.z += f.x; a0.w += f.y;
        }
    }
    a0.x += a1.x; a0.y += a1.y; a0.z += a1.z; a0.w += a1.w;
    *(float4*)(agg + (size_t)node * DK + lane * 4) = a0;
}

// ---------------- gather (64-wide, fp16 in) + accumulate into out ----------
__global__ void __launch_bounds__(256)
gather64_add_kernel(const __half* __restrict__ yh, float* __restrict__ out) {
    int node = (blockIdx.x * blockDim.x + threadIdx.x) >> 5;
    int lane = threadIdx.x & 31;
    if (node >= N_NODES) return;
    int beg = g_rowptr[node];
    int end = g_rowptr[node + 1];

    float2 a0 = make_float2(0.f, 0.f);
    float2 a1 = make_float2(0.f, 0.f);

    for (int base = beg; base < end; base += 32) {
        int n = end - base; if (n > 32) n = 32;
        int myidx = (base + lane < end) ? g_eidx[base + lane] : 0;
        int j = 0;
        for (; j + 3 < n; j += 4) {
            int s0 = __shfl_sync(0xffffffffu, myidx, j);
            int s1 = __shfl_sync(0xffffffffu, myidx, j + 1);
            int s2 = __shfl_sync(0xffffffffu, myidx, j + 2);
            int s3 = __shfl_sync(0xffffffffu, myidx, j + 3);
            uint32_t u0 = *(const uint32_t*)(yh + (size_t)s0 * DOUT2 + lane * 2);
            uint32_t u1 = *(const uint32_t*)(yh + (size_t)s1 * DOUT2 + lane * 2);
            uint32_t u2 = *(const uint32_t*)(yh + (size_t)s2 * DOUT2 + lane * 2);
            uint32_t u3 = *(const uint32_t*)(yh + (size_t)s3 * DOUT2 + lane * 2);
            float2 f;
            f = __half22float2(*(__half2*)&u0); a0.x += f.x; a0.y += f.y;
            f = __half22float2(*(__half2*)&u1); a1.x += f.x; a1.y += f.y;
            f = __half22float2(*(__half2*)&u2); a0.x += f.x; a0.y += f.y;
            f = __half22float2(*(__half2*)&u3); a1.x += f.x; a1.y += f.y;
        }
        for (; j < n; j++) {
            int s0 = __shfl_sync(0xffffffffu, myidx, j);
            uint32_t u0 = *(const uint32_t*)(yh + (size_t)s0 * DOUT2 + lane * 2);
            float2 f = __half22float2(*(__half2*)&u0);
            a0.x += f.x; a0.y += f.y;
        }
    }
    a0.x += a1.x; a0.y += a1.y;
    float2* po = (float2*)(out + (size_t)node * DOUT2 + lane * 2);
    float2 o = *po;
    o.x += a0.x; o.y += a0.y;
    *po = o;
}

// ---------------- mma.sync tf32 GEMM (fp32 agg phase, fp16 row phase) -------
// PHASES=2: hh(fp16, [N,128]) = A(fp32)@Wl + Xh(fp16)@Wr + b  (+ fp32 stats)
// PHASES=1 + SPLIT: rows = Xh fp16; cols 0-63 -> yh(fp16, [N,64]) = Xh@Wl;
//                   cols 64-127 -> out(fp32, [N,64]) = Xh@Wr + b

template<int DOUT>
struct StageRegs {
    float4 rv[4];                       // fp32 row regs
    uint2  hv[4];                       // fp16 row regs (4 halfs each)
    float4 wv[DOUT == 128 ? 4 : 2];
};

template<int DOUT, bool SPLIT>
__device__ __forceinline__ void ldg_stage(StageRegs<DOUT>& R, bool useHalf,
                                          const float* __restrict__ rowsF,
                                          const __half* __restrict__ rowsH,
                                          const float* __restrict__ Wl,
                                          const float* __restrict__ Wr,
                                          int k0, int row0, int nrows, int tid) {
#pragma unroll
    for (int j = 0; j < 4; j++) {
        int idx = tid + j * 256;
        int r = idx >> 3, c4 = idx & 7;
        if (useHalf) {
            uint2 u = make_uint2(0u, 0u);
            if (row0 + r < nrows)
                u = *(const uint2*)&rowsH[(size_t)(row0 + r) * 128 + k0 + c4 * 4];
            R.hv[j] = u;
        } else {
            float4 v = make_float4(0.f, 0.f, 0.f, 0.f);
            if (row0 + r < nrows)
                v = *(const float4*)&rowsF[(size_t)(row0 + r) * 128 + k0 + c4 * 4];
            R.rv[j] = v;
        }
    }
    constexpr int WI = (DOUT == 128) ? 4 : 2;
#pragma unroll
    for (int j = 0; j < WI; j++) {
        int idx = tid + j * 256;
        int k, c4;
        if (DOUT == 128) { k = idx >> 5; c4 = idx & 31; }
        else             { k = idx >> 4; c4 = idx & 15; }
        if (SPLIT) {
            int c = c4 * 4;
            if (c < 64) R.wv[j] = *(const float4*)&Wl[(size_t)(k0 + k) * 64 + c];
            else        R.wv[j] = *(const float4*)&Wr[(size_t)(k0 + k) * 64 + (c - 64)];
        } else {
            R.wv[j] = *(const float4*)&Wl[(size_t)(k0 + k) * DOUT + c4 * 4];
        }
    }
}

template<int DOUT>
__device__ __forceinline__ void sts_stage(const StageRegs<DOUT>& R, bool useHalf,
                                          uint32_t* sA, uint32_t* sW, int tid) {
    constexpr int WST = DOUT + 8;
#pragma unroll
    for (int j = 0; j < 4; j++) {
        int idx = tid + j * 256;
        int r = idx >> 3, c4 = idx & 7;
        uint4 o;
        if (useHalf) {
            uint2 u = R.hv[j];
            float2 f01 = __half22float2(*(__half2*)&u.x);
            float2 f23 = __half22float2(*(__half2*)&u.y);
            o = make_uint4(f2tf(f01.x), f2tf(f01.y), f2tf(f23.x), f2tf(f23.y));
        } else {
            float4 v = R.rv[j];
            o = make_uint4(f2tf(v.x), f2tf(v.y), f2tf(v.z), f2tf(v.w));
        }
        *(uint4*)&sA[r * 36 + c4 * 4] = o;
    }
    constexpr int WI = (DOUT == 128) ? 4 : 2;
#pragma unroll
    for (int j = 0; j < WI; j++) {
        int idx = tid + j * 256;
        int k, c4;
        if (DOUT == 128) { k = idx >> 5; c4 = idx & 31; }
        else             { k = idx >> 4; c4 = idx & 15; }
        float4 v = R.wv[j];
        *(uint4*)&sW[k * WST + c4 * 4] =
            make_uint4(f2tf(v.x), f2tf(v.y), f2tf(v.z), f2tf(v.w));
    }
}

template<int DOUT, int PHASES, bool STATS, bool SPLIT>
__global__ void __launch_bounds__(256, 1)
gemm_mma(const float* __restrict__ A, const __half* __restrict__ Xh,
         const float* __restrict__ Wl, const float* __restrict__ Wr,
         const float* __restrict__ bias, float* __restrict__ out,
         __half* __restrict__ ho, float* __restrict__ stats, int nrows) {
    constexpr int WST    = DOUT + 8;
    constexpr int NT     = DOUT / 16;
    constexpr int ASZ    = 128 * 36;
    constexpr int NSTAGE = PHASES * 4;
    constexpr int HOST   = SPLIT ? 64 : DOUT;   // ho row stride (halfs)

    extern __shared__ uint32_t sm[];
    uint32_t* sA[2] = { sm, sm + ASZ };
    uint32_t* sW[2] = { sm + 2 * ASZ, sm + 2 * ASZ + 32 * WST };

    int tid  = threadIdx.x;
    int wid  = tid >> 5, lane = tid & 31;
    int wr   = wid & 3, wc = wid >> 2;
    int g    = lane >> 2, tg = lane & 3;
    int row0 = blockIdx.x * 128;

    float acc[2][NT][4];
#pragma unroll
    for (int rt = 0; rt < 2; rt++)
#pragma unroll
        for (int ct = 0; ct < NT; ct++)
#pragma unroll
            for (int j = 0; j < 4; j++) acc[rt][ct][j] = 0.f;

    StageRegs<DOUT> R;
    const bool half0 = SPLIT;
    ldg_stage<DOUT, SPLIT>(R, half0, A, Xh, Wl, Wr, 0, row0, nrows, tid);
    sts_stage<DOUT>(R, half0, sA[0], sW[0], tid);

#pragma unroll
    for (int s = 0; s < NSTAGE; s++) {
        bool hn = false;
        if (s + 1 < NSTAGE) {
            hn = SPLIT || (PHASES == 2 && s + 1 >= 4);
            const float* W1 = (PHASES == 2 && s + 1 >= 4) ? Wr : Wl;
            ldg_stage<DOUT, SPLIT>(R, hn, A, Xh, W1, Wr, ((s + 1) & 3) * 32,
                                   row0, nrows, tid);
        }
        __syncthreads();
        if (s + 1 < NSTAGE) sts_stage<DOUT>(R, hn, sA[(s + 1) & 1], sW[(s + 1) & 1], tid);

        const uint32_t* As = sA[s & 1];
        const uint32_t* Ws = sW[s & 1];
#pragma unroll
        for (int kk = 0; kk < 32; kk += 8) {
            uint32_t a[2][4];
#pragma unroll
            for (int rt = 0; rt < 2; rt++) {
                int rb = wr * 32 + rt * 16;
                a[rt][0] = As[(rb + g) * 36 + kk + tg];
                a[rt][1] = As[(rb + g + 8) * 36 + kk + tg];
                a[rt][2] = As[(rb + g) * 36 + kk + tg + 4];
                a[rt][3] = As[(rb + g + 8) * 36 + kk + tg + 4];
            }
#pragma unroll
            for (int ct = 0; ct < NT; ct++) {
                int nb = wc * (DOUT / 2) + ct * 8 + g;
                uint32_t b0 = Ws[(kk + tg) * WST + nb];
                uint32_t b1 = Ws[(kk + tg + 4) * WST + nb];
                mma_tf32(acc[0][ct], a[0], b0, b1);
                mma_tf32(acc[1][ct], a[1], b0, b1);
            }
        }
    }

    // ---- epilogue ----
    float* sst = (float*)sm;
    if (STATS) {
        __syncthreads();
        sst[tid] = 0.f;
        __syncthreads();
    }

#pragma unroll
    for (int ct = 0; ct < NT; ct++) {
        int nb = wc * (DOUT / 2) + ct * 8 + 2 * tg;
        float b0, b1;
        if (SPLIT) {
            b0 = (nb >= 64) ? bias[nb - 64] : 0.f;
            b1 = (nb >= 64) ? bias[nb - 63] : 0.f;
        } else {
            b0 = bias[nb]; b1 = bias[nb + 1];
        }
        float s0 = 0.f, q0 = 0.f, s1 = 0.f, q1 = 0.f;
#pragma unroll
        for (int rt = 0; rt < 2; rt++) {
            int gr = row0 + wr * 32 + rt * 16 + g;
            float v0 = acc[rt][ct][0] + b0, v1 = acc[rt][ct][1] + b1;
            float v2 = acc[rt][ct][2] + b0, v3 = acc[rt][ct][3] + b1;
            if (gr < nrows) {
                if (!SPLIT || nb < 64) {
                    __half2 hv = __floats2half2_rn(v0, v1);
                    *(__half2*)(ho + (size_t)gr * HOST + nb) = hv;
                } else {
                    *(float2*)(out + (size_t)gr * 64 + nb - 64) = make_float2(v0, v1);
                }
                if (STATS) { s0 += v0; q0 += v0 * v0; s1 += v1; q1 += v1 * v1; }
            }
            if (gr + 8 < nrows) {
                if (!SPLIT || nb < 64) {
                    __half2 hv = __floats2half2_rn(v2, v3);
                    *(__half2*)(ho + (size_t)(gr + 8) * HOST + nb) = hv;
                } else {
                    *(float2*)(out + (size_t)(gr + 8) * 64 + nb - 64) = make_float2(v2, v3);
                }
                if (STATS) { s0 += v2; q0 += v2 * v2; s1 += v3; q1 += v3 * v3; }
            }
        }
        if (STATS) {
#pragma unroll
            for (int off = 4; off <= 16; off <<= 1) {
                s0 += __shfl_xor_sync(0xffffffffu, s0, off);
                q0 += __shfl_xor_sync(0xffffffffu, q0, off);
                s1 += __shfl_xor_sync(0xffffffffu, s1, off);
                q1 += __shfl_xor_sync(0xffffffffu, q1, off);
            }
            if (g == 0) {
                atomicAdd(&sst[nb],            s0);
                atomicAdd(&sst[DOUT + nb],     q0);
                atomicAdd(&sst[nb + 1],        s1);
                atomicAdd(&sst[DOUT + nb + 1], q1);
            }
        }
    }

    if (STATS) {
        __syncthreads();
        atomicAdd(&stats[tid], sst[tid]);   // tid < 256 == 2*DOUT
    }
}

// ---------------- BN (finalize fused) + exact GELU; fp16 in, fp16 out ----
__device__ __forceinline__ float gelu_exact(float v) {
    return 0.5f * v * (1.0f + erff(v * 0.70710678118654752f));
}

__global__ void bn_gelu_kernel(const __half* __restrict__ hh,
                               const float* __restrict__ stats,
                               const float* __restrict__ g,
                               const float* __restrict__ be,
                               __half* __restrict__ outh,
                               int n4, float invn) {
    __shared__ float ssm[2 * DK];
    int t = threadIdx.x;
    if (t < DK) {
        float mu  = stats[t] * invn;
        float var = stats[DK + t] * invn - mu * mu;
        float rs  = rsqrtf(var + BN_EPS);
        float s   = g[t] * rs;
        ssm[t]      = s;
        ssm[DK + t] = be[t] - mu * s;
    }
    __syncthreads();
    int i = blockIdx.x * blockDim.x + t;
    if (i >= n4) return;
    int c4 = i & (DK / 4 - 1);
    uint2 u = ((const uint2*)hh)[i];
    float2 f01 = __half22float2(*(__half2*)&u.x);
    float2 f23 = __half22float2(*(__half2*)&u.y);
    float4 sc = *(float4*)&ssm[c4 * 4];
    float4 sh = *(float4*)&ssm[DK + c4 * 4];
    float4 v;
    v.x = gelu_exact(f01.x * sc.x + sh.x);
    v.y = gelu_exact(f01.y * sc.y + sh.y);
    v.z = gelu_exact(f23.x * sc.z + sh.z);
    v.w = gelu_exact(f23.y * sc.w + sh.w);
    __half2 h0 = __floats2half2_rn(v.x, v.y);
    __half2 h1 = __floats2half2_rn(v.z, v.w);
    ((uint2*)outh)[i] = make_uint2(*(uint32_t*)&h0, *(uint32_t*)&h1);
}

// ---------------- launch ----------------
extern "C" void kernel_launch(void* const* d_in, const int* in_sizes, int n_in,
                              void* d_out, int out_size) {
    const float* x   = (const float*)d_in[0];
    const void*  ei  = d_in[1];
    const float* W0l = (const float*)d_in[2];
    const float* W0r = (const float*)d_in[3];
    const float* b0  = (const float*)d_in[4];
    const float* g0  = (const float*)d_in[5];
    const float* be0 = (const float*)d_in[6];
    const float* W1l = (const float*)d_in[7];
    const float* W1r = (const float*)d_in[8];
    const float* b1  = (const float*)d_in[9];
    const float* g1  = (const float*)d_in[10];
    const float* be1 = (const float*)d_in[11];
    const float* W2l = (const float*)d_in[12];
    const float* W2r = (const float*)d_in[13];
    const float* b2  = (const float*)d_in[14];
    float* out = (float*)d_out;

    int E = in_sizes[1] / 2;
    if (E > E_MAX) E = E_MAX;

    void* p;
    cudaGetSymbolAddress(&p, g_agg);    float*  agg    = (float*)p;
    cudaGetSymbolAddress(&p, g_hh);     __half* hh     = (__half*)p;
    cudaGetSymbolAddress(&p, g_xh);     __half* xh     = (__half*)p;
    cudaGetSymbolAddress(&p, g_yh);     __half* yh     = (__half*)p;
    cudaGetSymbolAddress(&p, g_stats0); float*  stats0 = (float*)p;
    cudaGetSymbolAddress(&p, g_stats1); float*  stats1 = (float*)p;

    const int smemA = 2 * (128 * 36 + 32 * (128 + 8)) * 4;   // 71680
    cudaFuncSetAttribute((const void*)gemm_mma<DK, 2, true,  false>,
                         cudaFuncAttributeMaxDynamicSharedMemorySize, smemA);
    cudaFuncSetAttribute((const void*)gemm_mma<DK, 1, false, true>,
                         cudaFuncAttributeMaxDynamicSharedMemorySize, smemA);

    int eb      = (E + 255) / 256;
    int gblocks = (N_NODES + 127) / 128;
    int gab     = (N_NODES * 32 + 255) / 256;
    int n4      = N_NODES * DK / 4;
    int bgb     = (n4 + 255) / 256;
    float invn  = 1.0f / (float)N_NODES;

    // ---- CSR build ----
    init_kernel<<<(n4 + 255) / 256, 256>>>((const int*)ei, x, xh, n4);
    hist_kernel<<<eb, 256>>>(ei, E);
    scan_kernel<<<SCAN_G, SCAN_B>>>();
    fill_kernel<<<eb, 256>>>(ei, E);

    // ---- layer 0 ----
    gather_kernel<<<gab, 256>>>(xh, agg);
    gemm_mma<DK, 2, true, false><<<gblocks, 256, smemA>>>(
        agg, xh, W0l, W0r, b0, nullptr, hh, stats0, N_NODES);
    bn_gelu_kernel<<<bgb, 256>>>(hh, stats0, g0, be0, xh, n4, invn);

    // ---- layer 1 ----
    gather_kernel<<<gab, 256>>>(xh, agg);
    gemm_mma<DK, 2, true, false><<<gblocks, 256, smemA>>>(
        agg, xh, W1l, W1r, b1, nullptr, hh, stats1, N_NODES);
    bn_gelu_kernel<<<bgb, 256>>>(hh, stats1, g1, be1, xh, n4, invn);

    // ---- layer 2: split gemm ([yh fp16 | self+bias fp32]) then gather-add ----
    gemm_mma<DK, 1, false, true><<<gblocks, 256, smemA>>>(
        agg, xh, W2l, W2r, b2, out, yh, nullptr, N_NODES);
    gather64_add_kernel<<<gab, 256>>>(yh, out);
}

// round 17
// speedup vs baseline: 1.5284x; 1.1876x over previous
#include <cuda_runtime.h>
#include <cuda_fp16.h>
#include <math.h>
#include <stdint.h>

#define N_NODES 50000
#define E_MAX   1000000
#define DK 128
#define DOUT2 64
#define BN_EPS 1e-5f
#define SCAN_B 1024
#define SCAN_G ((N_NODES + SCAN_B - 1) / SCAN_B)   // 49

// ---------------- scratch ----------------
__device__ float  g_agg[N_NODES * DK];
__device__ __half g_hh[N_NODES * DK];    // fp16 pre-BN hidden
__device__ __half g_xh[N_NODES * DK];    // fp16 activations
__device__ __half g_yh[N_NODES * DOUT2]; // fp16 layer-2 neighbor-path
__device__ __half g_wt[5][128 * 128];    // fp16 transposed weights [n][k]
                                         // 0:W0l 1:W0r 2:W1l 3:W1r 4:[W2l|W2r]
__device__ float  g_stats0[2 * DK];
__device__ float  g_stats1[2 * DK];
__device__ int    g_is64;
__device__ int    g_deg[N_NODES];
__device__ int    g_rowptr[N_NODES + 1];
__device__ int    g_rank[E_MAX];
__device__ int    g_eidx[E_MAX];

// ---------------- helpers ----------------
__device__ __forceinline__ void mma_f16(float* c, const uint32_t* a,
                                        uint32_t b0, uint32_t b1) {
    asm volatile(
        "mma.sync.aligned.m16n8k16.row.col.f32.f16.f16.f32 "
        "{%0,%1,%2,%3}, {%4,%5,%6,%7}, {%8,%9}, {%0,%1,%2,%3};"
        : "+f"(c[0]), "+f"(c[1]), "+f"(c[2]), "+f"(c[3])
        : "r"(a[0]), "r"(a[1]), "r"(a[2]), "r"(a[3]), "r"(b0), "r"(b1));
}

// ---------------- init: zero deg/stats + detect + x->fp16 + W transpose -----
__global__ void init_kernel(const int* __restrict__ ei32,
                            const float* __restrict__ x,
                            __half* __restrict__ xh, int n4,
                            const float* __restrict__ W0l, const float* __restrict__ W0r,
                            const float* __restrict__ W1l, const float* __restrict__ W1r,
                            const float* __restrict__ W2l, const float* __restrict__ W2r) {
    int idx = blockIdx.x * blockDim.x + threadIdx.x;
    if (idx < N_NODES) g_deg[idx] = 0;
    if (idx < n4) {
        float4 v = ((const float4*)x)[idx];
        __half2 h0 = __floats2half2_rn(v.x, v.y);
        __half2 h1 = __floats2half2_rn(v.z, v.w);
        ((uint2*)xh)[idx] = make_uint2(*(uint32_t*)&h0, *(uint32_t*)&h1);
    }
    if (idx < 65536) {
        int s = idx >> 14, e = idx & 16383, n = e >> 7, k = e & 127;
        const float* W = (s == 0) ? W0l : (s == 1) ? W0r : (s == 2) ? W1l : W1r;
        g_wt[s][n * 128 + k] = __float2half(W[k * 128 + n]);
    } else if (idx < 81920) {
        int e = idx - 65536, n = e >> 7, k = e & 127;
        float v = (n < 64) ? W2l[k * 64 + n] : W2r[k * 64 + (n - 64)];
        g_wt[4][n * 128 + k] = __float2half(v);
    }
    if (blockIdx.x == 0) {
        g_stats0[threadIdx.x] = 0.f;
        g_stats1[threadIdx.x] = 0.f;
    }
    if (blockIdx.x == 1) {
        __shared__ int any;
        if (threadIdx.x == 0) any = 0;
        __syncthreads();
        if (threadIdx.x < 128) {
            int w = 1 + 2 * threadIdx.x;
            if (ei32[w] != 0) atomicOr(&any, 1);
        }
        __syncthreads();
        if (threadIdx.x == 0) g_is64 = (any == 0) ? 1 : 0;
    }
}

// ---------------- CSR build ----------------
__global__ void hist_kernel(const void* __restrict__ eiv, int E) {
    int i = blockIdx.x * blockDim.x + threadIdx.x;
    if (i >= E) return;
    long long d;
    if (g_is64) d = ((const long long*)eiv)[E + i];
    else        d = ((const int*)eiv)[E + i];
    if ((unsigned long long)d < N_NODES)
        g_rank[i] = atomicAdd(&g_deg[(int)d], 1);
}

__global__ void scan_kernel() {
    __shared__ int warp_sums[32];
    __shared__ int s_boff;
    int tid  = threadIdx.x;
    int lane = tid & 31, warp = tid >> 5;

    int acc = 0;
    int lim = blockIdx.x * SCAN_B;
    for (int i = tid; i < lim; i += SCAN_B) acc += g_deg[i];
#pragma unroll
    for (int o = 16; o > 0; o >>= 1) acc += __shfl_down_sync(0xffffffffu, acc, o);
    if (lane == 0) warp_sums[warp] = acc;
    __syncthreads();
    if (tid < 32) {
        int w = warp_sums[tid];
#pragma unroll
        for (int o = 16; o > 0; o >>= 1) w += __shfl_down_sync(0xffffffffu, w, o);
        if (tid == 0) s_boff = w;
    }
    __syncthreads();

    int idx = blockIdx.x * SCAN_B + tid;
    int v = (idx < N_NODES) ? g_deg[idx] : 0;
    int s = v;
#pragma unroll
    for (int o = 1; o < 32; o <<= 1) {
        int u = __shfl_up_sync(0xffffffffu, s, o);
        if (lane >= o) s += u;
    }
    if (lane == 31) warp_sums[warp] = s;
    __syncthreads();
    if (warp == 0) {
        int w = warp_sums[lane];
        int ws = w;
#pragma unroll
        for (int o = 1; o < 32; o <<= 1) {
            int u = __shfl_up_sync(0xffffffffu, ws, o);
            if (lane >= o) ws += u;
        }
        warp_sums[lane] = ws - w;
    }
    __syncthreads();
    int excl = s - v + warp_sums[warp] + s_boff;
    if (idx < N_NODES) {
        g_rowptr[idx] = excl;
        if (idx == N_NODES - 1) g_rowptr[N_NODES] = excl + v;
    }
}

__global__ void fill_kernel(const void* __restrict__ eiv, int E) {
    int i = blockIdx.x * blockDim.x + threadIdx.x;
    if (i >= E) return;
    long long s, d;
    if (g_is64) {
        s = ((const long long*)eiv)[i];
        d = ((const long long*)eiv)[E + i];
    } else {
        s = ((const int*)eiv)[i];
        d = ((const int*)eiv)[E + i];
    }
    if ((unsigned long long)s >= N_NODES || (unsigned long long)d >= N_NODES) return;
    g_eidx[g_rowptr[(int)d] + g_rank[i]] = (int)s;
}

// ---------------- gather (128-wide, fp16 in / fp32 out) ----------------
__global__ void __launch_bounds__(256)
gather_kernel(const __half* __restrict__ xh, float* __restrict__ agg) {
    int node = (blockIdx.x * blockDim.x + threadIdx.x) >> 5;
    int lane = threadIdx.x & 31;
    if (node >= N_NODES) return;
    int beg = g_rowptr[node];
    int end = g_rowptr[node + 1];

    float4 a0 = make_float4(0.f, 0.f, 0.f, 0.f);
    float4 a1 = make_float4(0.f, 0.f, 0.f, 0.f);

    for (int base = beg; base < end; base += 32) {
        int n = end - base; if (n > 32) n = 32;
        int myidx = (base + lane < end) ? g_eidx[base + lane] : 0;
        int j = 0;
        for (; j + 3 < n; j += 4) {
            int s0 = __shfl_sync(0xffffffffu, myidx, j);
            int s1 = __shfl_sync(0xffffffffu, myidx, j + 1);
            int s2 = __shfl_sync(0xffffffffu, myidx, j + 2);
            int s3 = __shfl_sync(0xffffffffu, myidx, j + 3);
            uint2 u0 = *(const uint2*)(xh + (size_t)s0 * DK + lane * 4);
            uint2 u1 = *(const uint2*)(xh + (size_t)s1 * DK + lane * 4);
            uint2 u2 = *(const uint2*)(xh + (size_t)s2 * DK + lane * 4);
            uint2 u3 = *(const uint2*)(xh + (size_t)s3 * DK + lane * 4);
            float2 f;
            f = __half22float2(*(__half2*)&u0.x); a0.x += f.x; a0.y += f.y;
            f = __half22float2(*(__half2*)&u0.y); a0.z += f.x; a0.w += f.y;
            f = __half22float2(*(__half2*)&u1.x); a1.x += f.x; a1.y += f.y;
            f = __half22float2(*(__half2*)&u1.y); a1.z += f.x; a1.w += f.y;
            f = __half22float2(*(__half2*)&u2.x); a0.x += f.x; a0.y += f.y;
            f = __half22float2(*(__half2*)&u2.y); a0.z += f.x; a0.w += f.y;
            f = __half22float2(*(__half2*)&u3.x); a1.x += f.x; a1.y += f.y;
            f = __half22float2(*(__half2*)&u3.y); a1.z += f.x; a1.w += f.y;
        }
        for (; j < n; j++) {
            int s0 = __shfl_sync(0xffffffffu, myidx, j);
            uint2 u0 = *(const uint2*)(xh + (size_t)s0 * DK + lane * 4);
            float2 f;
            f = __half22float2(*(__half2*)&u0.x); a0.x += f.x; a0.y += f.y;
            f = __half22float2(*(__half2*)&u0.y); a0.z += f.x; a0.w += f.y;
        }
    }
    a0.x += a1.x; a0.y += a1.y; a0.z += a1.z; a0.w += a1.w;
    *(float4*)(agg + (size_t)node * DK + lane * 4) = a0;
}

// ---------------- gather (64-wide, fp16 in) + accumulate into out ----------
__global__ void __launch_bounds__(256)
gather64_add_kernel(const __half* __restrict__ yh, float* __restrict__ out) {
    int node = (blockIdx.x * blockDim.x + threadIdx.x) >> 5;
    int lane = threadIdx.x & 31;
    if (node >= N_NODES) return;
    int beg = g_rowptr[node];
    int end = g_rowptr[node + 1];

    float2 a0 = make_float2(0.f, 0.f);
    float2 a1 = make_float2(0.f, 0.f);

    for (int base = beg; base < end; base += 32) {
        int n = end - base; if (n > 32) n = 32;
        int myidx = (base + lane < end) ? g_eidx[base + lane] : 0;
        int j = 0;
        for (; j + 3 < n; j += 4) {
            int s0 = __shfl_sync(0xffffffffu, myidx, j);
            int s1 = __shfl_sync(0xffffffffu, myidx, j + 1);
            int s2 = __shfl_sync(0xffffffffu, myidx, j + 2);
            int s3 = __shfl_sync(0xffffffffu, myidx, j + 3);
            uint32_t u0 = *(const uint32_t*)(yh + (size_t)s0 * DOUT2 + lane * 2);
            uint32_t u1 = *(const uint32_t*)(yh + (size_t)s1 * DOUT2 + lane * 2);
            uint32_t u2 = *(const uint32_t*)(yh + (size_t)s2 * DOUT2 + lane * 2);
            uint32_t u3 = *(const uint32_t*)(yh + (size_t)s3 * DOUT2 + lane * 2);
            float2 f;
            f = __half22float2(*(__half2*)&u0); a0.x += f.x; a0.y += f.y;
            f = __half22float2(*(__half2*)&u1); a1.x += f.x; a1.y += f.y;
            f = __half22float2(*(__half2*)&u2); a0.x += f.x; a0.y += f.y;
            f = __half22float2(*(__half2*)&u3); a1.x += f.x; a1.y += f.y;
        }
        for (; j < n; j++) {
            int s0 = __shfl_sync(0xffffffffu, myidx, j);
            uint32_t u0 = *(const uint32_t*)(yh + (size_t)s0 * DOUT2 + lane * 2);
            float2 f = __half22float2(*(__half2*)&u0);
            a0.x += f.x; a0.y += f.y;
        }
    }
    a0.x += a1.x; a0.y += a1.y;
    float2* po = (float2*)(out + (size_t)node * DOUT2 + lane * 2);
    float2 o = *po;
    o.x += a0.x; o.y += a0.y;
    *po = o;
}

// ---------------- mma.sync f16 GEMM (m16n8k16, fp32 accumulate) ----------
// smem tiles fp16: sA 128 rows x 40 halfs (stride 20 words), sW 128 n x 40 halfs.
// PHASES=2: hh(fp16) = A(fp32->fp16)@WtL^T + Xh@WtR^T + b  (+ fp32 stats)
// PHASES=1 + SPLIT: rows Xh; Wt = combined [W2l|W2r]^T;
//   cols 0-63 -> yh fp16; cols 64-127 -> out fp32 (+ bias)

struct StageRegs {
    float4 rv[4];   // fp32 rows
    uint2  hv[4];   // fp16 rows
    uint2  wv[4];   // fp16 weights
};

__device__ __forceinline__ void ldg_stage(StageRegs& R, bool useHalf,
                                          const float* __restrict__ rowsF,
                                          const __half* __restrict__ rowsH,
                                          const __half* __restrict__ Wt,
                                          int k0, int row0, int nrows, int tid) {
#pragma unroll
    for (int j = 0; j < 4; j++) {
        int idx = tid + j * 256;
        int r = idx >> 3, c = idx & 7;
        if (useHalf) {
            uint2 u = make_uint2(0u, 0u);
            if (row0 + r < nrows)
                u = *(const uint2*)&rowsH[(size_t)(row0 + r) * 128 + k0 + c * 4];
            R.hv[j] = u;
        } else {
            float4 v = make_float4(0.f, 0.f, 0.f, 0.f);
            if (row0 + r < nrows)
                v = *(const float4*)&rowsF[(size_t)(row0 + r) * 128 + k0 + c * 4];
            R.rv[j] = v;
        }
    }
#pragma unroll
    for (int j = 0; j < 4; j++) {
        int idx = tid + j * 256;
        int n = idx >> 3, c = idx & 7;
        R.wv[j] = *(const uint2*)&Wt[(size_t)n * 128 + k0 + c * 4];
    }
}

__device__ __forceinline__ void sts_stage(const StageRegs& R, bool useHalf,
                                          uint32_t* sA, uint32_t* sW, int tid) {
#pragma unroll
    for (int j = 0; j < 4; j++) {
        int idx = tid + j * 256;
        int r = idx >> 3, c = idx & 7;
        uint2 o;
        if (useHalf) {
            o = R.hv[j];
        } else {
            float4 v = R.rv[j];
            __half2 h0 = __floats2half2_rn(v.x, v.y);
            __half2 h1 = __floats2half2_rn(v.z, v.w);
            o = make_uint2(*(uint32_t*)&h0, *(uint32_t*)&h1);
        }
        *(uint2*)&sA[r * 20 + c * 2] = o;
    }
#pragma unroll
    for (int j = 0; j < 4; j++) {
        int idx = tid + j * 256;
        int n = idx >> 3, c = idx & 7;
        *(uint2*)&sW[n * 20 + c * 2] = R.wv[j];
    }
}

template<int PHASES, bool STATS, bool SPLIT>
__global__ void __launch_bounds__(256)
gemm_mma(const float* __restrict__ A, const __half* __restrict__ Xh,
         const __half* __restrict__ WtL, const __half* __restrict__ WtR,
         const float* __restrict__ bias, float* __restrict__ out,
         __half* __restrict__ ho, float* __restrict__ stats, int nrows) {
    constexpr int NT     = 8;             // 8 col tiles of 16 per warp pair
    constexpr int ABUF   = 128 * 20;      // words per buffer
    constexpr int NSTAGE = PHASES * 4;
    constexpr int HOST   = SPLIT ? 64 : 128;  // ho row stride (halfs)

    extern __shared__ uint32_t sm[];
    uint32_t* sA[2] = { sm, sm + ABUF };
    uint32_t* sW[2] = { sm + 2 * ABUF, sm + 3 * ABUF };

    int tid  = threadIdx.x;
    int wid  = tid >> 5, lane = tid & 31;
    int wr   = wid & 3, wc = wid >> 2;
    int g    = lane >> 2, tg = lane & 3;
    int row0 = blockIdx.x * 128;

    float acc[2][NT][4];
#pragma unroll
    for (int rt = 0; rt < 2; rt++)
#pragma unroll
        for (int ct = 0; ct < NT; ct++)
#pragma unroll
            for (int j = 0; j < 4; j++) acc[rt][ct][j] = 0.f;

    StageRegs R;
    const bool half0 = SPLIT;
    ldg_stage(R, half0, A, Xh, WtL, 0, row0, nrows, tid);
    sts_stage(R, half0, sA[0], sW[0], tid);

#pragma unroll
    for (int s = 0; s < NSTAGE; s++) {
        bool hn = false;
        if (s + 1 < NSTAGE) {
            hn = SPLIT || (PHASES == 2 && s + 1 >= 4);
            const __half* W1 = (PHASES == 2 && s + 1 >= 4) ? WtR : WtL;
            ldg_stage(R, hn, A, Xh, W1, ((s + 1) & 3) * 32, row0, nrows, tid);
        }
        __syncthreads();
        if (s + 1 < NSTAGE) sts_stage(R, hn, sA[(s + 1) & 1], sW[(s + 1) & 1], tid);

        const uint32_t* As = sA[s & 1];
        const uint32_t* Ws = sW[s & 1];
#pragma unroll
        for (int kk2 = 0; kk2 < 16; kk2 += 8) {     // k-half offset in words
            uint32_t a[2][4];
#pragma unroll
            for (int rt = 0; rt < 2; rt++) {
                int rb = wr * 32 + rt * 16;
                int b0i = (rb + g) * 20 + kk2 + tg;
                int b1i = (rb + g + 8) * 20 + kk2 + tg;
                a[rt][0] = As[b0i];
                a[rt][1] = As[b1i];
                a[rt][2] = As[b0i + 4];
                a[rt][3] = As[b1i + 4];
            }
#pragma unroll
            for (int ct = 0; ct < NT; ct++) {
                int nb = wc * 64 + ct * 8 + g;
                uint32_t b0 = Ws[nb * 20 + kk2 + tg];
                uint32_t b1 = Ws[nb * 20 + kk2 + tg + 4];
                mma_f16(acc[0][ct], a[0], b0, b1);
                mma_f16(acc[1][ct], a[1], b0, b1);
            }
        }
    }

    // ---- epilogue ----
    float* sst = (float*)sm;
    if (STATS) {
        __syncthreads();
        sst[tid] = 0.f;
        __syncthreads();
    }

#pragma unroll
    for (int ct = 0; ct < NT; ct++) {
        int nb = wc * 64 + ct * 8 + 2 * tg;
        float b0, b1;
        if (SPLIT) {
            b0 = (nb >= 64) ? bias[nb - 64] : 0.f;
            b1 = (nb >= 64) ? bias[nb - 63] : 0.f;
        } else {
            b0 = bias[nb]; b1 = bias[nb + 1];
        }
        float s0 = 0.f, q0 = 0.f, s1 = 0.f, q1 = 0.f;
#pragma unroll
        for (int rt = 0; rt < 2; rt++) {
            int gr = row0 + wr * 32 + rt * 16 + g;
            float v0 = acc[rt][ct][0] + b0, v1 = acc[rt][ct][1] + b1;
            float v2 = acc[rt][ct][2] + b0, v3 = acc[rt][ct][3] + b1;
            if (gr < nrows) {
                if (!SPLIT || nb < 64) {
                    __half2 hv = __floats2half2_rn(v0, v1);
                    *(__half2*)(ho + (size_t)gr * HOST + nb) = hv;
                } else {
                    *(float2*)(out + (size_t)gr * 64 + nb - 64) = make_float2(v0, v1);
                }
                if (STATS) { s0 += v0; q0 += v0 * v0; s1 += v1; q1 += v1 * v1; }
            }
            if (gr + 8 < nrows) {
                if (!SPLIT || nb < 64) {
                    __half2 hv = __floats2half2_rn(v2, v3);
                    *(__half2*)(ho + (size_t)(gr + 8) * HOST + nb) = hv;
                } else {
                    *(float2*)(out + (size_t)(gr + 8) * 64 + nb - 64) = make_float2(v2, v3);
                }
                if (STATS) { s0 += v2; q0 += v2 * v2; s1 += v3; q1 += v3 * v3; }
            }
        }
        if (STATS) {
#pragma unroll
            for (int off = 4; off <= 16; off <<= 1) {
                s0 += __shfl_xor_sync(0xffffffffu, s0, off);
                q0 += __shfl_xor_sync(0xffffffffu, q0, off);
                s1 += __shfl_xor_sync(0xffffffffu, s1, off);
                q1 += __shfl_xor_sync(0xffffffffu, q1, off);
            }
            if (g == 0) {
                atomicAdd(&sst[nb],           s0);
                atomicAdd(&sst[128 + nb],     q0);
                atomicAdd(&sst[nb + 1],       s1);
                atomicAdd(&sst[128 + nb + 1], q1);
            }
        }
    }

    if (STATS) {
        __syncthreads();
        atomicAdd(&stats[tid], sst[tid]);   // tid < 256 == 2*128
    }
}

// ---------------- BN (finalize fused) + exact GELU; fp16 in, fp16 out ----
__device__ __forceinline__ float gelu_exact(float v) {
    return 0.5f * v * (1.0f + erff(v * 0.70710678118654752f));
}

__global__ void bn_gelu_kernel(const __half* __restrict__ hh,
                               const float* __restrict__ stats,
                               const float* __restrict__ g,
                               const float* __restrict__ be,
                               __half* __restrict__ outh,
                               int n4, float invn) {
    __shared__ float ssm[2 * DK];
    int t = threadIdx.x;
    if (t < DK) {
        float mu  = stats[t] * invn;
        float var = stats[DK + t] * invn - mu * mu;
        float rs  = rsqrtf(var + BN_EPS);
        float s   = g[t] * rs;
        ssm[t]      = s;
        ssm[DK + t] = be[t] - mu * s;
    }
    __syncthreads();
    int i = blockIdx.x * blockDim.x + t;
    if (i >= n4) return;
    int c4 = i & (DK / 4 - 1);
    uint2 u = ((const uint2*)hh)[i];
    float2 f01 = __half22float2(*(__half2*)&u.x);
    float2 f23 = __half22float2(*(__half2*)&u.y);
    float4 sc = *(float4*)&ssm[c4 * 4];
    float4 sh = *(float4*)&ssm[DK + c4 * 4];
    float4 v;
    v.x = gelu_exact(f01.x * sc.x + sh.x);
    v.y = gelu_exact(f01.y * sc.y + sh.y);
    v.z = gelu_exact(f23.x * sc.z + sh.z);
    v.w = gelu_exact(f23.y * sc.w + sh.w);
    __half2 h0 = __floats2half2_rn(v.x, v.y);
    __half2 h1 = __floats2half2_rn(v.z, v.w);
    ((uint2*)outh)[i] = make_uint2(*(uint32_t*)&h0, *(uint32_t*)&h1);
}

// ---------------- launch ----------------
extern "C" void kernel_launch(void* const* d_in, const int* in_sizes, int n_in,
                              void* d_out, int out_size) {
    const float* x   = (const float*)d_in[0];
    const void*  ei  = d_in[1];
    const float* W0l = (const float*)d_in[2];
    const float* W0r = (const float*)d_in[3];
    const float* b0  = (const float*)d_in[4];
    const float* g0  = (const float*)d_in[5];
    const float* be0 = (const float*)d_in[6];
    const float* W1l = (const float*)d_in[7];
    const float* W1r = (const float*)d_in[8];
    const float* b1  = (const float*)d_in[9];
    const float* g1  = (const float*)d_in[10];
    const float* be1 = (const float*)d_in[11];
    const float* W2l = (const float*)d_in[12];
    const float* W2r = (const float*)d_in[13];
    const float* b2  = (const float*)d_in[14];
    float* out = (float*)d_out;

    int E = in_sizes[1] / 2;
    if (E > E_MAX) E = E_MAX;

    void* p;
    cudaGetSymbolAddress(&p, g_agg);    float*  agg    = (float*)p;
    cudaGetSymbolAddress(&p, g_hh);     __half* hh     = (__half*)p;
    cudaGetSymbolAddress(&p, g_xh);     __half* xh     = (__half*)p;
    cudaGetSymbolAddress(&p, g_yh);     __half* yh     = (__half*)p;
    cudaGetSymbolAddress(&p, g_wt);     __half* wt     = (__half*)p;
    cudaGetSymbolAddress(&p, g_stats0); float*  stats0 = (float*)p;
    cudaGetSymbolAddress(&p, g_stats1); float*  stats1 = (float*)p;

    const __half* wt0l = wt;
    const __half* wt0r = wt + 1 * 128 * 128;
    const __half* wt1l = wt + 2 * 128 * 128;
    const __half* wt1r = wt + 3 * 128 * 128;
    const __half* wt2  = wt + 4 * 128 * 128;

    const int smemG = 4 * 128 * 20 * 4;   // 40960 B

    int eb      = (E + 255) / 256;
    int gblocks = (N_NODES + 127) / 128;
    int gab     = (N_NODES * 32 + 255) / 256;
    int n4      = N_NODES * DK / 4;
    int bgb     = (n4 + 255) / 256;
    float invn  = 1.0f / (float)N_NODES;

    // ---- CSR build + fp16 conversions + weight transposes ----
    init_kernel<<<(n4 + 255) / 256, 256>>>((const int*)ei, x, xh, n4,
                                           W0l, W0r, W1l, W1r, W2l, W2r);
    hist_kernel<<<eb, 256>>>(ei, E);
    scan_kernel<<<SCAN_G, SCAN_B>>>();
    fill_kernel<<<eb, 256>>>(ei, E);

    // ---- layer 0 ----
    gather_kernel<<<gab, 256>>>(xh, agg);
    gemm_mma<2, true, false><<<gblocks, 256, smemG>>>(
        agg, xh, wt0l, wt0r, b0, nullptr, hh, stats0, N_NODES);
    bn_gelu_kernel<<<bgb, 256>>>(hh, stats0, g0, be0, xh, n4, invn);

    // ---- layer 1 ----
    gather_kernel<<<gab, 256>>>(xh, agg);
    gemm_mma<2, true, false><<<gblocks, 256, smemG>>>(
        agg, xh, wt1l, wt1r, b1, nullptr, hh, stats1, N_NODES);
    bn_gelu_kernel<<<bgb, 256>>>(hh, stats1, g1, be1, xh, n4, invn);

    // ---- layer 2: split gemm ([yh fp16 | self+bias fp32]) then gather-add ----
    gemm_mma<1, false, true><<<gblocks, 256, smemG>>>(
        agg, xh, wt2, wt2, b2, out, yh, nullptr, N_NODES);
    gather64_add_kernel<<<gab, 256>>>(yh, out);
}